// round 1
// baseline (speedup 1.0000x reference)
#include <cuda_runtime.h>
#include <math.h>

#define BB 16
#define LL 2048
#define WIN 128
#define DD 512
#define HH 8
#define HD 64
#define FF 2048
#define NLAYER 3
#define VV 32000
#define MMOT 32
#define SS 129            // WIN + 1 (cond row)
#define RT (BB*SS)        // 2064 transformer rows
#define WR (BB*WIN)       // 2048 window rows
#define EPSV 1e-5f
#define NCHUNK (VV/64)    // 500 softmax partial chunks

// ------------------- device scratch (static, no allocation) -------------------
__device__ float g_condin[BB*4*DD];
__device__ float g_poolpart[BB*8*3*DD];
__device__ float g_tin[BB*DD];
__device__ float g_temb[BB*DD];
__device__ float g_condout[BB*DD];
__device__ float g_x[RT*DD];
__device__ float g_xt[WR*DD];
__device__ float g_x1[WR*DD];
__device__ float g_qkv[RT*3*DD];
__device__ float g_scores[BB*HH*SS*SS];
__device__ float g_ctx[RT*DD];
__device__ float g_tmp[RT*DD];
__device__ float g_ff[RT*FF];
__device__ float g_predv[WR*DD];
__device__ float g_predx1[WR*DD];
__device__ float g_hadapt[WR*DD];
__device__ float2 g_smpart[WR*NCHUNK];
__device__ float g_picked[WR];
__device__ float g_rowrecon[WR];
__device__ float g_velred[256];
__device__ int g_comporig[WR];
__device__ int g_complabel[WR];
__device__ int g_amap[WR];
__device__ int g_nvalid;

// ------------------- pools: left/right/glob partial sums ---------------------
__global__ void pool_partial(const int* __restrict__ tok, const int* __restrict__ ws,
                             const int* __restrict__ we, const float* __restrict__ emb) {
    int b = blockIdx.x, c = blockIdx.y, d = threadIdx.x;   // 512 threads
    int s0 = ws[b], e0 = we[b];
    float gl = 0.f, lf = 0.f, rt = 0.f;
    int l0 = c * (LL/8);
#pragma unroll 4
    for (int i = 0; i < LL/8; i++) {
        int l = l0 + i;
        int t = tok[b*LL + l];
        float v = emb[(size_t)t*DD + d];
        gl += v;
        if (l < s0)  lf += v;
        if (l >= e0) rt += v;
    }
    float* p = g_poolpart + ((size_t)(b*8 + c)*3)*DD;
    p[d] = lf; p[DD + d] = rt; p[2*DD + d] = gl;
}

__global__ void pool_reduce(const int* __restrict__ mot, const int* __restrict__ mlen,
                            const int* __restrict__ ws, const int* __restrict__ we,
                            const float* __restrict__ emb) {
    int b = blockIdx.x, d = threadIdx.x;
    float lf = 0.f, rt = 0.f, gl = 0.f;
    for (int c = 0; c < 8; c++) {
        const float* p = g_poolpart + ((size_t)(b*8 + c)*3)*DD;
        lf += p[d]; rt += p[DD + d]; gl += p[2*DD + d];
    }
    int ml = mlen[b];
    float mo = 0.f;
    for (int i = 0; i < MMOT; i++)
        if (i < ml) mo += emb[(size_t)mot[b*MMOT + i]*DD + d];
    mo /= (float)(ml > 1 ? ml : 1);
    float lden = (float)(ws[b] > 1 ? ws[b] : 1);
    int rc = LL - we[b];
    float rden = (float)(rc > 1 ? rc : 1);
    float* o = g_condin + (size_t)b*4*DD;
    o[d]        = mo;            // motif
    o[DD + d]   = lf / lden;     // left
    o[2*DD + d] = rt / rden;     // right
    o[3*DD + d] = gl / (float)LL;// glob
}

// ------------------- time embedding input (sin/cos) --------------------------
__global__ void tin_build(const float* __restrict__ t) {
    int b = blockIdx.x, d = threadIdx.x;
    int k = d % (DD/2);
    float f = expf(-logf(10000.f) * (float)k / (float)(DD/2 - 1));
    float a = t[b] * f;
    g_tin[b*DD + d] = (d < DD/2) ? sinf(a) : cosf(a);
}

__global__ void copy_cond() {
    int b = blockIdx.x, d = threadIdx.x;
    g_x[(size_t)b*SS*DD + d] = g_condout[b*DD + d];
}

// ------------------- build x_t, x1, x --------------------------------------
__global__ void build_x(const int* __restrict__ tok, const int* __restrict__ ws,
                        const int* __restrict__ we, const float* __restrict__ t,
                        const float* __restrict__ x0, const float* __restrict__ emb) {
    int idx = blockIdx.x*blockDim.x + threadIdx.x;
    if (idx >= BB*WIN*DD) return;
    int d = idx % DD; int r = idx / DD; int j = r % WIN; int b = r / WIN;
    int s0 = ws[b];
    int act = we[b] - s0;
    float x1v = 0.f;
    if (j < act) {
        int tk = tok[b*LL + s0 + j];
        x1v = emb[(size_t)tk*DD + d];
    }
    float tv = t[b];
    float xt = (1.f - tv)*x0[idx] + tv*x1v;
    g_x1[idx] = x1v;
    g_xt[idx] = xt;
    g_x[((size_t)b*SS + 1 + j)*DD + d] = xt + g_temb[b*DD + d];
}

// ------------------- valid-row compaction -----------------------------------
__global__ void compact_kernel(const int* __restrict__ tok, const int* __restrict__ ws,
                               const int* __restrict__ we) {
    __shared__ int off[BB+1];
    if (threadIdx.x == 0) {
        off[0] = 0;
        for (int b = 0; b < BB; b++) {
            int a = we[b] - ws[b];
            if (a < 0) a = 0; if (a > WIN) a = WIN;
            off[b+1] = off[b] + a;
        }
        g_nvalid = off[BB];
    }
    __syncthreads();
    for (int idx = threadIdx.x; idx < BB*WIN; idx += blockDim.x) {
        int b = idx / WIN, j = idx % WIN;
        int a = off[b+1] - off[b];
        if (j < a) {
            int r = off[b] + j;
            g_comporig[r]  = idx;
            g_amap[r]      = b*SS + 1 + j;
            g_complabel[r] = tok[b*LL + ws[b] + j];
        }
    }
}

// ------------------- generic SGEMM: C = A @ W^T + bias -----------------------
// A [M,K] (optionally indirected by g_amap, M optionally from g_nvalid)
// W [N,K] row-major. 64x64 tile, BK=16, 256 threads, 4x4 per thread.
__global__ void gemm_kernel(const float* __restrict__ A, const float* __restrict__ Wt,
                            const float* __restrict__ bias, float* __restrict__ C,
                            int Mh, int N, int K, int use_nv, int use_amap, int relu) {
    int Mact = use_nv ? g_nvalid : Mh;
    int by = blockIdx.y, bx = blockIdx.x;
    if (by*64 >= Mact) return;
    __shared__ float As[16][68];
    __shared__ float Bs[16][68];
    __shared__ int amap_s[64];
    int tid = threadIdx.x;
    if (tid < 64) {
        int m = by*64 + tid;
        amap_s[tid] = (m < Mact) ? (use_amap ? g_amap[m] : m) : -1;
    }
    __syncthreads();
    int lm = tid >> 2;
    int lk = (tid & 3) * 4;
    int arow = amap_s[lm];
    int brow = bx*64 + lm;
    bool aok = (arow >= 0), bok = (brow < N);
    const float* Ap = A + (size_t)(aok ? arow : 0)*K + lk;
    const float* Bp = Wt + (size_t)(bok ? brow : 0)*K + lk;
    int tx = tid & 15, ty = tid >> 4;
    float acc[4][4];
#pragma unroll
    for (int i = 0; i < 4; i++)
#pragma unroll
        for (int j = 0; j < 4; j++) acc[i][j] = 0.f;

    for (int k0 = 0; k0 < K; k0 += 16) {
        float4 av = aok ? *(const float4*)(Ap + k0) : make_float4(0,0,0,0);
        float4 bv = bok ? *(const float4*)(Bp + k0) : make_float4(0,0,0,0);
        __syncthreads();
        As[lk][lm] = av.x; As[lk+1][lm] = av.y; As[lk+2][lm] = av.z; As[lk+3][lm] = av.w;
        Bs[lk][lm] = bv.x; Bs[lk+1][lm] = bv.y; Bs[lk+2][lm] = bv.z; Bs[lk+3][lm] = bv.w;
        __syncthreads();
#pragma unroll
        for (int kk = 0; kk < 16; kk++) {
            float4 a4 = *(const float4*)&As[kk][ty*4];
            float4 b4 = *(const float4*)&Bs[kk][tx*4];
            float ar[4] = {a4.x, a4.y, a4.z, a4.w};
            float br[4] = {b4.x, b4.y, b4.z, b4.w};
#pragma unroll
            for (int i = 0; i < 4; i++)
#pragma unroll
                for (int j = 0; j < 4; j++) acc[i][j] += ar[i]*br[j];
        }
    }
#pragma unroll
    for (int i = 0; i < 4; i++) {
        int row = by*64 + ty*4 + i;
        if (row >= Mact) continue;
#pragma unroll
        for (int j = 0; j < 4; j++) {
            int col = bx*64 + tx*4 + j;
            if (col >= N) continue;
            float v = acc[i][j] + bias[col];
            if (relu) v = fmaxf(v, 0.f);
            C[(size_t)row*N + col] = v;
        }
    }
}

// ------------------- decode GEMM + fused online-softmax partials -------------
__global__ void decode_kernel(const float* __restrict__ A, const float* __restrict__ Wt,
                              const float* __restrict__ bias) {
    int Mact = g_nvalid;
    int by = blockIdx.y, bx = blockIdx.x;
    if (by*64 >= Mact) return;
    __shared__ float As[16][68];
    __shared__ float Bs[16][68];
    int tid = threadIdx.x;
    int lm = tid >> 2;
    int lk = (tid & 3) * 4;
    int arow = by*64 + lm;
    int brow = bx*64 + lm;
    bool aok = (arow < Mact);
    const float* Ap = A + (size_t)(aok ? arow : 0)*DD + lk;
    const float* Bp = Wt + (size_t)brow*DD + lk;
    int tx = tid & 15, ty = tid >> 4;
    float acc[4][4];
#pragma unroll
    for (int i = 0; i < 4; i++)
#pragma unroll
        for (int j = 0; j < 4; j++) acc[i][j] = 0.f;

    for (int k0 = 0; k0 < DD; k0 += 16) {
        float4 av = aok ? *(const float4*)(Ap + k0) : make_float4(0,0,0,0);
        float4 bv = *(const float4*)(Bp + k0);
        __syncthreads();
        As[lk][lm] = av.x; As[lk+1][lm] = av.y; As[lk+2][lm] = av.z; As[lk+3][lm] = av.w;
        Bs[lk][lm] = bv.x; Bs[lk+1][lm] = bv.y; Bs[lk+2][lm] = bv.z; Bs[lk+3][lm] = bv.w;
        __syncthreads();
#pragma unroll
        for (int kk = 0; kk < 16; kk++) {
            float4 a4 = *(const float4*)&As[kk][ty*4];
            float4 b4 = *(const float4*)&Bs[kk][tx*4];
            float ar[4] = {a4.x, a4.y, a4.z, a4.w};
            float br[4] = {b4.x, b4.y, b4.z, b4.w};
#pragma unroll
            for (int i = 0; i < 4; i++)
#pragma unroll
                for (int j = 0; j < 4; j++) acc[i][j] += ar[i]*br[j];
        }
    }
    // per-row (max, sum-exp) over this 64-col tile; lanes 0..15 within half-warp share a row
#pragma unroll
    for (int i = 0; i < 4; i++) {
        int row = by*64 + ty*4 + i;
        float vv[4];
        float mx = -1e30f;
#pragma unroll
        for (int j = 0; j < 4; j++) {
            int col = bx*64 + tx*4 + j;
            vv[j] = acc[i][j] + bias[col];
            mx = fmaxf(mx, vv[j]);
        }
#pragma unroll
        for (int off = 1; off < 16; off <<= 1)
            mx = fmaxf(mx, __shfl_xor_sync(0xffffffffu, mx, off));
        float se = 0.f;
#pragma unroll
        for (int j = 0; j < 4; j++) se += expf(vv[j] - mx);
#pragma unroll
        for (int off = 1; off < 16; off <<= 1)
            se += __shfl_xor_sync(0xffffffffu, se, off);
        if (tx == 0 && row < Mact)
            g_smpart[(size_t)row*NCHUNK + bx] = make_float2(mx, se);
    }
}

// ------------------- attention ----------------------------------------------
__global__ void attn_scores() {
    int bh = blockIdx.x; int b = bh / HH, h = bh % HH;
    __shared__ float ks[SS][HD];
    const float* base = g_qkv + (size_t)b*SS*3*DD;
    for (int i = threadIdx.x; i < SS*HD; i += blockDim.x) {
        int s = i / HD, d = i % HD;
        ks[s][d] = base[(size_t)s*3*DD + DD + h*HD + d];
    }
    __syncthreads();
    int q = threadIdx.x;
    if (q < SS) {
        float qr[HD];
#pragma unroll
        for (int d = 0; d < HD; d++) qr[d] = base[(size_t)q*3*DD + h*HD + d];
        float* srow = g_scores + ((size_t)bh*SS + q)*SS;
        for (int k = 0; k < SS; k++) {
            float a = 0.f;
#pragma unroll
            for (int d = 0; d < HD; d++) a += qr[d]*ks[k][d];
            srow[k] = a * 0.125f;  // 1/sqrt(64)
        }
    }
}

__global__ void attn_softmax() {
    int row = blockIdx.x*4 + threadIdx.x/32;
    int lane = threadIdx.x % 32;
    if (row >= BB*HH*SS) return;
    float* p = g_scores + (size_t)row*SS;
    float v[5];
    float mx = -1e30f;
    int cnt = 0;
    for (int i = lane; i < SS; i += 32) { v[cnt] = p[i]; mx = fmaxf(mx, v[cnt]); cnt++; }
#pragma unroll
    for (int off = 16; off; off >>= 1) mx = fmaxf(mx, __shfl_xor_sync(0xffffffffu, mx, off));
    float se = 0.f;
    for (int c = 0; c < cnt; c++) { v[c] = expf(v[c]-mx); se += v[c]; }
#pragma unroll
    for (int off = 16; off; off >>= 1) se += __shfl_xor_sync(0xffffffffu, se, off);
    float inv = 1.f/se;
    cnt = 0;
    for (int i = lane; i < SS; i += 32) { p[i] = v[cnt]*inv; cnt++; }
}

__global__ void attn_ctx() {
    int bh = blockIdx.x; int b = bh / HH, h = bh % HH;
    __shared__ float vs[SS][HD];
    const float* base = g_qkv + (size_t)b*SS*3*DD + 2*DD + h*HD;
    for (int i = threadIdx.x; i < SS*HD; i += blockDim.x) {
        int s = i / HD, d = i % HD;
        vs[s][d] = base[(size_t)s*3*DD + d];
    }
    __syncthreads();
    for (int i = threadIdx.x; i < SS*HD; i += blockDim.x) {
        int q = i / HD, d = i % HD;
        const float* pr = g_scores + ((size_t)bh*SS + q)*SS;
        float a = 0.f;
        for (int k = 0; k < SS; k++) a += pr[k]*vs[k][d];
        g_ctx[((size_t)b*SS + q)*DD + h*HD + d] = a;
    }
}

// ------------------- residual + layernorm -----------------------------------
__global__ void ln_kernel(float* __restrict__ x, const float* __restrict__ add,
                          const float* __restrict__ g, const float* __restrict__ bb) {
    __shared__ float red[256];
    __shared__ float stats[2];
    int tid = threadIdx.x;
    float* xr = x + (size_t)blockIdx.x*DD;
    const float* ar = add + (size_t)blockIdx.x*DD;
    float v0 = xr[tid]       + ar[tid];
    float v1 = xr[tid + 256] + ar[tid + 256];
    red[tid] = v0 + v1;
    __syncthreads();
    for (int st = 128; st; st >>= 1) { if (tid < st) red[tid] += red[tid+st]; __syncthreads(); }
    if (tid == 0) stats[0] = red[0] * (1.f/DD);
    __syncthreads();
    float mean = stats[0];
    float d0 = v0 - mean, d1 = v1 - mean;
    red[tid] = d0*d0 + d1*d1;
    __syncthreads();
    for (int st = 128; st; st >>= 1) { if (tid < st) red[tid] += red[tid+st]; __syncthreads(); }
    if (tid == 0) stats[1] = rsqrtf(red[0]*(1.f/DD) + EPSV);
    __syncthreads();
    float inv = stats[1];
    xr[tid]       = d0*inv*g[tid]       + bb[tid];
    xr[tid + 256] = d1*inv*g[tid + 256] + bb[tid + 256];
}

// ------------------- velocity loss partials + pred_x1 ------------------------
__global__ void velpred_kernel(const float* __restrict__ t, const float* __restrict__ x0) {
    int nv = g_nvalid;
    int total = nv * DD;
    float lsum = 0.f;
    for (int e = blockIdx.x*blockDim.x + threadIdx.x; e < total; e += gridDim.x*blockDim.x) {
        int r = e / DD, d = e % DD;
        int orig = g_comporig[r];
        int b = orig / WIN;
        float pv = g_predv[e];
        float diff = pv - (g_x1[(size_t)orig*DD + d] - x0[(size_t)orig*DD + d]);
        lsum += diff*diff;
        g_predx1[e] = g_xt[(size_t)orig*DD + d] + (1.f - t[b])*pv;
    }
    __shared__ float sm[256];
    sm[threadIdx.x] = lsum;
    __syncthreads();
    for (int st = 128; st; st >>= 1) { if (threadIdx.x < st) sm[threadIdx.x] += sm[threadIdx.x+st]; __syncthreads(); }
    if (threadIdx.x == 0) g_velred[blockIdx.x] = sm[0];
}

// ------------------- picked logit --------------------------------------------
__global__ void picked_kernel(const float* __restrict__ decW, const float* __restrict__ decB) {
    int r = blockIdx.x*8 + threadIdx.x/32;
    int lane = threadIdx.x % 32;
    if (r >= g_nvalid) return;
    int lab = g_complabel[r];
    const float* a = g_hadapt + (size_t)r*DD;
    const float* w = decW + (size_t)lab*DD;
    float s = 0.f;
    for (int i = lane; i < DD; i += 32) s += a[i]*w[i];
#pragma unroll
    for (int off = 16; off; off >>= 1) s += __shfl_xor_sync(0xffffffffu, s, off);
    if (lane == 0) g_picked[r] = s + decB[lab];
}

// ------------------- logsumexp combine ---------------------------------------
__global__ void combine_kernel() {
    int r = blockIdx.x;
    int nv = g_nvalid;
    float m = -1e30f, s = 0.f;
    if (r < nv) {
        for (int i = threadIdx.x; i < NCHUNK; i += blockDim.x) {
            float2 p = g_smpart[(size_t)r*NCHUNK + i];
            if (p.x > m) { s = s*expf(m - p.x) + p.y; m = p.x; }
            else         { s += p.y*expf(p.x - m); }
        }
    }
    __shared__ float sm[128], ss[128];
    sm[threadIdx.x] = m; ss[threadIdx.x] = s;
    __syncthreads();
    for (int st = 64; st; st >>= 1) {
        if (threadIdx.x < st) {
            float m1 = sm[threadIdx.x], s1 = ss[threadIdx.x];
            float m2 = sm[threadIdx.x+st], s2 = ss[threadIdx.x+st];
            float M = fmaxf(m1, m2);
            sm[threadIdx.x] = M;
            ss[threadIdx.x] = s1*expf(m1 - M) + s2*expf(m2 - M);
        }
        __syncthreads();
    }
    if (threadIdx.x == 0) {
        if (r < nv) {
            float lse = sm[0] + logf(ss[0]);
            g_rowrecon[r] = lse - g_picked[r];
        } else {
            g_rowrecon[r] = 0.f;
        }
    }
}

// ------------------- final loss ----------------------------------------------
__global__ void final_kernel(float* __restrict__ out) {
    __shared__ float sm[256];
    int tid = threadIdx.x;
    int nv = g_nvalid;
    sm[tid] = g_velred[tid];
    __syncthreads();
    for (int st = 128; st; st >>= 1) { if (tid < st) sm[tid] += sm[tid+st]; __syncthreads(); }
    float vel = sm[0] / ((float)nv * (float)DD);
    __syncthreads();
    float r = 0.f;
    for (int i = tid; i < nv; i += 256) r += g_rowrecon[i];
    sm[tid] = r;
    __syncthreads();
    for (int st = 128; st; st >>= 1) { if (tid < st) sm[tid] += sm[tid+st]; __syncthreads(); }
    if (tid == 0) out[0] = vel + 0.1f * (sm[0] / (float)nv);
}

// ------------------- host side -----------------------------------------------
static void launch_gemm(const float* A, const float* W, const float* bias, float* C,
                        int M, int N, int K, int use_nv, int use_amap, int relu) {
    dim3 grid((N + 63)/64, (M + 63)/64);
    gemm_kernel<<<grid, 256>>>(A, W, bias, C, M, N, K, use_nv, use_amap, relu);
}

extern "C" void kernel_launch(void* const* d_in, const int* in_sizes, int n_in,
                              void* d_out, int out_size) {
    (void)in_sizes; (void)n_in; (void)out_size;
    const int*   tok       = (const int*)  d_in[0];
    const int*   motif_ids = (const int*)  d_in[1];
    const int*   motif_len = (const int*)  d_in[2];
    const int*   ws        = (const int*)  d_in[3];
    const int*   we        = (const int*)  d_in[4];
    const float* t         = (const float*)d_in[5];
    const float* x0        = (const float*)d_in[6];
    const float* emb       = (const float*)d_in[7];
    const float* decW      = (const float*)d_in[8];
    const float* decB      = (const float*)d_in[9];
    const float* adW       = (const float*)d_in[10];
    const float* adB       = (const float*)d_in[11];
    const float* tpW       = (const float*)d_in[12];
    const float* tpB       = (const float*)d_in[13];
    const float* cpW       = (const float*)d_in[14];
    const float* cpB       = (const float*)d_in[15];
    const float* qkvW      = (const float*)d_in[16];
    const float* qkvB      = (const float*)d_in[17];
    const float* aoW       = (const float*)d_in[18];
    const float* aoB       = (const float*)d_in[19];
    const float* f1W       = (const float*)d_in[20];
    const float* f1B       = (const float*)d_in[21];
    const float* f2W       = (const float*)d_in[22];
    const float* f2B       = (const float*)d_in[23];
    const float* ln1g      = (const float*)d_in[24];
    const float* ln1b      = (const float*)d_in[25];
    const float* ln2g      = (const float*)d_in[26];
    const float* ln2b      = (const float*)d_in[27];
    const float* outW      = (const float*)d_in[28];
    const float* outB      = (const float*)d_in[29];

    static bool inited = false;
    static float *p_tin, *p_temb, *p_condin, *p_condout, *p_x, *p_qkv, *p_ctx, *p_tmp,
                 *p_ff, *p_predv, *p_predx1, *p_hadapt;
    if (!inited) {
        cudaGetSymbolAddress((void**)&p_tin,     g_tin);
        cudaGetSymbolAddress((void**)&p_temb,    g_temb);
        cudaGetSymbolAddress((void**)&p_condin,  g_condin);
        cudaGetSymbolAddress((void**)&p_condout, g_condout);
        cudaGetSymbolAddress((void**)&p_x,       g_x);
        cudaGetSymbolAddress((void**)&p_qkv,     g_qkv);
        cudaGetSymbolAddress((void**)&p_ctx,     g_ctx);
        cudaGetSymbolAddress((void**)&p_tmp,     g_tmp);
        cudaGetSymbolAddress((void**)&p_ff,      g_ff);
        cudaGetSymbolAddress((void**)&p_predv,   g_predv);
        cudaGetSymbolAddress((void**)&p_predx1,  g_predx1);
        cudaGetSymbolAddress((void**)&p_hadapt,  g_hadapt);
        inited = true;
    }

    // pools + cond input
    pool_partial<<<dim3(BB, 8), 512>>>(tok, ws, we, emb);
    pool_reduce<<<BB, 512>>>(motif_ids, motif_len, ws, we, emb);
    // time embedding
    tin_build<<<BB, 512>>>(t);
    launch_gemm(p_tin, tpW, tpB, p_temb, BB, DD, DD, 0, 0, 0);
    // cond projection -> x row 0
    launch_gemm(p_condin, cpW, cpB, p_condout, BB, DD, 4*DD, 0, 0, 0);
    copy_cond<<<BB, 512>>>();
    // x_t / x1 / x rows 1..128
    build_x<<<(BB*WIN*DD + 255)/256, 256>>>(tok, ws, we, t, x0, emb);
    // valid-row compaction
    compact_kernel<<<1, 256>>>(tok, ws, we);

    // transformer layers
    for (int i = 0; i < NLAYER; i++) {
        launch_gemm(p_x, qkvW + (size_t)i*3*DD*DD, qkvB + (size_t)i*3*DD, p_qkv,
                    RT, 3*DD, DD, 0, 0, 0);
        attn_scores<<<BB*HH, 256>>>();
        attn_softmax<<<(BB*HH*SS + 3)/4, 128>>>();
        attn_ctx<<<BB*HH, 256>>>();
        launch_gemm(p_ctx, aoW + (size_t)i*DD*DD, aoB + (size_t)i*DD, p_tmp,
                    RT, DD, DD, 0, 0, 0);
        ln_kernel<<<RT, 256>>>(p_x, p_tmp, ln1g + (size_t)i*DD, ln1b + (size_t)i*DD);
        launch_gemm(p_x, f1W + (size_t)i*FF*DD, f1B + (size_t)i*FF, p_ff,
                    RT, FF, DD, 0, 0, 1);
        launch_gemm(p_ff, f2W + (size_t)i*DD*FF, f2B + (size_t)i*DD, p_tmp,
                    RT, DD, FF, 0, 0, 0);
        ln_kernel<<<RT, 256>>>(p_x, p_tmp, ln2g + (size_t)i*DD, ln2b + (size_t)i*DD);
    }

    // pred_v over valid rows only (A indirected through g_amap into x)
    launch_gemm(p_x, outW, outB, p_predv, WR, DD, DD, 1, 1, 0);
    velpred_kernel<<<256, 256>>>(t, x0);
    // adapter over valid rows
    launch_gemm(p_predx1, adW, adB, p_hadapt, WR, DD, DD, 1, 0, 0);
    // decode GEMM with fused online softmax partials
    decode_kernel<<<dim3(NCHUNK, (WR + 63)/64), 256>>>(p_hadapt, decW, decB);
    picked_kernel<<<WR/8, 256>>>(decW, decB);
    combine_kernel<<<WR, 128>>>();
    final_kernel<<<1, 256>>>((float*)d_out);
}

// round 3
// speedup vs baseline: 1.7009x; 1.7009x over previous
#include <cuda_runtime.h>
#include <cuda_bf16.h>
#include <cuda_pipeline.h>
#include <mma.h>
#include <math.h>

using namespace nvcuda;

#define BB 16
#define LL 2048
#define WIN 128
#define DD 512
#define HH 8
#define HD 64
#define FF 2048
#define NLAYER 3
#define VV 32000
#define MMOT 32
#define SS 129            // WIN + 1 (cond row)
#define RT (BB*SS)        // 2064 transformer rows
#define WR (BB*WIN)       // 2048 window rows
#define EPSV 1e-5f
#define NCH2 (VV/128)     // 250 softmax partial chunks
#define SA 40             // padded smem row stride (elems), 80B = multiple of 16B

// ------------------- device scratch (static, no allocation) -------------------
__device__ float g_condin[BB*4*DD];
__device__ float g_poolpart[BB*8*3*DD];
__device__ float g_tin[BB*DD];
__device__ float g_temb[BB*DD];
__device__ float g_condout[BB*DD];
__device__ float g_x[RT*DD];
__device__ float g_xt[WR*DD];
__device__ float g_x1[WR*DD];
__device__ float g_qkv[RT*3*DD];
__device__ float g_scores[BB*HH*SS*SS];
__device__ float g_tmp[RT*DD];
__device__ float g_predv[WR*DD];
__device__ float2 g_smpart[(size_t)WR*NCH2];
__device__ float g_picked[WR];
__device__ float g_rowrecon[WR];
__device__ float g_velred[256];
__device__ int g_comporig[WR];
__device__ int g_complabel[WR];
__device__ int g_amap[WR];
__device__ int g_nvalid;

// bf16 activations
__device__ __nv_bfloat16 g_xb[RT*DD];
__device__ __nv_bfloat16 g_ctxb[RT*DD];
__device__ __nv_bfloat16 g_ffb[RT*FF];
__device__ __nv_bfloat16 g_px1b[WR*DD];
__device__ __nv_bfloat16 g_hab[WR*DD];
// bf16 weights
__device__ __nv_bfloat16 g_wqkv[NLAYER*3*DD*DD];
__device__ __nv_bfloat16 g_wao[NLAYER*DD*DD];
__device__ __nv_bfloat16 g_wf1[NLAYER*FF*DD];
__device__ __nv_bfloat16 g_wf2[NLAYER*DD*FF];
__device__ __nv_bfloat16 g_wout[DD*DD];
__device__ __nv_bfloat16 g_wad[DD*DD];
__device__ __nv_bfloat16 g_wdec[(size_t)VV*DD];

// ------------------- fp32 -> bf16 conversion ---------------------------------
__global__ void f2b_kernel(const float4* __restrict__ s, __nv_bfloat16* __restrict__ d, int n4) {
    int i = blockIdx.x*blockDim.x + threadIdx.x;
    if (i >= n4) return;
    float4 v = s[i];
    __nv_bfloat162* o = (__nv_bfloat162*)d;
    o[i*2]   = __float22bfloat162_rn(make_float2(v.x, v.y));
    o[i*2+1] = __float22bfloat162_rn(make_float2(v.z, v.w));
}

// ------------------- async tile fill helper ----------------------------------
// Fill a 128x32 bf16 tile (row stride SA) from rows of src [*,K].
__device__ __forceinline__ void issue_tileA(const __nv_bfloat16* A, int K, int k0,
                                            __nv_bfloat16* sa, const int* amap_s, int tid) {
    // 512 chunks of 8 elems; 2 per thread
    int c0 = tid*2;
    int row0 = c0 >> 2, kc0 = (c0 & 3) << 3;
    int ar0 = amap_s[row0];
    __pipeline_memcpy_async(sa + row0*SA + kc0,
                            A + (size_t)(ar0 < 0 ? 0 : ar0)*K + k0 + kc0, 16);
    int c1 = c0 + 1;
    int row1 = c1 >> 2, kc1 = (c1 & 3) << 3;
    int ar1 = amap_s[row1];
    __pipeline_memcpy_async(sa + row1*SA + kc1,
                            A + (size_t)(ar1 < 0 ? 0 : ar1)*K + k0 + kc1, 16);
}
__device__ __forceinline__ void issue_tileB(const __nv_bfloat16* B, int K, int k0,
                                            __nv_bfloat16* sb, int Brow0, int tid) {
    int c0 = tid*2;
    int row0 = c0 >> 2, kc0 = (c0 & 3) << 3;
    __pipeline_memcpy_async(sb + row0*SA + kc0,
                            B + (size_t)(Brow0 + row0)*K + k0 + kc0, 16);
    int c1 = c0 + 1;
    int row1 = c1 >> 2, kc1 = (c1 & 3) << 3;
    __pipeline_memcpy_async(sb + row1*SA + kc1,
                            B + (size_t)(Brow0 + row1)*K + k0 + kc1, 16);
}

// ------------------- bf16 WMMA GEMM: C = A @ W^T + bias ----------------------
// A [M,K] bf16 rowmajor (rows optionally indirected via g_amap), W [N,K] bf16.
// 128x128x32 tiles, 256 threads: 8 warps as 2Mx4N, each warp 64x32 (4x2 wmma).
__global__ void __launch_bounds__(256) gemm_bf(const __nv_bfloat16* __restrict__ A,
                                               const __nv_bfloat16* __restrict__ W,
                                               const float* __restrict__ bias,
                                               float* __restrict__ C,
                                               __nv_bfloat16* __restrict__ Cb,
                                               int Mh, int N, int K,
                                               int use_nv, int use_amap, int relu) {
    __shared__ __nv_bfloat16 sA[2][128*SA];
    __shared__ __nv_bfloat16 sB[2][128*SA];
    __shared__ int amap_s[128];
    int Mact = use_nv ? g_nvalid : Mh;
    int by = blockIdx.y, bx = blockIdx.x;
    if (by*128 >= Mact) return;
    int tid = threadIdx.x;
    if (tid < 128) {
        int m = by*128 + tid;
        amap_s[tid] = (m < Mact) ? (use_amap ? g_amap[m] : m) : -1;
    }
    __syncthreads();
    int lane = tid & 31, wid = tid >> 5;
    int warp_m = wid & 1, warp_n = wid >> 1;
    int Brow0 = bx*128;

    wmma::fragment<wmma::accumulator, 16, 16, 16, float> acc[4][2];
    for (int i = 0; i < 4; i++)
        for (int j = 0; j < 2; j++)
            wmma::fill_fragment(acc[i][j], 0.0f);

    int nk = K/32;
    issue_tileA(A, K, 0, sA[0], amap_s, tid);
    issue_tileB(W, K, 0, sB[0], Brow0, tid);
    __pipeline_commit();
    for (int i = 0; i < nk; i++) {
        if (i + 1 < nk) {
            issue_tileA(A, K, (i+1)*32, sA[(i+1)&1], amap_s, tid);
            issue_tileB(W, K, (i+1)*32, sB[(i+1)&1], Brow0, tid);
            __pipeline_commit();
            __pipeline_wait_prior(1);
        } else {
            __pipeline_wait_prior(0);
        }
        __syncthreads();
        const __nv_bfloat16* sa = sA[i&1];
        const __nv_bfloat16* sb = sB[i&1];
        for (int kk = 0; kk < 32; kk += 16) {
            wmma::fragment<wmma::matrix_a, 16, 16, 16, __nv_bfloat16, wmma::row_major> af[4];
            for (int am = 0; am < 4; am++)
                wmma::load_matrix_sync(af[am], sa + (warp_m*64 + am*16)*SA + kk, SA);
            for (int an = 0; an < 2; an++) {
                wmma::fragment<wmma::matrix_b, 16, 16, 16, __nv_bfloat16, wmma::col_major> bf;
                wmma::load_matrix_sync(bf, sb + (warp_n*32 + an*16)*SA + kk, SA);
                for (int am = 0; am < 4; am++)
                    wmma::mma_sync(acc[am][an], af[am], bf, acc[am][an]);
            }
        }
        __syncthreads();
    }

    // epilogue: stage 16x16 tiles through smem (reuse sA)
    float* stage = ((float*)&sA[0][0]) + wid*256;
    int r = lane >> 1, halfc = (lane & 1)*8;
    for (int am = 0; am < 4; am++) {
        for (int an = 0; an < 2; an++) {
            wmma::store_matrix_sync(stage, acc[am][an], 16, wmma::mem_row_major);
            __syncwarp();
            int grow = by*128 + warp_m*64 + am*16 + r;
            int gcol = bx*128 + warp_n*32 + an*16 + halfc;
            if (grow < Mact) {
                float v[8];
                for (int j = 0; j < 8; j++) {
                    v[j] = stage[r*16 + halfc + j] + bias[gcol + j];
                    if (relu) v[j] = fmaxf(v[j], 0.f);
                }
                if (C) {
                    float4* p = (float4*)(C + (size_t)grow*N + gcol);
                    p[0] = make_float4(v[0], v[1], v[2], v[3]);
                    p[1] = make_float4(v[4], v[5], v[6], v[7]);
                }
                if (Cb) {
                    __nv_bfloat162* p = (__nv_bfloat162*)(Cb + (size_t)grow*N + gcol);
                    p[0] = __float22bfloat162_rn(make_float2(v[0], v[1]));
                    p[1] = __float22bfloat162_rn(make_float2(v[2], v[3]));
                    p[2] = __float22bfloat162_rn(make_float2(v[4], v[5]));
                    p[3] = __float22bfloat162_rn(make_float2(v[6], v[7]));
                }
            }
            __syncwarp();
        }
    }
}

// ------------------- decode GEMM + fused online-softmax partials -------------
__global__ void __launch_bounds__(256) decode_bf(const __nv_bfloat16* __restrict__ A,
                                                 const __nv_bfloat16* __restrict__ W,
                                                 const float* __restrict__ bias) {
    __shared__ __nv_bfloat16 sA[2][128*SA];
    __shared__ __nv_bfloat16 sB[2][128*SA];
    __shared__ int amap_s[128];
    __shared__ float bias_s[128];
    __shared__ float2 red[128][4];
    int Mact = g_nvalid;
    int by = blockIdx.y, bx = blockIdx.x;
    if (by*128 >= Mact) return;
    int tid = threadIdx.x;
    if (tid < 128) {
        int m = by*128 + tid;
        amap_s[tid] = (m < Mact) ? m : -1;
        bias_s[tid] = bias[bx*128 + tid];
    }
    __syncthreads();
    int lane = tid & 31, wid = tid >> 5;
    int warp_m = wid & 1, warp_n = wid >> 1;
    int Brow0 = bx*128;

    wmma::fragment<wmma::accumulator, 16, 16, 16, float> acc[4][2];
    for (int i = 0; i < 4; i++)
        for (int j = 0; j < 2; j++)
            wmma::fill_fragment(acc[i][j], 0.0f);

    int nk = DD/32;
    issue_tileA(A, DD, 0, sA[0], amap_s, tid);
    issue_tileB(W, DD, 0, sB[0], Brow0, tid);
    __pipeline_commit();
    for (int i = 0; i < nk; i++) {
        if (i + 1 < nk) {
            issue_tileA(A, DD, (i+1)*32, sA[(i+1)&1], amap_s, tid);
            issue_tileB(W, DD, (i+1)*32, sB[(i+1)&1], Brow0, tid);
            __pipeline_commit();
            __pipeline_wait_prior(1);
        } else {
            __pipeline_wait_prior(0);
        }
        __syncthreads();
        const __nv_bfloat16* sa = sA[i&1];
        const __nv_bfloat16* sb = sB[i&1];
        for (int kk = 0; kk < 32; kk += 16) {
            wmma::fragment<wmma::matrix_a, 16, 16, 16, __nv_bfloat16, wmma::row_major> af[4];
            for (int am = 0; am < 4; am++)
                wmma::load_matrix_sync(af[am], sa + (warp_m*64 + am*16)*SA + kk, SA);
            for (int an = 0; an < 2; an++) {
                wmma::fragment<wmma::matrix_b, 16, 16, 16, __nv_bfloat16, wmma::col_major> bf;
                wmma::load_matrix_sync(bf, sb + (warp_n*32 + an*16)*SA + kk, SA);
                for (int am = 0; am < 4; am++)
                    wmma::mma_sync(acc[am][an], af[am], bf, acc[am][an]);
            }
        }
        __syncthreads();
    }

    // epilogue: per-row (max, sum-exp) over this block's 128 cols
    float* stage = ((float*)&sA[0][0]) + wid*256;
    int r = lane >> 1, halfc = (lane & 1)*8;
    float rm[4], rs[4];
    for (int am = 0; am < 4; am++) { rm[am] = -1e30f; rs[am] = 0.f; }
    for (int am = 0; am < 4; am++) {
        for (int an = 0; an < 2; an++) {
            wmma::store_matrix_sync(stage, acc[am][an], 16, wmma::mem_row_major);
            __syncwarp();
            int coll = warp_n*32 + an*16 + halfc;
            float vv[8];
            float mx = -1e30f;
            for (int j = 0; j < 8; j++) {
                vv[j] = stage[r*16 + halfc + j] + bias_s[coll + j];
                mx = fmaxf(mx, vv[j]);
            }
            float mxo = __shfl_xor_sync(0xffffffffu, mx, 1);
            float mxa = fmaxf(mx, mxo);
            float se = 0.f;
            for (int j = 0; j < 8; j++) se += expf(vv[j] - mxa);
            se += __shfl_xor_sync(0xffffffffu, se, 1);
            // merge (mxa, se) into running (rm, rs)
            if (mxa > rm[am]) { rs[am] = rs[am]*expf(rm[am] - mxa) + se; rm[am] = mxa; }
            else              { rs[am] += se*expf(mxa - rm[am]); }
            __syncwarp();
        }
    }
    for (int am = 0; am < 4; am++) {
        int rl = warp_m*64 + am*16 + r;
        if ((lane & 1) == 0) red[rl][warp_n] = make_float2(rm[am], rs[am]);
    }
    __syncthreads();
    if (tid < 128) {
        int grow = by*128 + tid;
        if (grow < Mact) {
            float m = -1e30f, s = 0.f;
            for (int w = 0; w < 4; w++) {
                float2 p = red[tid][w];
                if (p.x > m) { s = s*expf(m - p.x) + p.y; m = p.x; }
                else         { s += p.y*expf(p.x - m); }
            }
            g_smpart[(size_t)grow*NCH2 + bx] = make_float2(m, s);
        }
    }
}

// ------------------- pools: left/right/glob partial sums ---------------------
__global__ void pool_partial(const int* __restrict__ tok, const int* __restrict__ ws,
                             const int* __restrict__ we, const float* __restrict__ emb) {
    int b = blockIdx.x, c = blockIdx.y, d = threadIdx.x;
    int s0 = ws[b], e0 = we[b];
    float gl = 0.f, lf = 0.f, rt = 0.f;
    int l0 = c * (LL/8);
#pragma unroll 4
    for (int i = 0; i < LL/8; i++) {
        int l = l0 + i;
        int t = tok[b*LL + l];
        float v = emb[(size_t)t*DD + d];
        gl += v;
        if (l < s0)  lf += v;
        if (l >= e0) rt += v;
    }
    float* p = g_poolpart + ((size_t)(b*8 + c)*3)*DD;
    p[d] = lf; p[DD + d] = rt; p[2*DD + d] = gl;
}

__global__ void pool_reduce(const int* __restrict__ mot, const int* __restrict__ mlen,
                            const int* __restrict__ ws, const int* __restrict__ we,
                            const float* __restrict__ emb) {
    int b = blockIdx.x, d = threadIdx.x;
    float lf = 0.f, rt = 0.f, gl = 0.f;
    for (int c = 0; c < 8; c++) {
        const float* p = g_poolpart + ((size_t)(b*8 + c)*3)*DD;
        lf += p[d]; rt += p[DD + d]; gl += p[2*DD + d];
    }
    int ml = mlen[b];
    float mo = 0.f;
    for (int i = 0; i < MMOT; i++)
        if (i < ml) mo += emb[(size_t)mot[b*MMOT + i]*DD + d];
    mo /= (float)(ml > 1 ? ml : 1);
    float lden = (float)(ws[b] > 1 ? ws[b] : 1);
    int rc = LL - we[b];
    float rden = (float)(rc > 1 ? rc : 1);
    float* o = g_condin + (size_t)b*4*DD;
    o[d]        = mo;
    o[DD + d]   = lf / lden;
    o[2*DD + d] = rt / rden;
    o[3*DD + d] = gl / (float)LL;
}

// ------------------- time embedding input (sin/cos) --------------------------
__global__ void tin_build(const float* __restrict__ t) {
    int b = blockIdx.x, d = threadIdx.x;
    int k = d % (DD/2);
    float f = expf(-logf(10000.f) * (float)k / (float)(DD/2 - 1));
    float a = t[b] * f;
    g_tin[b*DD + d] = (d < DD/2) ? sinf(a) : cosf(a);
}

__global__ void copy_cond() {
    int b = blockIdx.x, d = threadIdx.x;
    float v = g_condout[b*DD + d];
    g_x[(size_t)b*SS*DD + d] = v;
    g_xb[(size_t)b*SS*DD + d] = __float2bfloat16(v);
}

// ------------------- build x_t, x1, x ----------------------------------------
__global__ void build_x(const int* __restrict__ tok, const int* __restrict__ ws,
                        const int* __restrict__ we, const float* __restrict__ t,
                        const float* __restrict__ x0, const float* __restrict__ emb) {
    int idx = blockIdx.x*blockDim.x + threadIdx.x;
    if (idx >= BB*WIN*DD) return;
    int d = idx % DD; int r = idx / DD; int j = r % WIN; int b = r / WIN;
    int s0 = ws[b];
    int act = we[b] - s0;
    float x1v = 0.f;
    if (j < act) {
        int tk = tok[b*LL + s0 + j];
        x1v = emb[(size_t)tk*DD + d];
    }
    float tv = t[b];
    float xt = (1.f - tv)*x0[idx] + tv*x1v;
    g_x1[idx] = x1v;
    g_xt[idx] = xt;
    float xv = xt + g_temb[b*DD + d];
    g_x[((size_t)b*SS + 1 + j)*DD + d] = xv;
    g_xb[((size_t)b*SS + 1 + j)*DD + d] = __float2bfloat16(xv);
}

// ------------------- valid-row compaction ------------------------------------
__global__ void compact_kernel(const int* __restrict__ tok, const int* __restrict__ ws,
                               const int* __restrict__ we) {
    __shared__ int off[BB+1];
    if (threadIdx.x == 0) {
        off[0] = 0;
        for (int b = 0; b < BB; b++) {
            int a = we[b] - ws[b];
            if (a < 0) a = 0;
            if (a > WIN) a = WIN;
            off[b+1] = off[b] + a;
        }
        g_nvalid = off[BB];
    }
    __syncthreads();
    for (int idx = threadIdx.x; idx < BB*WIN; idx += blockDim.x) {
        int b = idx / WIN, j = idx % WIN;
        int a = off[b+1] - off[b];
        if (j < a) {
            int r = off[b] + j;
            g_comporig[r]  = idx;
            g_amap[r]      = b*SS + 1 + j;
            g_complabel[r] = tok[b*LL + ws[b] + j];
        }
    }
}

// ------------------- small fp32 SGEMM (tiny M=16 GEMMs only) -----------------
__global__ void gemm_small(const float* __restrict__ A, const float* __restrict__ Wt,
                           const float* __restrict__ bias, float* __restrict__ C,
                           int M, int N, int K) {
    int n0 = blockIdx.x*64;
    int tid = threadIdx.x;
    int col = n0 + (tid & 63);
    for (int row = tid >> 6; row < M; row += 4) {
        if (col < N) {
            const float* a = A + (size_t)row*K;
            const float* w = Wt + (size_t)col*K;
            float s = 0.f;
            for (int k = 0; k < K; k += 4) {
                float4 av = *(const float4*)(a + k);
                float4 wv = *(const float4*)(w + k);
                s += av.x*wv.x + av.y*wv.y + av.z*wv.z + av.w*wv.w;
            }
            C[(size_t)row*N + col] = s + bias[col];
        }
    }
}

// ------------------- attention ----------------------------------------------
__global__ void attn_scores() {
    int bh = blockIdx.x; int b = bh / HH, h = bh % HH;
    __shared__ float ks[SS][HD];
    const float* base = g_qkv + (size_t)b*SS*3*DD;
    for (int i = threadIdx.x; i < SS*HD; i += blockDim.x) {
        int s = i / HD, d = i % HD;
        ks[s][d] = base[(size_t)s*3*DD + DD + h*HD + d];
    }
    __syncthreads();
    int q = threadIdx.x;
    if (q < SS) {
        float qr[HD];
#pragma unroll
        for (int d = 0; d < HD; d++) qr[d] = base[(size_t)q*3*DD + h*HD + d];
        float* srow = g_scores + ((size_t)bh*SS + q)*SS;
        for (int k = 0; k < SS; k++) {
            const float4* k4 = (const float4*)ks[k];
            float a = 0.f;
#pragma unroll
            for (int dq = 0; dq < 16; dq++) {
                float4 kv = k4[dq];
                a += qr[4*dq+0]*kv.x + qr[4*dq+1]*kv.y + qr[4*dq+2]*kv.z + qr[4*dq+3]*kv.w;
            }
            srow[k] = a * 0.125f;
        }
    }
}

__global__ void attn_softmax() {
    int row = blockIdx.x*4 + threadIdx.x/32;
    int lane = threadIdx.x % 32;
    if (row >= BB*HH*SS) return;
    float* p = g_scores + (size_t)row*SS;
    float v[5];
    float mx = -1e30f;
    int cnt = 0;
    for (int i = lane; i < SS; i += 32) { v[cnt] = p[i]; mx = fmaxf(mx, v[cnt]); cnt++; }
#pragma unroll
    for (int off = 16; off; off >>= 1) mx = fmaxf(mx, __shfl_xor_sync(0xffffffffu, mx, off));
    float se = 0.f;
    for (int c = 0; c < cnt; c++) { v[c] = expf(v[c]-mx); se += v[c]; }
#pragma unroll
    for (int off = 16; off; off >>= 1) se += __shfl_xor_sync(0xffffffffu, se, off);
    float inv = 1.f/se;
    cnt = 0;
    for (int i = lane; i < SS; i += 32) { p[i] = v[cnt]*inv; cnt++; }
}

__global__ void attn_ctx() {
    int bh = blockIdx.x; int b = bh / HH, h = bh % HH;
    __shared__ float vs[SS][HD];
    const float* base = g_qkv + (size_t)b*SS*3*DD + 2*DD + h*HD;
    for (int i = threadIdx.x; i < SS*HD; i += blockDim.x) {
        int s = i / HD, d = i % HD;
        vs[s][d] = base[(size_t)s*3*DD + d];
    }
    __syncthreads();
    for (int i = threadIdx.x; i < SS*HD; i += blockDim.x) {
        int q = i / HD, d = i % HD;
        const float* pr = g_scores + ((size_t)bh*SS + q)*SS;
        float a = 0.f;
        for (int k = 0; k < SS; k++) a += pr[k]*vs[k][d];
        g_ctxb[((size_t)b*SS + q)*DD + h*HD + d] = __float2bfloat16(a);
    }
}

// ------------------- residual + layernorm (fp32 + bf16 out) ------------------
__global__ void ln_kernel(float* __restrict__ x, __nv_bfloat16* __restrict__ xb,
                          const float* __restrict__ add,
                          const float* __restrict__ gam, const float* __restrict__ bet) {
    __shared__ float red[256];
    __shared__ float stats[2];
    int tid = threadIdx.x;
    float* xr = x + (size_t)blockIdx.x*DD;
    __nv_bfloat16* xbr = xb + (size_t)blockIdx.x*DD;
    const float* ar = add + (size_t)blockIdx.x*DD;
    float v0 = xr[tid]       + ar[tid];
    float v1 = xr[tid + 256] + ar[tid + 256];
    red[tid] = v0 + v1;
    __syncthreads();
    for (int st = 128; st; st >>= 1) { if (tid < st) red[tid] += red[tid+st]; __syncthreads(); }
    if (tid == 0) stats[0] = red[0] * (1.f/DD);
    __syncthreads();
    float mean = stats[0];
    float d0 = v0 - mean, d1 = v1 - mean;
    red[tid] = d0*d0 + d1*d1;
    __syncthreads();
    for (int st = 128; st; st >>= 1) { if (tid < st) red[tid] += red[tid+st]; __syncthreads(); }
    if (tid == 0) stats[1] = rsqrtf(red[0]*(1.f/DD) + EPSV);
    __syncthreads();
    float inv = stats[1];
    float o0 = d0*inv*gam[tid]       + bet[tid];
    float o1 = d1*inv*gam[tid + 256] + bet[tid + 256];
    xr[tid]        = o0;
    xr[tid + 256]  = o1;
    xbr[tid]       = __float2bfloat16(o0);
    xbr[tid + 256] = __float2bfloat16(o1);
}

// ------------------- velocity loss partials + pred_x1 (bf16) -----------------
__global__ void velpred_kernel(const float* __restrict__ t, const float* __restrict__ x0) {
    int nv = g_nvalid;
    int total = nv * DD;
    float lsum = 0.f;
    for (int e = blockIdx.x*blockDim.x + threadIdx.x; e < total; e += gridDim.x*blockDim.x) {
        int r = e / DD, d = e % DD;
        int orig = g_comporig[r];
        int b = orig / WIN;
        float pv = g_predv[e];
        float diff = pv - (g_x1[(size_t)orig*DD + d] - x0[(size_t)orig*DD + d]);
        lsum += diff*diff;
        g_px1b[e] = __float2bfloat16(g_xt[(size_t)orig*DD + d] + (1.f - t[b])*pv);
    }
    __shared__ float sm[256];
    sm[threadIdx.x] = lsum;
    __syncthreads();
    for (int st = 128; st; st >>= 1) { if (threadIdx.x < st) sm[threadIdx.x] += sm[threadIdx.x+st]; __syncthreads(); }
    if (threadIdx.x == 0) g_velred[blockIdx.x] = sm[0];
}

// ------------------- picked logit (bf16 inputs) ------------------------------
__global__ void picked_kernel(const float* __restrict__ decB) {
    int r = blockIdx.x*8 + threadIdx.x/32;
    int lane = threadIdx.x % 32;
    if (r >= g_nvalid) return;
    int lab = g_complabel[r];
    const __nv_bfloat16* a = g_hab + (size_t)r*DD;
    const __nv_bfloat16* w = g_wdec + (size_t)lab*DD;
    float s = 0.f;
    for (int i = lane; i < DD; i += 32)
        s += __bfloat162float(a[i]) * __bfloat162float(w[i]);
#pragma unroll
    for (int off = 16; off; off >>= 1) s += __shfl_xor_sync(0xffffffffu, s, off);
    if (lane == 0) g_picked[r] = s + decB[lab];
}

// ------------------- logsumexp combine ---------------------------------------
__global__ void combine_kernel() {
    int r = blockIdx.x;
    int nv = g_nvalid;
    float m = -1e30f, s = 0.f;
    if (r < nv) {
        for (int i = threadIdx.x; i < NCH2; i += blockDim.x) {
            float2 p = g_smpart[(size_t)r*NCH2 + i];
            if (p.x > m) { s = s*expf(m - p.x) + p.y; m = p.x; }
            else         { s += p.y*expf(p.x - m); }
        }
    }
    __shared__ float sm[128], ss[128];
    sm[threadIdx.x] = m; ss[threadIdx.x] = s;
    __syncthreads();
    for (int st = 64; st; st >>= 1) {
        if (threadIdx.x < st) {
            float m1 = sm[threadIdx.x], s1 = ss[threadIdx.x];
            float m2 = sm[threadIdx.x+st], s2 = ss[threadIdx.x+st];
            float M = fmaxf(m1, m2);
            sm[threadIdx.x] = M;
            ss[threadIdx.x] = s1*expf(m1 - M) + s2*expf(m2 - M);
        }
        __syncthreads();
    }
    if (threadIdx.x == 0) {
        if (r < nv) {
            float lse = sm[0] + logf(ss[0]);
            g_rowrecon[r] = lse - g_picked[r];
        } else {
            g_rowrecon[r] = 0.f;
        }
    }
}

// ------------------- final loss ----------------------------------------------
__global__ void final_kernel(float* __restrict__ out) {
    __shared__ float sm[256];
    int tid = threadIdx.x;
    int nv = g_nvalid;
    sm[tid] = g_velred[tid];
    __syncthreads();
    for (int st = 128; st; st >>= 1) { if (tid < st) sm[tid] += sm[tid+st]; __syncthreads(); }
    float vel = sm[0] / ((float)nv * (float)DD);
    __syncthreads();
    float r = 0.f;
    for (int i = tid; i < nv; i += 256) r += g_rowrecon[i];
    sm[tid] = r;
    __syncthreads();
    for (int st = 128; st; st >>= 1) { if (tid < st) sm[tid] += sm[tid+st]; __syncthreads(); }
    if (tid == 0) out[0] = vel + 0.1f * (sm[0] / (float)nv);
}

// ------------------- host side -----------------------------------------------
static void conv_w(const float* src, __nv_bfloat16* dst, size_t n) {
    int n4 = (int)(n / 4);
    f2b_kernel<<<(n4 + 255)/256, 256>>>((const float4*)src, dst, n4);
}

extern "C" void kernel_launch(void* const* d_in, const int* in_sizes, int n_in,
                              void* d_out, int out_size) {
    (void)in_sizes; (void)n_in; (void)out_size;
    const int*   tok       = (const int*)  d_in[0];
    const int*   motif_ids = (const int*)  d_in[1];
    const int*   motif_len = (const int*)  d_in[2];
    const int*   ws        = (const int*)  d_in[3];
    const int*   we        = (const int*)  d_in[4];
    const float* t         = (const float*)d_in[5];
    const float* x0        = (const float*)d_in[6];
    const float* emb       = (const float*)d_in[7];
    const float* decW      = (const float*)d_in[8];
    const float* decB      = (const float*)d_in[9];
    const float* adW       = (const float*)d_in[10];
    const float* adB       = (const float*)d_in[11];
    const float* tpW       = (const float*)d_in[12];
    const float* tpB       = (const float*)d_in[13];
    const float* cpW       = (const float*)d_in[14];
    const float* cpB       = (const float*)d_in[15];
    const float* qkvW      = (const float*)d_in[16];
    const float* qkvB      = (const float*)d_in[17];
    const float* aoW       = (const float*)d_in[18];
    const float* aoB       = (const float*)d_in[19];
    const float* f1W       = (const float*)d_in[20];
    const float* f1B       = (const float*)d_in[21];
    const float* f2W       = (const float*)d_in[22];
    const float* f2B       = (const float*)d_in[23];
    const float* ln1g      = (const float*)d_in[24];
    const float* ln1b      = (const float*)d_in[25];
    const float* ln2g      = (const float*)d_in[26];
    const float* ln2b      = (const float*)d_in[27];
    const float* outW      = (const float*)d_in[28];
    const float* outB      = (const float*)d_in[29];

    static bool inited = false;
    static float *p_tin, *p_temb, *p_condin, *p_condout, *p_qkv, *p_tmp, *p_predv;
    static __nv_bfloat16 *p_xb, *p_ctxb, *p_ffb, *p_px1b, *p_hab;
    static __nv_bfloat16 *p_wqkv, *p_wao, *p_wf1, *p_wf2, *p_wout, *p_wad, *p_wdec;
    static float *p_x;
    if (!inited) {
        cudaGetSymbolAddress((void**)&p_tin,     g_tin);
        cudaGetSymbolAddress((void**)&p_temb,    g_temb);
        cudaGetSymbolAddress((void**)&p_condin,  g_condin);
        cudaGetSymbolAddress((void**)&p_condout, g_condout);
        cudaGetSymbolAddress((void**)&p_x,       g_x);
        cudaGetSymbolAddress((void**)&p_qkv,     g_qkv);
        cudaGetSymbolAddress((void**)&p_tmp,     g_tmp);
        cudaGetSymbolAddress((void**)&p_predv,   g_predv);
        cudaGetSymbolAddress((void**)&p_xb,      g_xb);
        cudaGetSymbolAddress((void**)&p_ctxb,    g_ctxb);
        cudaGetSymbolAddress((void**)&p_ffb,     g_ffb);
        cudaGetSymbolAddress((void**)&p_px1b,    g_px1b);
        cudaGetSymbolAddress((void**)&p_hab,     g_hab);
        cudaGetSymbolAddress((void**)&p_wqkv,    g_wqkv);
        cudaGetSymbolAddress((void**)&p_wao,     g_wao);
        cudaGetSymbolAddress((void**)&p_wf1,     g_wf1);
        cudaGetSymbolAddress((void**)&p_wf2,     g_wf2);
        cudaGetSymbolAddress((void**)&p_wout,    g_wout);
        cudaGetSymbolAddress((void**)&p_wad,     g_wad);
        cudaGetSymbolAddress((void**)&p_wdec,    g_wdec);
        inited = true;
    }

    // weight conversions (fp32 -> bf16)
    conv_w(qkvW, p_wqkv, (size_t)NLAYER*3*DD*DD);
    conv_w(aoW,  p_wao,  (size_t)NLAYER*DD*DD);
    conv_w(f1W,  p_wf1,  (size_t)NLAYER*FF*DD);
    conv_w(f2W,  p_wf2,  (size_t)NLAYER*DD*FF);
    conv_w(outW, p_wout, (size_t)DD*DD);
    conv_w(adW,  p_wad,  (size_t)DD*DD);
    conv_w(decW, p_wdec, (size_t)VV*DD);

    // pools + cond input
    pool_partial<<<dim3(BB, 8), 512>>>(tok, ws, we, emb);
    pool_reduce<<<BB, 512>>>(motif_ids, motif_len, ws, we, emb);
    // time embedding
    tin_build<<<BB, 512>>>(t);
    gemm_small<<<DD/64, 256>>>(p_tin, tpW, tpB, p_temb, BB, DD, DD);
    // cond projection -> x row 0
    gemm_small<<<DD/64, 256>>>(p_condin, cpW, cpB, p_condout, BB, DD, 4*DD);
    copy_cond<<<BB, 512>>>();
    // x_t / x1 / x rows 1..128
    build_x<<<(BB*WIN*DD + 255)/256, 256>>>(tok, ws, we, t, x0, emb);
    // valid-row compaction
    compact_kernel<<<1, 256>>>(tok, ws, we);

    // transformer layers
    for (int i = 0; i < NLAYER; i++) {
        gemm_bf<<<dim3(3*DD/128, (RT+127)/128), 256>>>(
            p_xb, p_wqkv + (size_t)i*3*DD*DD, qkvB + (size_t)i*3*DD,
            p_qkv, (__nv_bfloat16*)0, RT, 3*DD, DD, 0, 0, 0);
        attn_scores<<<BB*HH, 256>>>();
        attn_softmax<<<(BB*HH*SS + 3)/4, 128>>>();
        attn_ctx<<<BB*HH, 256>>>();
        gemm_bf<<<dim3(DD/128, (RT+127)/128), 256>>>(
            p_ctxb, p_wao + (size_t)i*DD*DD, aoB + (size_t)i*DD,
            p_tmp, (__nv_bfloat16*)0, RT, DD, DD, 0, 0, 0);
        ln_kernel<<<RT, 256>>>(p_x, p_xb, p_tmp, ln1g + (size_t)i*DD, ln1b + (size_t)i*DD);
        gemm_bf<<<dim3(FF/128, (RT+127)/128), 256>>>(
            p_xb, p_wf1 + (size_t)i*FF*DD, f1B + (size_t)i*FF,
            (float*)0, p_ffb, RT, FF, DD, 0, 0, 1);
        gemm_bf<<<dim3(DD/128, (RT+127)/128), 256>>>(
            p_ffb, p_wf2 + (size_t)i*DD*FF, f2B + (size_t)i*DD,
            p_tmp, (__nv_bfloat16*)0, RT, DD, FF, 0, 0, 0);
        ln_kernel<<<RT, 256>>>(p_x, p_xb, p_tmp, ln2g + (size_t)i*DD, ln2b + (size_t)i*DD);
    }

    // pred_v over valid rows only (rows of x indirected via g_amap)
    gemm_bf<<<dim3(DD/128, (WR+127)/128), 256>>>(
        p_xb, p_wout, outB, p_predv, (__nv_bfloat16*)0, WR, DD, DD, 1, 1, 0);
    velpred_kernel<<<256, 256>>>(t, x0);
    // adapter over compact valid rows
    gemm_bf<<<dim3(DD/128, (WR+127)/128), 256>>>(
        p_px1b, p_wad, adB, (float*)0, p_hab, WR, DD, DD, 1, 0, 0);
    // decode GEMM with fused online softmax partials
    decode_bf<<<dim3(NCH2, (WR+127)/128), 256>>>(p_hab, p_wdec, decB);
    picked_kernel<<<WR/8, 256>>>(decB);
    combine_kernel<<<WR, 128>>>();
    final_kernel<<<1, 256>>>((float*)d_out);
}

// round 4
// speedup vs baseline: 1.8459x; 1.0852x over previous
#include <cuda_runtime.h>
#include <cuda_bf16.h>
#include <mma.h>
#include <math.h>
#include <stdint.h>

using namespace nvcuda;

#define BB 16
#define LL 2048
#define WIN 128
#define DD 512
#define HH 8
#define HD 64
#define FF 2048
#define NLAYER 3
#define VV 32000
#define MMOT 32
#define SS 129            // WIN + 1 (cond row)
#define RT (BB*SS)        // 2064 transformer rows
#define RTP 2176          // RT padded to 128
#define WR (BB*WIN)       // 2048 window rows
#define EPSV 1e-5f
#define NCH2 (VV/128)     // 250 softmax partial chunks

#define TROW 72           // padded tile row stride (elems)
#define TILE_ELEMS (128*TROW)      // 9216
#define TILE_BYTES (TILE_ELEMS*2)  // 18432
#define DYNSM (4*TILE_BYTES + 32)  // 2 stages x (A+B) + barriers

// ---------------- mbarrier / bulk-copy PTX (verbatim-style macros) -----------
#define MBARRIER_INIT(mbar_smem_addr, count) \
    asm volatile("mbarrier.init.shared.b64 [%0], %1;" \
        :: "r"((uint32_t)(mbar_smem_addr)), "r"((uint32_t)(count)) : "memory")

#define MBARRIER_EXPECT_TX(mbar_smem_addr, tx_bytes) \
    asm volatile("mbarrier.arrive.expect_tx.shared.b64 _, [%0], %1;" \
        :: "r"((uint32_t)(mbar_smem_addr)), "r"((uint32_t)(tx_bytes)) : "memory")

#define MBARRIER_WAIT_PARITY(mbar_smem_addr, phase_parity) do { \
    uint32_t _mbar = (uint32_t)(mbar_smem_addr); \
    uint32_t _parity = (uint32_t)(phase_parity); \
    uint32_t _done; \
    asm volatile( \
        "{\n\t" \
        ".reg .pred p;\n\t" \
        "mbarrier.try_wait.parity.acquire.cta.shared::cta.b64 p, [%1], %2;\n\t" \
        "selp.b32 %0, 1, 0, p;\n\t" \
        "}" \
        : "=r"(_done) : "r"(_mbar), "r"(_parity) : "memory"); \
    if (!_done) { \
        asm volatile( \
            "{\n\t" \
            ".reg .pred P1;\n\t" \
            "WAIT_LOOP_%=:\n\t" \
            "mbarrier.try_wait.parity.acquire.cta.shared::cta.b64 P1, [%0], %1, 0x989680;\n\t" \
            "@P1 bra.uni WAIT_DONE_%=;\n\t" \
            "bra.uni WAIT_LOOP_%=;\n\t" \
            "WAIT_DONE_%=:\n\t" \
            "}" \
            :: "r"(_mbar), "r"(_parity) : "memory"); \
    } \
} while(0)

#define BULK_LOAD(dst_smem, src_gmem, nbytes, mbar_smem) \
    asm volatile("cp.async.bulk.shared::cluster.global.mbarrier::complete_tx::bytes [%0], [%1], %2, [%3];" \
        :: "r"((uint32_t)(dst_smem)), "l"(src_gmem), "r"((uint32_t)(nbytes)), \
           "r"((uint32_t)(mbar_smem)) : "memory")

#define FENCE_PROXY_ASYNC() \
    asm volatile("fence.proxy.async.shared::cta;" ::: "memory")

__device__ __forceinline__ uint32_t sptr(const void* p) {
    return (uint32_t)__cvta_generic_to_shared(p);
}

// ------------------- device scratch (static, no allocation) -------------------
__device__ float g_condin[BB*4*DD];
__device__ float g_poolpart[BB*8*3*DD];
__device__ float g_tin[BB*DD];
__device__ float g_temb[BB*DD];
__device__ float g_condout[BB*DD];
__device__ float g_x[RT*DD];
__device__ float g_xt[WR*DD];
__device__ float g_x1[WR*DD];
__device__ float g_qkv[RT*3*DD];
__device__ float g_scores[BB*HH*SS*SS];
__device__ float g_tmp[RT*DD];
__device__ float g_predv[WR*DD];
__device__ float2 g_smpart[(size_t)WR*NCH2];
__device__ float g_picked[WR];
__device__ float g_rowrecon[WR];
__device__ float g_velred[256];
__device__ int g_comporig[WR];
__device__ int g_complabel[WR];
__device__ int g_amap[WR];
__device__ int g_nvalid;

// bf16 activations (16B-aligned for uint4 access)
__device__ __align__(16) __nv_bfloat16 g_xb[RT*DD];
__device__ __align__(16) __nv_bfloat16 g_ctxb[RT*DD];
__device__ __align__(16) __nv_bfloat16 g_ffb[RT*FF];
__device__ __align__(16) __nv_bfloat16 g_px1b[WR*DD];
__device__ __align__(16) __nv_bfloat16 g_hab[WR*DD];

// packed (tile-contiguous) operands: [Nblk][Kchunk] tiles of [128][TROW] bf16
__device__ __align__(16) __nv_bfloat16 g_apack[17*32*TILE_ELEMS];       // max 2176 x 2048
__device__ __align__(16) __nv_bfloat16 g_wqkvP[NLAYER*12*8*TILE_ELEMS];
__device__ __align__(16) __nv_bfloat16 g_waoP[NLAYER*4*8*TILE_ELEMS];
__device__ __align__(16) __nv_bfloat16 g_wf1P[NLAYER*16*8*TILE_ELEMS];
__device__ __align__(16) __nv_bfloat16 g_wf2P[NLAYER*4*32*TILE_ELEMS];
__device__ __align__(16) __nv_bfloat16 g_woutP[4*8*TILE_ELEMS];
__device__ __align__(16) __nv_bfloat16 g_wadP[4*8*TILE_ELEMS];
__device__ __align__(16) __nv_bfloat16 g_wdecP[250*8*TILE_ELEMS];

// ------------------- pack kernels --------------------------------------------
// weights: fp32 [N,K] row-major -> bf16 packed tiles
__global__ void wpack_kernel(const float4* __restrict__ W, uint4* __restrict__ out,
                             int N, int K) {
    int idx = blockIdx.x*blockDim.x + threadIdx.x;   // one 8-elem chunk
    int ck = K >> 3;
    if (idx >= N*ck) return;
    int n = idx / ck, q = idx - n*ck;
    int k = q << 3;
    int kc = k >> 6, c8 = (k >> 3) & 7;
    int KC = K >> 6;
    size_t doff = ((size_t)(n >> 7)*KC + kc)*TILE_ELEMS + (size_t)(n & 127)*TROW + c8*8;
    float4 a = W[(size_t)idx*2], b = W[(size_t)idx*2 + 1];
    __nv_bfloat162 r0 = __float22bfloat162_rn(make_float2(a.x, a.y));
    __nv_bfloat162 r1 = __float22bfloat162_rn(make_float2(a.z, a.w));
    __nv_bfloat162 r2 = __float22bfloat162_rn(make_float2(b.x, b.y));
    __nv_bfloat162 r3 = __float22bfloat162_rn(make_float2(b.z, b.w));
    uint4 v;
    v.x = *(uint32_t*)&r0; v.y = *(uint32_t*)&r1;
    v.z = *(uint32_t*)&r2; v.w = *(uint32_t*)&r3;
    out[doff >> 3] = v;
}

// activations: bf16 [*,K] row-major (optional amap gather / nvalid bound) -> packed
__global__ void apack_kernel(const __nv_bfloat16* __restrict__ A, __nv_bfloat16* __restrict__ outh,
                             int Mpad, int K, int Mh, int use_nv, int use_amap) {
    int idx = blockIdx.x*blockDim.x + threadIdx.x;
    int ck = K >> 3;
    if (idx >= Mpad*ck) return;
    int m = idx / ck, q = idx - m*ck;
    int Mact = use_nv ? g_nvalid : Mh;
    int k = q << 3;
    int kc = k >> 6, c8 = (k >> 3) & 7;
    int KC = K >> 6;
    size_t doff = ((size_t)(m >> 7)*KC + kc)*TILE_ELEMS + (size_t)(m & 127)*TROW + c8*8;
    uint4 v = make_uint4(0, 0, 0, 0);
    if (m < Mact) {
        int ar = use_amap ? g_amap[m] : m;
        v = *(const uint4*)(A + (size_t)ar*K + k);
    }
    *(uint4*)(outh + doff) = v;
}

// ------------------- wmma compute on one 128x128x64 chunk --------------------
__device__ __forceinline__ void compute_chunk64(const __nv_bfloat16* sa, const __nv_bfloat16* sb,
        int warp_m, int warp_n,
        wmma::fragment<wmma::accumulator, 16, 16, 16, float> (&acc)[4][2]) {
#pragma unroll
    for (int kk = 0; kk < 64; kk += 16) {
        wmma::fragment<wmma::matrix_a, 16, 16, 16, __nv_bfloat16, wmma::row_major> af[4];
#pragma unroll
        for (int am = 0; am < 4; am++)
            wmma::load_matrix_sync(af[am], sa + (warp_m*64 + am*16)*TROW + kk, TROW);
#pragma unroll
        for (int an = 0; an < 2; an++) {
            wmma::fragment<wmma::matrix_b, 16, 16, 16, __nv_bfloat16, wmma::col_major> bf;
            wmma::load_matrix_sync(bf, sb + (warp_n*32 + an*16)*TROW + kk, TROW);
#pragma unroll
            for (int am = 0; am < 4; am++)
                wmma::mma_sync(acc[am][an], af[am], bf, acc[am][an]);
        }
    }
}

// ------------------- mainloop (bulk-copy double buffer) ----------------------
__device__ __forceinline__ void gemm_mainloop(const __nv_bfloat16* Abase,
        const __nv_bfloat16* Bbase, unsigned char* dynsm, int nk, int tid,
        int warp_m, int warp_n,
        wmma::fragment<wmma::accumulator, 16, 16, 16, float> (&acc)[4][2]) {
    __nv_bfloat16* sA0 = (__nv_bfloat16*)(dynsm);
    __nv_bfloat16* sB0 = (__nv_bfloat16*)(dynsm + TILE_BYTES);
    __nv_bfloat16* sA1 = (__nv_bfloat16*)(dynsm + 2*TILE_BYTES);
    __nv_bfloat16* sB1 = (__nv_bfloat16*)(dynsm + 3*TILE_BYTES);
    uint32_t mbar0 = sptr(dynsm + 4*TILE_BYTES);
    uint32_t mbar1 = mbar0 + 8;
    if (tid == 0) {
        MBARRIER_INIT(mbar0, 1);
        MBARRIER_INIT(mbar1, 1);
    }
    __syncthreads();
    if (tid == 0) {
        FENCE_PROXY_ASYNC();
        MBARRIER_EXPECT_TX(mbar0, 2*TILE_BYTES);
        BULK_LOAD(sptr(sA0), Abase, TILE_BYTES, mbar0);
        BULK_LOAD(sptr(sB0), Bbase, TILE_BYTES, mbar0);
        MBARRIER_EXPECT_TX(mbar1, 2*TILE_BYTES);
        BULK_LOAD(sptr(sA1), Abase + TILE_ELEMS, TILE_BYTES, mbar1);
        BULK_LOAD(sptr(sB1), Bbase + TILE_ELEMS, TILE_BYTES, mbar1);
    }
    for (int i = 0; i < nk; i++) {
        int s = i & 1;
        int ph = (i >> 1) & 1;
        MBARRIER_WAIT_PARITY(s ? mbar1 : mbar0, ph);
        compute_chunk64(s ? sA1 : sA0, s ? sB1 : sB0, warp_m, warp_n, acc);
        __syncthreads();
        if (tid == 0 && i + 2 < nk) {
            FENCE_PROXY_ASYNC();
            uint32_t mb = s ? mbar1 : mbar0;
            MBARRIER_EXPECT_TX(mb, 2*TILE_BYTES);
            BULK_LOAD(sptr(s ? sA1 : sA0), Abase + (size_t)(i+2)*TILE_ELEMS, TILE_BYTES, mb);
            BULK_LOAD(sptr(s ? sB1 : sB0), Bbase + (size_t)(i+2)*TILE_ELEMS, TILE_BYTES, mb);
        }
    }
}

// ------------------- packed GEMM: C = A @ W^T + bias -------------------------
__global__ void __launch_bounds__(256) gemm_pk(const __nv_bfloat16* __restrict__ Ap,
        const __nv_bfloat16* __restrict__ Wp, const float* __restrict__ bias,
        float* C, __nv_bfloat16* Cb, int Mh, int N, int K, int use_nv, int relu) {
    extern __shared__ __align__(16) unsigned char dynsm[];
    int Mact = use_nv ? g_nvalid : Mh;
    int by = blockIdx.y, bx = blockIdx.x;
    if (by*128 >= Mact) return;
    int tid = threadIdx.x, lane = tid & 31, wid = tid >> 5;
    int warp_m = wid & 1, warp_n = wid >> 1;
    int KC = K >> 6;

    wmma::fragment<wmma::accumulator, 16, 16, 16, float> acc[4][2];
    for (int i = 0; i < 4; i++)
        for (int j = 0; j < 2; j++)
            wmma::fill_fragment(acc[i][j], 0.0f);

    gemm_mainloop(Ap + (size_t)by*KC*TILE_ELEMS, Wp + (size_t)bx*KC*TILE_ELEMS,
                  dynsm, KC, tid, warp_m, warp_n, acc);

    // epilogue: stage 16x16 tiles through smem (stage buffers free now)
    float* stage = ((float*)dynsm) + wid*256;
    int r = lane >> 1, halfc = (lane & 1)*8;
    for (int am = 0; am < 4; am++) {
        for (int an = 0; an < 2; an++) {
            wmma::store_matrix_sync(stage, acc[am][an], 16, wmma::mem_row_major);
            __syncwarp();
            int grow = by*128 + warp_m*64 + am*16 + r;
            int gcol = bx*128 + warp_n*32 + an*16 + halfc;
            if (grow < Mact) {
                float v[8];
                for (int j = 0; j < 8; j++) {
                    v[j] = stage[r*16 + halfc + j] + bias[gcol + j];
                    if (relu) v[j] = fmaxf(v[j], 0.f);
                }
                if (C) {
                    float4* p = (float4*)(C + (size_t)grow*N + gcol);
                    p[0] = make_float4(v[0], v[1], v[2], v[3]);
                    p[1] = make_float4(v[4], v[5], v[6], v[7]);
                }
                if (Cb) {
                    __nv_bfloat162* p = (__nv_bfloat162*)(Cb + (size_t)grow*N + gcol);
                    p[0] = __float22bfloat162_rn(make_float2(v[0], v[1]));
                    p[1] = __float22bfloat162_rn(make_float2(v[2], v[3]));
                    p[2] = __float22bfloat162_rn(make_float2(v[4], v[5]));
                    p[3] = __float22bfloat162_rn(make_float2(v[6], v[7]));
                }
            }
            __syncwarp();
        }
    }
}

// ------------------- packed decode GEMM + fused online-softmax ---------------
__global__ void __launch_bounds__(256) decode_pk(const __nv_bfloat16* __restrict__ Ap,
        const __nv_bfloat16* __restrict__ Wp, const float* __restrict__ bias) {
    extern __shared__ __align__(16) unsigned char dynsm[];
    __shared__ float bias_s[128];
    __shared__ float2 red[128][4];
    int Mact = g_nvalid;
    int by = blockIdx.y, bx = blockIdx.x;
    if (by*128 >= Mact) return;
    int tid = threadIdx.x, lane = tid & 31, wid = tid >> 5;
    int warp_m = wid & 1, warp_n = wid >> 1;
    if (tid < 128) bias_s[tid] = bias[bx*128 + tid];
    const int KC = DD/64;

    wmma::fragment<wmma::accumulator, 16, 16, 16, float> acc[4][2];
    for (int i = 0; i < 4; i++)
        for (int j = 0; j < 2; j++)
            wmma::fill_fragment(acc[i][j], 0.0f);

    gemm_mainloop(Ap + (size_t)by*KC*TILE_ELEMS, Wp + (size_t)bx*KC*TILE_ELEMS,
                  dynsm, KC, tid, warp_m, warp_n, acc);

    float* stage = ((float*)dynsm) + wid*256;
    int r = lane >> 1, halfc = (lane & 1)*8;
    float rm[4], rs[4];
    for (int am = 0; am < 4; am++) { rm[am] = -1e30f; rs[am] = 0.f; }
    for (int am = 0; am < 4; am++) {
        for (int an = 0; an < 2; an++) {
            wmma::store_matrix_sync(stage, acc[am][an], 16, wmma::mem_row_major);
            __syncwarp();
            int coll = warp_n*32 + an*16 + halfc;
            float vv[8];
            float mx = -1e30f;
            for (int j = 0; j < 8; j++) {
                vv[j] = stage[r*16 + halfc + j] + bias_s[coll + j];
                mx = fmaxf(mx, vv[j]);
            }
            float mxo = __shfl_xor_sync(0xffffffffu, mx, 1);
            float mxa = fmaxf(mx, mxo);
            float se = 0.f;
            for (int j = 0; j < 8; j++) se += expf(vv[j] - mxa);
            se += __shfl_xor_sync(0xffffffffu, se, 1);
            if (mxa > rm[am]) { rs[am] = rs[am]*expf(rm[am] - mxa) + se; rm[am] = mxa; }
            else              { rs[am] += se*expf(mxa - rm[am]); }
            __syncwarp();
        }
    }
    for (int am = 0; am < 4; am++) {
        int rl = warp_m*64 + am*16 + r;
        if ((lane & 1) == 0) red[rl][warp_n] = make_float2(rm[am], rs[am]);
    }
    __syncthreads();
    if (tid < 128) {
        int grow = by*128 + tid;
        if (grow < Mact) {
            float m = -1e30f, s = 0.f;
            for (int w = 0; w < 4; w++) {
                float2 p = red[tid][w];
                if (p.x > m) { s = s*expf(m - p.x) + p.y; m = p.x; }
                else         { s += p.y*expf(p.x - m); }
            }
            g_smpart[(size_t)grow*NCH2 + bx] = make_float2(m, s);
        }
    }
}

// ------------------- pools: left/right/glob partial sums ---------------------
__global__ void pool_partial(const int* __restrict__ tok, const int* __restrict__ ws,
                             const int* __restrict__ we, const float* __restrict__ emb) {
    int b = blockIdx.x, c = blockIdx.y, d = threadIdx.x;
    int s0 = ws[b], e0 = we[b];
    float gl = 0.f, lf = 0.f, rt = 0.f;
    int l0 = c * (LL/8);
#pragma unroll 4
    for (int i = 0; i < LL/8; i++) {
        int l = l0 + i;
        int t = tok[b*LL + l];
        float v = emb[(size_t)t*DD + d];
        gl += v;
        if (l < s0)  lf += v;
        if (l >= e0) rt += v;
    }
    float* p = g_poolpart + ((size_t)(b*8 + c)*3)*DD;
    p[d] = lf; p[DD + d] = rt; p[2*DD + d] = gl;
}

__global__ void pool_reduce(const int* __restrict__ mot, const int* __restrict__ mlen,
                            const int* __restrict__ ws, const int* __restrict__ we,
                            const float* __restrict__ emb) {
    int b = blockIdx.x, d = threadIdx.x;
    float lf = 0.f, rt = 0.f, gl = 0.f;
    for (int c = 0; c < 8; c++) {
        const float* p = g_poolpart + ((size_t)(b*8 + c)*3)*DD;
        lf += p[d]; rt += p[DD + d]; gl += p[2*DD + d];
    }
    int ml = mlen[b];
    float mo = 0.f;
    for (int i = 0; i < MMOT; i++)
        if (i < ml) mo += emb[(size_t)mot[b*MMOT + i]*DD + d];
    mo /= (float)(ml > 1 ? ml : 1);
    float lden = (float)(ws[b] > 1 ? ws[b] : 1);
    int rc = LL - we[b];
    float rden = (float)(rc > 1 ? rc : 1);
    float* o = g_condin + (size_t)b*4*DD;
    o[d]        = mo;
    o[DD + d]   = lf / lden;
    o[2*DD + d] = rt / rden;
    o[3*DD + d] = gl / (float)LL;
}

// ------------------- time embedding input (sin/cos) --------------------------
__global__ void tin_build(const float* __restrict__ t) {
    int b = blockIdx.x, d = threadIdx.x;
    int k = d % (DD/2);
    float f = expf(-logf(10000.f) * (float)k / (float)(DD/2 - 1));
    float a = t[b] * f;
    g_tin[b*DD + d] = (d < DD/2) ? sinf(a) : cosf(a);
}

__global__ void copy_cond() {
    int b = blockIdx.x, d = threadIdx.x;
    float v = g_condout[b*DD + d];
    g_x[(size_t)b*SS*DD + d] = v;
    g_xb[(size_t)b*SS*DD + d] = __float2bfloat16(v);
}

// ------------------- build x_t, x1, x ----------------------------------------
__global__ void build_x(const int* __restrict__ tok, const int* __restrict__ ws,
                        const int* __restrict__ we, const float* __restrict__ t,
                        const float* __restrict__ x0, const float* __restrict__ emb) {
    int idx = blockIdx.x*blockDim.x + threadIdx.x;
    if (idx >= BB*WIN*DD) return;
    int d = idx % DD; int r = idx / DD; int j = r % WIN; int b = r / WIN;
    int s0 = ws[b];
    int act = we[b] - s0;
    float x1v = 0.f;
    if (j < act) {
        int tk = tok[b*LL + s0 + j];
        x1v = emb[(size_t)tk*DD + d];
    }
    float tv = t[b];
    float xt = (1.f - tv)*x0[idx] + tv*x1v;
    g_x1[idx] = x1v;
    g_xt[idx] = xt;
    float xv = xt + g_temb[b*DD + d];
    g_x[((size_t)b*SS + 1 + j)*DD + d] = xv;
    g_xb[((size_t)b*SS + 1 + j)*DD + d] = __float2bfloat16(xv);
}

// ------------------- valid-row compaction ------------------------------------
__global__ void compact_kernel(const int* __restrict__ tok, const int* __restrict__ ws,
                               const int* __restrict__ we) {
    __shared__ int off[BB+1];
    if (threadIdx.x == 0) {
        off[0] = 0;
        for (int b = 0; b < BB; b++) {
            int a = we[b] - ws[b];
            if (a < 0) a = 0;
            if (a > WIN) a = WIN;
            off[b+1] = off[b] + a;
        }
        g_nvalid = off[BB];
    }
    __syncthreads();
    for (int idx = threadIdx.x; idx < BB*WIN; idx += blockDim.x) {
        int b = idx / WIN, j = idx % WIN;
        int a = off[b+1] - off[b];
        if (j < a) {
            int r = off[b] + j;
            g_comporig[r]  = idx;
            g_amap[r]      = b*SS + 1 + j;
            g_complabel[r] = tok[b*LL + ws[b] + j];
        }
    }
}

// ------------------- small fp32 SGEMM (tiny M=16 GEMMs only) -----------------
__global__ void gemm_small(const float* __restrict__ A, const float* __restrict__ Wt,
                           const float* __restrict__ bias, float* __restrict__ C,
                           int M, int N, int K) {
    int n0 = blockIdx.x*64;
    int tid = threadIdx.x;
    int col = n0 + (tid & 63);
    for (int row = tid >> 6; row < M; row += 4) {
        if (col < N) {
            const float* a = A + (size_t)row*K;
            const float* w = Wt + (size_t)col*K;
            float s = 0.f;
            for (int k = 0; k < K; k += 4) {
                float4 av = *(const float4*)(a + k);
                float4 wv = *(const float4*)(w + k);
                s += av.x*wv.x + av.y*wv.y + av.z*wv.z + av.w*wv.w;
            }
            C[(size_t)row*N + col] = s + bias[col];
        }
    }
}

// ------------------- attention ----------------------------------------------
__global__ void attn_scores() {
    int bh = blockIdx.x; int b = bh / HH, h = bh % HH;
    __shared__ float ks[SS][HD];
    const float* base = g_qkv + (size_t)b*SS*3*DD;
    for (int i = threadIdx.x; i < SS*HD; i += blockDim.x) {
        int s = i / HD, d = i % HD;
        ks[s][d] = base[(size_t)s*3*DD + DD + h*HD + d];
    }
    __syncthreads();
    int q = threadIdx.x;
    if (q < SS) {
        float qr[HD];
#pragma unroll
        for (int d = 0; d < HD; d++) qr[d] = base[(size_t)q*3*DD + h*HD + d];
        float* srow = g_scores + ((size_t)bh*SS + q)*SS;
        for (int k = 0; k < SS; k++) {
            const float4* k4 = (const float4*)ks[k];
            float a = 0.f;
#pragma unroll
            for (int dq = 0; dq < 16; dq++) {
                float4 kv = k4[dq];
                a += qr[4*dq+0]*kv.x + qr[4*dq+1]*kv.y + qr[4*dq+2]*kv.z + qr[4*dq+3]*kv.w;
            }
            srow[k] = a * 0.125f;
        }
    }
}

__global__ void attn_softmax() {
    int row = blockIdx.x*4 + threadIdx.x/32;
    int lane = threadIdx.x % 32;
    if (row >= BB*HH*SS) return;
    float* p = g_scores + (size_t)row*SS;
    float v[5];
    float mx = -1e30f;
    int cnt = 0;
    for (int i = lane; i < SS; i += 32) { v[cnt] = p[i]; mx = fmaxf(mx, v[cnt]); cnt++; }
#pragma unroll
    for (int off = 16; off; off >>= 1) mx = fmaxf(mx, __shfl_xor_sync(0xffffffffu, mx, off));
    float se = 0.f;
    for (int c = 0; c < cnt; c++) { v[c] = expf(v[c]-mx); se += v[c]; }
#pragma unroll
    for (int off = 16; off; off >>= 1) se += __shfl_xor_sync(0xffffffffu, se, off);
    float inv = 1.f/se;
    cnt = 0;
    for (int i = lane; i < SS; i += 32) { p[i] = v[cnt]*inv; cnt++; }
}

__global__ void attn_ctx() {
    int bh = blockIdx.x; int b = bh / HH, h = bh % HH;
    __shared__ float vs[SS][HD];
    const float* base = g_qkv + (size_t)b*SS*3*DD + 2*DD + h*HD;
    for (int i = threadIdx.x; i < SS*HD; i += blockDim.x) {
        int s = i / HD, d = i % HD;
        vs[s][d] = base[(size_t)s*3*DD + d];
    }
    __syncthreads();
    for (int i = threadIdx.x; i < SS*HD; i += blockDim.x) {
        int q = i / HD, d = i % HD;
        const float* pr = g_scores + ((size_t)bh*SS + q)*SS;
        float a = 0.f;
        for (int k = 0; k < SS; k++) a += pr[k]*vs[k][d];
        g_ctxb[((size_t)b*SS + q)*DD + h*HD + d] = __float2bfloat16(a);
    }
}

// ------------------- residual + layernorm (fp32 + bf16 out) ------------------
__global__ void ln_kernel(float* __restrict__ x, __nv_bfloat16* __restrict__ xb,
                          const float* __restrict__ add,
                          const float* __restrict__ gam, const float* __restrict__ bet) {
    __shared__ float red[256];
    __shared__ float stats[2];
    int tid = threadIdx.x;
    float* xr = x + (size_t)blockIdx.x*DD;
    __nv_bfloat16* xbr = xb + (size_t)blockIdx.x*DD;
    const float* ar = add + (size_t)blockIdx.x*DD;
    float v0 = xr[tid]       + ar[tid];
    float v1 = xr[tid + 256] + ar[tid + 256];
    red[tid] = v0 + v1;
    __syncthreads();
    for (int st = 128; st; st >>= 1) { if (tid < st) red[tid] += red[tid+st]; __syncthreads(); }
    if (tid == 0) stats[0] = red[0] * (1.f/DD);
    __syncthreads();
    float mean = stats[0];
    float d0 = v0 - mean, d1 = v1 - mean;
    red[tid] = d0*d0 + d1*d1;
    __syncthreads();
    for (int st = 128; st; st >>= 1) { if (tid < st) red[tid] += red[tid+st]; __syncthreads(); }
    if (tid == 0) stats[1] = rsqrtf(red[0]*(1.f/DD) + EPSV);
    __syncthreads();
    float inv = stats[1];
    float o0 = d0*inv*gam[tid]       + bet[tid];
    float o1 = d1*inv*gam[tid + 256] + bet[tid + 256];
    xr[tid]        = o0;
    xr[tid + 256]  = o1;
    xbr[tid]       = __float2bfloat16(o0);
    xbr[tid + 256] = __float2bfloat16(o1);
}

// ------------------- velocity loss partials + pred_x1 (bf16) -----------------
__global__ void velpred_kernel(const float* __restrict__ t, const float* __restrict__ x0) {
    int nv = g_nvalid;
    int total = nv * DD;
    float lsum = 0.f;
    for (int e = blockIdx.x*blockDim.x + threadIdx.x; e < total; e += gridDim.x*blockDim.x) {
        int r = e / DD, d = e % DD;
        int orig = g_comporig[r];
        int b = orig / WIN;
        float pv = g_predv[e];
        float diff = pv - (g_x1[(size_t)orig*DD + d] - x0[(size_t)orig*DD + d]);
        lsum += diff*diff;
        g_px1b[e] = __float2bfloat16(g_xt[(size_t)orig*DD + d] + (1.f - t[b])*pv);
    }
    __shared__ float sm[256];
    sm[threadIdx.x] = lsum;
    __syncthreads();
    for (int st = 128; st; st >>= 1) { if (threadIdx.x < st) sm[threadIdx.x] += sm[threadIdx.x+st]; __syncthreads(); }
    if (threadIdx.x == 0) g_velred[blockIdx.x] = sm[0];
}

// ------------------- picked logit (bf16, packed decode weights) --------------
__global__ void picked_kernel(const float* __restrict__ decB) {
    int r = blockIdx.x*8 + threadIdx.x/32;
    int lane = threadIdx.x % 32;
    if (r >= g_nvalid) return;
    int lab = g_complabel[r];
    const __nv_bfloat16* a = g_hab + (size_t)r*DD;
    size_t base = (size_t)(lab >> 7)*8*TILE_ELEMS + (size_t)(lab & 127)*TROW;
    float s = 0.f;
    for (int i = lane; i < DD; i += 32) {
        __nv_bfloat16 w = g_wdecP[base + (size_t)(i >> 6)*TILE_ELEMS + (i & 63)];
        s += __bfloat162float(a[i]) * __bfloat162float(w);
    }
#pragma unroll
    for (int off = 16; off; off >>= 1) s += __shfl_xor_sync(0xffffffffu, s, off);
    if (lane == 0) g_picked[r] = s + decB[lab];
}

// ------------------- logsumexp combine ---------------------------------------
__global__ void combine_kernel() {
    int r = blockIdx.x;
    int nv = g_nvalid;
    float m = -1e30f, s = 0.f;
    if (r < nv) {
        for (int i = threadIdx.x; i < NCH2; i += blockDim.x) {
            float2 p = g_smpart[(size_t)r*NCH2 + i];
            if (p.x > m) { s = s*expf(m - p.x) + p.y; m = p.x; }
            else         { s += p.y*expf(p.x - m); }
        }
    }
    __shared__ float sm[128], ss[128];
    sm[threadIdx.x] = m; ss[threadIdx.x] = s;
    __syncthreads();
    for (int st = 64; st; st >>= 1) {
        if (threadIdx.x < st) {
            float m1 = sm[threadIdx.x], s1 = ss[threadIdx.x];
            float m2 = sm[threadIdx.x+st], s2 = ss[threadIdx.x+st];
            float M = fmaxf(m1, m2);
            sm[threadIdx.x] = M;
            ss[threadIdx.x] = s1*expf(m1 - M) + s2*expf(m2 - M);
        }
        __syncthreads();
    }
    if (threadIdx.x == 0) {
        if (r < nv) {
            float lse = sm[0] + logf(ss[0]);
            g_rowrecon[r] = lse - g_picked[r];
        } else {
            g_rowrecon[r] = 0.f;
        }
    }
}

// ------------------- final loss ----------------------------------------------
__global__ void final_kernel(float* __restrict__ out) {
    __shared__ float sm[256];
    int tid = threadIdx.x;
    int nv = g_nvalid;
    sm[tid] = g_velred[tid];
    __syncthreads();
    for (int st = 128; st; st >>= 1) { if (tid < st) sm[tid] += sm[tid+st]; __syncthreads(); }
    float vel = sm[0] / ((float)nv * (float)DD);
    __syncthreads();
    float r = 0.f;
    for (int i = tid; i < nv; i += 256) r += g_rowrecon[i];
    sm[tid] = r;
    __syncthreads();
    for (int st = 128; st; st >>= 1) { if (tid < st) sm[tid] += sm[tid+st]; __syncthreads(); }
    if (tid == 0) out[0] = vel + 0.1f * (sm[0] / (float)nv);
}

// ------------------- host side -----------------------------------------------
static void wpack(const float* src, __nv_bfloat16* dst, int N, int K) {
    int chunks = N*(K >> 3);
    wpack_kernel<<<(chunks + 255)/256, 256>>>((const float4*)src, (uint4*)dst, N, K);
}
static void apack(const __nv_bfloat16* src, __nv_bfloat16* dst, int Mpad, int K,
                  int Mh, int use_nv, int use_amap) {
    int chunks = Mpad*(K >> 3);
    apack_kernel<<<(chunks + 255)/256, 256>>>(src, dst, Mpad, K, Mh, use_nv, use_amap);
}

extern "C" void kernel_launch(void* const* d_in, const int* in_sizes, int n_in,
                              void* d_out, int out_size) {
    (void)in_sizes; (void)n_in; (void)out_size;
    const int*   tok       = (const int*)  d_in[0];
    const int*   motif_ids = (const int*)  d_in[1];
    const int*   motif_len = (const int*)  d_in[2];
    const int*   ws        = (const int*)  d_in[3];
    const int*   we        = (const int*)  d_in[4];
    const float* t         = (const float*)d_in[5];
    const float* x0        = (const float*)d_in[6];
    const float* emb       = (const float*)d_in[7];
    const float* decW      = (const float*)d_in[8];
    const float* decB      = (const float*)d_in[9];
    const float* adW       = (const float*)d_in[10];
    const float* adB       = (const float*)d_in[11];
    const float* tpW       = (const float*)d_in[12];
    const float* tpB       = (const float*)d_in[13];
    const float* cpW       = (const float*)d_in[14];
    const float* cpB       = (const float*)d_in[15];
    const float* qkvW      = (const float*)d_in[16];
    const float* qkvB      = (const float*)d_in[17];
    const float* aoW       = (const float*)d_in[18];
    const float* aoB       = (const float*)d_in[19];
    const float* f1W       = (const float*)d_in[20];
    const float* f1B       = (const float*)d_in[21];
    const float* f2W       = (const float*)d_in[22];
    const float* f2B       = (const float*)d_in[23];
    const float* ln1g      = (const float*)d_in[24];
    const float* ln1b      = (const float*)d_in[25];
    const float* ln2g      = (const float*)d_in[26];
    const float* ln2b      = (const float*)d_in[27];
    const float* outW      = (const float*)d_in[28];
    const float* outB      = (const float*)d_in[29];

    static bool inited = false;
    static float *p_tin, *p_temb, *p_condin, *p_condout, *p_qkv, *p_tmp, *p_predv, *p_x;
    static __nv_bfloat16 *p_xb, *p_ctxb, *p_ffb, *p_px1b, *p_hab;
    static __nv_bfloat16 *p_apack, *p_wqkvP, *p_waoP, *p_wf1P, *p_wf2P, *p_woutP, *p_wadP, *p_wdecP;
    if (!inited) {
        cudaGetSymbolAddress((void**)&p_tin,     g_tin);
        cudaGetSymbolAddress((void**)&p_temb,    g_temb);
        cudaGetSymbolAddress((void**)&p_condin,  g_condin);
        cudaGetSymbolAddress((void**)&p_condout, g_condout);
        cudaGetSymbolAddress((void**)&p_x,       g_x);
        cudaGetSymbolAddress((void**)&p_qkv,     g_qkv);
        cudaGetSymbolAddress((void**)&p_tmp,     g_tmp);
        cudaGetSymbolAddress((void**)&p_predv,   g_predv);
        cudaGetSymbolAddress((void**)&p_xb,      g_xb);
        cudaGetSymbolAddress((void**)&p_ctxb,    g_ctxb);
        cudaGetSymbolAddress((void**)&p_ffb,     g_ffb);
        cudaGetSymbolAddress((void**)&p_px1b,    g_px1b);
        cudaGetSymbolAddress((void**)&p_hab,     g_hab);
        cudaGetSymbolAddress((void**)&p_apack,   g_apack);
        cudaGetSymbolAddress((void**)&p_wqkvP,   g_wqkvP);
        cudaGetSymbolAddress((void**)&p_waoP,    g_waoP);
        cudaGetSymbolAddress((void**)&p_wf1P,    g_wf1P);
        cudaGetSymbolAddress((void**)&p_wf2P,    g_wf2P);
        cudaGetSymbolAddress((void**)&p_woutP,   g_woutP);
        cudaGetSymbolAddress((void**)&p_wadP,    g_wadP);
        cudaGetSymbolAddress((void**)&p_wdecP,   g_wdecP);
        inited = true;
    }
    cudaFuncSetAttribute(gemm_pk, cudaFuncAttributeMaxDynamicSharedMemorySize, DYNSM);
    cudaFuncSetAttribute(decode_pk, cudaFuncAttributeMaxDynamicSharedMemorySize, DYNSM);

    // weight packing (fp32 -> bf16 tiled)
    for (int i = 0; i < NLAYER; i++) {
        wpack(qkvW + (size_t)i*3*DD*DD, p_wqkvP + (size_t)i*12*8*TILE_ELEMS, 3*DD, DD);
        wpack(aoW  + (size_t)i*DD*DD,   p_waoP  + (size_t)i*4*8*TILE_ELEMS,  DD, DD);
        wpack(f1W  + (size_t)i*FF*DD,   p_wf1P  + (size_t)i*16*8*TILE_ELEMS, FF, DD);
        wpack(f2W  + (size_t)i*DD*FF,   p_wf2P  + (size_t)i*4*32*TILE_ELEMS, DD, FF);
    }
    wpack(outW, p_woutP, DD, DD);
    wpack(adW,  p_wadP,  DD, DD);
    wpack(decW, p_wdecP, VV, DD);

    // pools + cond input
    pool_partial<<<dim3(BB, 8), 512>>>(tok, ws, we, emb);
    pool_reduce<<<BB, 512>>>(motif_ids, motif_len, ws, we, emb);
    tin_build<<<BB, 512>>>(t);
    gemm_small<<<DD/64, 256>>>(p_tin, tpW, tpB, p_temb, BB, DD, DD);
    gemm_small<<<DD/64, 256>>>(p_condin, cpW, cpB, p_condout, BB, DD, 4*DD);
    copy_cond<<<BB, 512>>>();
    build_x<<<(BB*WIN*DD + 255)/256, 256>>>(tok, ws, we, t, x0, emb);
    compact_kernel<<<1, 256>>>(tok, ws, we);

    // transformer layers
    for (int i = 0; i < NLAYER; i++) {
        apack(p_xb, p_apack, RTP, DD, RT, 0, 0);
        gemm_pk<<<dim3(12, RTP/128), 256, DYNSM>>>(
            p_apack, p_wqkvP + (size_t)i*12*8*TILE_ELEMS, qkvB + (size_t)i*3*DD,
            p_qkv, (__nv_bfloat16*)0, RT, 3*DD, DD, 0, 0);
        attn_scores<<<BB*HH, 256>>>();
        attn_softmax<<<(BB*HH*SS + 3)/4, 128>>>();
        attn_ctx<<<BB*HH, 256>>>();
        apack(p_ctxb, p_apack, RTP, DD, RT, 0, 0);
        gemm_pk<<<dim3(4, RTP/128), 256, DYNSM>>>(
            p_apack, p_waoP + (size_t)i*4*8*TILE_ELEMS, aoB + (size_t)i*DD,
            p_tmp, (__nv_bfloat16*)0, RT, DD, DD, 0, 0);
        ln_kernel<<<RT, 256>>>(p_x, p_xb, p_tmp, ln1g + (size_t)i*DD, ln1b + (size_t)i*DD);
        apack(p_xb, p_apack, RTP, DD, RT, 0, 0);
        gemm_pk<<<dim3(16, RTP/128), 256, DYNSM>>>(
            p_apack, p_wf1P + (size_t)i*16*8*TILE_ELEMS, f1B + (size_t)i*FF,
            (float*)0, p_ffb, RT, FF, DD, 0, 1);
        apack(p_ffb, p_apack, RTP, FF, RT, 0, 0);
        gemm_pk<<<dim3(4, RTP/128), 256, DYNSM>>>(
            p_apack, p_wf2P + (size_t)i*4*32*TILE_ELEMS, f2B + (size_t)i*DD,
            p_tmp, (__nv_bfloat16*)0, RT, DD, FF, 0, 0);
        ln_kernel<<<RT, 256>>>(p_x, p_xb, p_tmp, ln2g + (size_t)i*DD, ln2b + (size_t)i*DD);
    }

    // pred_v over valid rows (amap gather folded into apack)
    apack(p_xb, p_apack, WR, DD, WR, 1, 1);
    gemm_pk<<<dim3(4, WR/128), 256, DYNSM>>>(
        p_apack, p_woutP, outB, p_predv, (__nv_bfloat16*)0, WR, DD, DD, 1, 0);
    velpred_kernel<<<256, 256>>>(t, x0);
    // adapter over compact valid rows
    apack(p_px1b, p_apack, WR, DD, WR, 1, 0);
    gemm_pk<<<dim3(4, WR/128), 256, DYNSM>>>(
        p_apack, p_wadP, adB, (float*)0, p_hab, WR, DD, DD, 1, 0);
    // decode GEMM with fused online softmax partials
    apack(p_hab, p_apack, WR, DD, WR, 1, 0);
    decode_pk<<<dim3(NCH2, WR/128), 256, DYNSM>>>(p_apack, p_wdecP, decB);
    picked_kernel<<<WR/8, 256>>>(decB);
    combine_kernel<<<WR, 128>>>();
    final_kernel<<<1, 256>>>((float*)d_out);
}

// round 6
// speedup vs baseline: 2.4464x; 1.3253x over previous
#include <cuda_runtime.h>
#include <cuda_bf16.h>
#include <mma.h>
#include <math.h>
#include <stdint.h>

using namespace nvcuda;

#define BB 16
#define LL 2048
#define WIN 128
#define DD 512
#define HH 8
#define HD 64
#define FF 2048
#define NLAYER 3
#define VV 32000
#define MMOT 32
#define SS 129            // WIN + 1 (cond row)
#define RT (BB*SS)        // 2064 transformer rows
#define RTP 2176          // RT padded to 128
#define WR (BB*WIN)       // 2048 window rows
#define EPSV 1e-5f
#define NCH2 (VV/128)     // 250 softmax partial chunks

#define TROW 72                    // padded tile row stride (elems)
#define TILE_ELEMS (128*TROW)      // 9216
#define STG (64*TROW*2 + 128*TROW*2)   // 27648 bytes per stage (A64 + B128)
#define DYNSM (4*STG + 32)

// ---------------- mbarrier / bulk-copy PTX macros ----------------------------
#define MBARRIER_INIT(mbar_smem_addr, count) \
    asm volatile("mbarrier.init.shared.b64 [%0], %1;" \
        :: "r"((uint32_t)(mbar_smem_addr)), "r"((uint32_t)(count)) : "memory")

#define MBARRIER_EXPECT_TX(mbar_smem_addr, tx_bytes) \
    asm volatile("mbarrier.arrive.expect_tx.shared.b64 _, [%0], %1;" \
        :: "r"((uint32_t)(mbar_smem_addr)), "r"((uint32_t)(tx_bytes)) : "memory")

#define MBARRIER_WAIT_PARITY(mbar_smem_addr, phase_parity) do { \
    uint32_t _mbar = (uint32_t)(mbar_smem_addr); \
    uint32_t _parity = (uint32_t)(phase_parity); \
    uint32_t _done; \
    asm volatile( \
        "{\n\t" \
        ".reg .pred p;\n\t" \
        "mbarrier.try_wait.parity.acquire.cta.shared::cta.b64 p, [%1], %2;\n\t" \
        "selp.b32 %0, 1, 0, p;\n\t" \
        "}" \
        : "=r"(_done) : "r"(_mbar), "r"(_parity) : "memory"); \
    if (!_done) { \
        asm volatile( \
            "{\n\t" \
            ".reg .pred P1;\n\t" \
            "WAIT_LOOP_%=:\n\t" \
            "mbarrier.try_wait.parity.acquire.cta.shared::cta.b64 P1, [%0], %1, 0x989680;\n\t" \
            "@P1 bra.uni WAIT_DONE_%=;\n\t" \
            "bra.uni WAIT_LOOP_%=;\n\t" \
            "WAIT_DONE_%=:\n\t" \
            "}" \
            :: "r"(_mbar), "r"(_parity) : "memory"); \
    } \
} while(0)

#define BULK_LOAD(dst_smem, src_gmem, nbytes, mbar_smem) \
    asm volatile("cp.async.bulk.shared::cluster.global.mbarrier::complete_tx::bytes [%0], [%1], %2, [%3];" \
        :: "r"((uint32_t)(dst_smem)), "l"(src_gmem), "r"((uint32_t)(nbytes)), \
           "r"((uint32_t)(mbar_smem)) : "memory")

#define FENCE_PROXY_ASYNC() \
    asm volatile("fence.proxy.async.shared::cta;" ::: "memory")

__device__ __forceinline__ uint32_t sptr(const void* p) {
    return (uint32_t)__cvta_generic_to_shared(p);
}

// packed layout offset: tiles [m/128][k/64] of [128][TROW]
__device__ __forceinline__ size_t pk(int m, int k, int KC) {
    return ((size_t)(m >> 7)*KC + (k >> 6))*TILE_ELEMS + (size_t)(m & 127)*TROW + (k & 63);
}

// ------------------- device scratch (static, no allocation) -------------------
__device__ float g_condin[BB*4*DD];
__device__ float g_poolpart[BB*8*3*DD];
__device__ float g_tin[BB*DD];
__device__ float g_temb[BB*DD];
__device__ float g_condout[BB*DD];
__device__ float g_x[RT*DD];
__device__ float g_xt[WR*DD];
__device__ float g_x1[WR*DD];
__device__ float g_qkv[RT*3*DD];
__device__ float g_scores[BB*HH*SS*SS];
__device__ float g_tmp[RT*DD];
__device__ float g_predv[RTP*DD];
__device__ float2 g_smpart[(size_t)WR*NCH2];
__device__ float g_picked[WR];
__device__ float g_rowrecon[WR];
__device__ float g_velred[256];
__device__ int g_comporig[WR];
__device__ int g_complabel[WR];
__device__ int g_amap[WR];
__device__ int g_nvalid;

// packed bf16 activations
__device__ __align__(16) __nv_bfloat16 g_xpk[17*8*TILE_ELEMS];
__device__ __align__(16) __nv_bfloat16 g_ctxpk[17*8*TILE_ELEMS];
__device__ __align__(16) __nv_bfloat16 g_ffpk[17*32*TILE_ELEMS];
__device__ __align__(16) __nv_bfloat16 g_px1pk[16*8*TILE_ELEMS];
__device__ __align__(16) __nv_bfloat16 g_habpk[16*8*TILE_ELEMS];
// packed bf16 weights
__device__ __align__(16) __nv_bfloat16 g_wqkvP[NLAYER*12*8*TILE_ELEMS];
__device__ __align__(16) __nv_bfloat16 g_waoP[NLAYER*4*8*TILE_ELEMS];
__device__ __align__(16) __nv_bfloat16 g_wf1P[NLAYER*16*8*TILE_ELEMS];
__device__ __align__(16) __nv_bfloat16 g_wf2P[NLAYER*4*32*TILE_ELEMS];
__device__ __align__(16) __nv_bfloat16 g_woutP[4*8*TILE_ELEMS];
__device__ __align__(16) __nv_bfloat16 g_wadP[4*8*TILE_ELEMS];
__device__ __align__(16) __nv_bfloat16 g_wdecP[250*8*TILE_ELEMS];

// ------------------- fused weight packing ------------------------------------
__device__ __forceinline__ void packone(const float4* __restrict__ W,
                                        __nv_bfloat16* __restrict__ dst, int idx, int K) {
    int ck = K >> 3;
    int n = idx / ck, q = idx - n*ck;
    int k = q << 3;
    int kc = k >> 6, c8 = (k >> 3) & 7;
    int KC = K >> 6;
    size_t doff = ((size_t)(n >> 7)*KC + kc)*TILE_ELEMS + (size_t)(n & 127)*TROW + c8*8;
    float4 a = W[(size_t)idx*2], b = W[(size_t)idx*2 + 1];
    __nv_bfloat162 r0 = __float22bfloat162_rn(make_float2(a.x, a.y));
    __nv_bfloat162 r1 = __float22bfloat162_rn(make_float2(a.z, a.w));
    __nv_bfloat162 r2 = __float22bfloat162_rn(make_float2(b.x, b.y));
    __nv_bfloat162 r3 = __float22bfloat162_rn(make_float2(b.z, b.w));
    uint4 v;
    v.x = *(uint32_t*)&r0; v.y = *(uint32_t*)&r1;
    v.z = *(uint32_t*)&r2; v.w = *(uint32_t*)&r3;
    ((uint4*)dst)[doff >> 3] = v;
}

__global__ void wpack_all(const float* qkvW, const float* aoW, const float* f1W,
                          const float* f2W, const float* outW, const float* adW,
                          const float* decW) {
    int idx = blockIdx.x*blockDim.x + threadIdx.x;
    if      (idx <  294912) packone((const float4*)qkvW, g_wqkvP, idx,           512);
    else if (idx <  393216) packone((const float4*)aoW,  g_waoP,  idx - 294912,  512);
    else if (idx <  786432) packone((const float4*)f1W,  g_wf1P,  idx - 393216,  512);
    else if (idx < 1179648) packone((const float4*)f2W,  g_wf2P,  idx - 786432,  2048);
    else if (idx < 1212416) packone((const float4*)outW, g_woutP, idx - 1179648, 512);
    else if (idx < 1245184) packone((const float4*)adW,  g_wadP,  idx - 1212416, 512);
    else if (idx < 3293184) packone((const float4*)decW, g_wdecP, idx - 1245184, 512);
}

// ------------------- pools -----------------------------------------------------
__global__ void pool_partial(const int* __restrict__ tok, const int* __restrict__ ws,
                             const int* __restrict__ we, const float* __restrict__ emb) {
    int b = blockIdx.x, c = blockIdx.y, d = threadIdx.x;
    int s0 = ws[b], e0 = we[b];
    float gl = 0.f, lf = 0.f, rt = 0.f;
    int l0 = c * (LL/8);
#pragma unroll 4
    for (int i = 0; i < LL/8; i++) {
        int l = l0 + i;
        int t = tok[b*LL + l];
        float v = emb[(size_t)t*DD + d];
        gl += v;
        if (l < s0)  lf += v;
        if (l >= e0) rt += v;
    }
    float* p = g_poolpart + ((size_t)(b*8 + c)*3)*DD;
    p[d] = lf; p[DD + d] = rt; p[2*DD + d] = gl;
}

// pool_reduce + motif + time-embedding input fused
__global__ void prep_kernel(const int* __restrict__ mot, const int* __restrict__ mlen,
                            const int* __restrict__ ws, const int* __restrict__ we,
                            const float* __restrict__ emb, const float* __restrict__ t) {
    int b = blockIdx.x, d = threadIdx.x;
    float lf = 0.f, rt = 0.f, gl = 0.f;
    for (int c = 0; c < 8; c++) {
        const float* p = g_poolpart + ((size_t)(b*8 + c)*3)*DD;
        lf += p[d]; rt += p[DD + d]; gl += p[2*DD + d];
    }
    int ml = mlen[b];
    float mo = 0.f;
    for (int i = 0; i < MMOT; i++)
        if (i < ml) mo += emb[(size_t)mot[b*MMOT + i]*DD + d];
    mo /= (float)(ml > 1 ? ml : 1);
    float lden = (float)(ws[b] > 1 ? ws[b] : 1);
    int rc = LL - we[b];
    float rden = (float)(rc > 1 ? rc : 1);
    float* o = g_condin + (size_t)b*4*DD;
    o[d]        = mo;
    o[DD + d]   = lf / lden;
    o[2*DD + d] = rt / rden;
    o[3*DD + d] = gl / (float)LL;
    // time embedding input
    int k = d % (DD/2);
    float f = expf(-logf(10000.f) * (float)k / (float)(DD/2 - 1));
    float a = t[b] * f;
    g_tin[b*DD + d] = (d < DD/2) ? sinf(a) : cosf(a);
}

// ------------------- small fp32 GEMMs (temb + cond), one launch ---------------
__global__ void gemm_small2(const float* __restrict__ tpW, const float* __restrict__ tpB,
                            const float* __restrict__ cpW, const float* __restrict__ cpB) {
    int bx = blockIdx.x;
    int tid = threadIdx.x;
    const float* A; const float* Wt; const float* bias; float* C; int K; int n0;
    if (bx < 8) { A = g_tin;    Wt = tpW; bias = tpB; C = g_temb;    K = 512;  n0 = bx*64; }
    else        { A = g_condin; Wt = cpW; bias = cpB; C = g_condout; K = 2048; n0 = (bx-8)*64; }
    int col = n0 + (tid & 63);
    for (int row = tid >> 6; row < BB; row += 4) {
        const float* a = A + (size_t)row*K;
        const float* w = Wt + (size_t)col*K;
        float s = 0.f;
        for (int k = 0; k < K; k += 4) {
            float4 av = *(const float4*)(a + k);
            float4 wv = *(const float4*)(w + k);
            s += av.x*wv.x + av.y*wv.y + av.z*wv.z + av.w*wv.w;
        }
        C[(size_t)row*DD + col] = s + bias[col];
    }
}

// ------------------- fused build: x_t/x1/x + cond rows + compaction ----------
__global__ void build_all2(const int* __restrict__ tok, const int* __restrict__ ws,
                           const int* __restrict__ we, const float* __restrict__ t,
                           const float* __restrict__ x0, const float* __restrict__ emb) {
    int bid = blockIdx.x;
    int tid = threadIdx.x;
    if (bid < 4096) {
        int idx = bid*256 + tid;
        int d = idx % DD; int r = idx / DD; int j = r % WIN; int b = r / WIN;
        int s0 = ws[b];
        int act = we[b] - s0;
        float x1v = 0.f;
        if (j < act) {
            int tk = tok[b*LL + s0 + j];
            x1v = emb[(size_t)tk*DD + d];
        }
        float tv = t[b];
        float xt = (1.f - tv)*x0[idx] + tv*x1v;
        g_x1[idx] = x1v;
        g_xt[idx] = xt;
        float xv = xt + g_temb[b*DD + d];
        int m = b*SS + 1 + j;
        g_x[(size_t)m*DD + d] = xv;
        g_xpk[pk(m, d, 8)] = __float2bfloat16(xv);
    } else if (bid < 4128) {
        int local = (bid - 4096)*256 + tid;   // < 8192
        int b = local >> 9, d = local & 511;
        float v = g_condout[b*DD + d];
        int m = b*SS;
        g_x[(size_t)m*DD + d] = v;
        g_xpk[pk(m, d, 8)] = __float2bfloat16(v);
    } else {
        __shared__ int off[BB+1];
        if (tid == 0) {
            off[0] = 0;
            for (int b = 0; b < BB; b++) {
                int a = we[b] - ws[b];
                if (a < 0) a = 0;
                if (a > WIN) a = WIN;
                off[b+1] = off[b] + a;
            }
            g_nvalid = off[BB];
        }
        __syncthreads();
        for (int idx = tid; idx < BB*WIN; idx += 256) {
            int b = idx / WIN, j = idx % WIN;
            int a = off[b+1] - off[b];
            if (j < a) {
                int r = off[b] + j;
                g_comporig[r]  = idx;
                g_amap[r]      = b*SS + 1 + j;
                g_complabel[r] = tok[b*LL + ws[b] + j];
            }
        }
    }
}

// ------------------- wmma compute on one 64x128x64 chunk ---------------------
using FragAcc = wmma::fragment<wmma::accumulator, 16, 16, 16, float>;

__device__ __forceinline__ void compute64(const __nv_bfloat16* sa, const __nv_bfloat16* sb,
                                          int warp_m, int warp_n, FragAcc (&acc)[2][2]) {
#pragma unroll
    for (int kk = 0; kk < 64; kk += 16) {
        wmma::fragment<wmma::matrix_a, 16, 16, 16, __nv_bfloat16, wmma::row_major> af[2];
#pragma unroll
        for (int am = 0; am < 2; am++)
            wmma::load_matrix_sync(af[am], sa + (warp_m*32 + am*16)*TROW + kk, TROW);
#pragma unroll
        for (int an = 0; an < 2; an++) {
            wmma::fragment<wmma::matrix_b, 16, 16, 16, __nv_bfloat16, wmma::col_major> bf;
            wmma::load_matrix_sync(bf, sb + (warp_n*32 + an*16)*TROW + kk, TROW);
#pragma unroll
            for (int am = 0; am < 2; am++)
                wmma::mma_sync(acc[am][an], af[am], bf, acc[am][an]);
        }
    }
}

__device__ __forceinline__ void mainloop64(const __nv_bfloat16* Abase,
        const __nv_bfloat16* Bbase, unsigned char* dynsm, int nk, int tid,
        int warp_m, int warp_n, FragAcc (&acc)[2][2]) {
    uint32_t mb = sptr(dynsm + 4*STG);
    if (tid == 0) {
        MBARRIER_INIT(mb,      1);
        MBARRIER_INIT(mb + 8,  1);
        MBARRIER_INIT(mb + 16, 1);
        MBARRIER_INIT(mb + 24, 1);
    }
    __syncthreads();
    if (tid == 0) {
        FENCE_PROXY_ASYNC();
#pragma unroll
        for (int s = 0; s < 3; s++) {
            MBARRIER_EXPECT_TX(mb + 8*s, STG);
            BULK_LOAD(sptr(dynsm + s*STG), Abase + (size_t)s*TILE_ELEMS, 64*TROW*2, mb + 8*s);
            BULK_LOAD(sptr(dynsm + s*STG + 64*TROW*2), Bbase + (size_t)s*TILE_ELEMS, 128*TROW*2, mb + 8*s);
        }
    }
    for (int i = 0; i < nk; i++) {
        int s = i & 3;
        int ph = (i >> 2) & 1;
        MBARRIER_WAIT_PARITY(mb + 8*s, ph);
        compute64((const __nv_bfloat16*)(dynsm + s*STG),
                  (const __nv_bfloat16*)(dynsm + s*STG + 64*TROW*2),
                  warp_m, warp_n, acc);
        __syncthreads();
        if (tid == 0 && i + 3 < nk) {
            FENCE_PROXY_ASYNC();
            int s2 = (i + 3) & 3;
            MBARRIER_EXPECT_TX(mb + 8*s2, STG);
            BULK_LOAD(sptr(dynsm + s2*STG), Abase + (size_t)(i+3)*TILE_ELEMS, 64*TROW*2, mb + 8*s2);
            BULK_LOAD(sptr(dynsm + s2*STG + 64*TROW*2), Bbase + (size_t)(i+3)*TILE_ELEMS, 128*TROW*2, mb + 8*s2);
        }
    }
}

// ------------------- packed GEMM: C = A @ W^T + bias -------------------------
__global__ void __launch_bounds__(256) gemm64(const __nv_bfloat16* __restrict__ Ap,
        const __nv_bfloat16* __restrict__ Wp, const float* __restrict__ bias,
        float* C, __nv_bfloat16* Cpk, int Mh, int N, int KC, int use_nv, int relu) {
    extern __shared__ __align__(16) unsigned char dynsm[];
    int Mact = use_nv ? g_nvalid : Mh;
    int by = blockIdx.y, bx = blockIdx.x;
    if (by*64 >= Mact) return;
    int tid = threadIdx.x, lane = tid & 31, wid = tid >> 5;
    int warp_m = wid & 1, warp_n = wid >> 1;

    FragAcc acc[2][2];
    for (int i = 0; i < 2; i++)
        for (int j = 0; j < 2; j++)
            wmma::fill_fragment(acc[i][j], 0.0f);

    const __nv_bfloat16* Abase = Ap + ((size_t)(by >> 1)*KC)*TILE_ELEMS + (size_t)(by & 1)*64*TROW;
    const __nv_bfloat16* Bbase = Wp + (size_t)bx*KC*TILE_ELEMS;
    mainloop64(Abase, Bbase, dynsm, KC, tid, warp_m, warp_n, acc);

    float* stage = ((float*)dynsm) + wid*256;
    int r = lane >> 1, halfc = (lane & 1)*8;
    int KCo = N >> 6;
    for (int am = 0; am < 2; am++) {
        for (int an = 0; an < 2; an++) {
            wmma::store_matrix_sync(stage, acc[am][an], 16, wmma::mem_row_major);
            __syncwarp();
            int grow = by*64 + warp_m*32 + am*16 + r;
            int gcol = bx*128 + warp_n*32 + an*16 + halfc;
            if (grow < Mact) {
                float v[8];
                for (int j = 0; j < 8; j++) {
                    v[j] = stage[r*16 + halfc + j] + bias[gcol + j];
                    if (relu) v[j] = fmaxf(v[j], 0.f);
                }
                if (C) {
                    float4* p = (float4*)(C + (size_t)grow*N + gcol);
                    p[0] = make_float4(v[0], v[1], v[2], v[3]);
                    p[1] = make_float4(v[4], v[5], v[6], v[7]);
                }
                if (Cpk) {
                    __nv_bfloat162 b0 = __float22bfloat162_rn(make_float2(v[0], v[1]));
                    __nv_bfloat162 b1 = __float22bfloat162_rn(make_float2(v[2], v[3]));
                    __nv_bfloat162 b2 = __float22bfloat162_rn(make_float2(v[4], v[5]));
                    __nv_bfloat162 b3 = __float22bfloat162_rn(make_float2(v[6], v[7]));
                    uint4 u;
                    u.x = *(uint32_t*)&b0; u.y = *(uint32_t*)&b1;
                    u.z = *(uint32_t*)&b2; u.w = *(uint32_t*)&b3;
                    *(uint4*)(Cpk + pk(grow, gcol, KCo)) = u;
                }
            }
            __syncwarp();
        }
    }
}

// ------------------- packed decode GEMM + fused online-softmax ---------------
__global__ void __launch_bounds__(256) decode64(const __nv_bfloat16* __restrict__ Ap,
        const __nv_bfloat16* __restrict__ Wp, const float* __restrict__ bias) {
    extern __shared__ __align__(16) unsigned char dynsm[];
    __shared__ float bias_s[128];
    __shared__ float2 red[64][4];
    int Mact = g_nvalid;
    int by = blockIdx.y, bx = blockIdx.x;
    if (by*64 >= Mact) return;
    int tid = threadIdx.x, lane = tid & 31, wid = tid >> 5;
    int warp_m = wid & 1, warp_n = wid >> 1;
    if (tid < 128) bias_s[tid] = bias[bx*128 + tid];

    FragAcc acc[2][2];
    for (int i = 0; i < 2; i++)
        for (int j = 0; j < 2; j++)
            wmma::fill_fragment(acc[i][j], 0.0f);

    const int KC = DD/64;
    const __nv_bfloat16* Abase = Ap + ((size_t)(by >> 1)*KC)*TILE_ELEMS + (size_t)(by & 1)*64*TROW;
    const __nv_bfloat16* Bbase = Wp + (size_t)bx*KC*TILE_ELEMS;
    mainloop64(Abase, Bbase, dynsm, KC, tid, warp_m, warp_n, acc);

    float* stage = ((float*)dynsm) + wid*256;
    int r = lane >> 1, halfc = (lane & 1)*8;
    float rm[2], rs[2];
    rm[0] = rm[1] = -1e30f; rs[0] = rs[1] = 0.f;
    for (int am = 0; am < 2; am++) {
        for (int an = 0; an < 2; an++) {
            wmma::store_matrix_sync(stage, acc[am][an], 16, wmma::mem_row_major);
            __syncwarp();
            int coll = warp_n*32 + an*16 + halfc;
            float vv[8];
            float mx = -1e30f;
            for (int j = 0; j < 8; j++) {
                vv[j] = stage[r*16 + halfc + j] + bias_s[coll + j];
                mx = fmaxf(mx, vv[j]);
            }
            float mxo = __shfl_xor_sync(0xffffffffu, mx, 1);
            float mxa = fmaxf(mx, mxo);
            float se = 0.f;
            for (int j = 0; j < 8; j++) se += expf(vv[j] - mxa);
            se += __shfl_xor_sync(0xffffffffu, se, 1);
            if (mxa > rm[am]) { rs[am] = rs[am]*expf(rm[am] - mxa) + se; rm[am] = mxa; }
            else              { rs[am] += se*expf(mxa - rm[am]); }
            __syncwarp();
        }
    }
    for (int am = 0; am < 2; am++) {
        int rl = warp_m*32 + am*16 + r;
        if ((lane & 1) == 0) red[rl][warp_n] = make_float2(rm[am], rs[am]);
    }
    __syncthreads();
    if (tid < 64) {
        int grow = by*64 + tid;
        if (grow < Mact) {
            float m = -1e30f, s = 0.f;
            for (int w = 0; w < 4; w++) {
                float2 p = red[tid][w];
                if (p.x > m) { s = s*expf(m - p.x) + p.y; m = p.x; }
                else         { s += p.y*expf(p.x - m); }
            }
            g_smpart[(size_t)grow*NCH2 + bx] = make_float2(m, s);
        }
    }
}

// ------------------- attention ----------------------------------------------
__global__ void attn_scores() {
    int bh = blockIdx.x; int b = bh / HH, h = bh % HH;
    __shared__ float ks[SS][HD];
    const float* base = g_qkv + (size_t)b*SS*3*DD;
    for (int i = threadIdx.x; i < SS*HD; i += blockDim.x) {
        int s = i / HD, d = i % HD;
        ks[s][d] = base[(size_t)s*3*DD + DD + h*HD + d];
    }
    __syncthreads();
    int q = threadIdx.x;
    if (q < SS) {
        float qr[HD];
#pragma unroll
        for (int d = 0; d < HD; d++) qr[d] = base[(size_t)q*3*DD + h*HD + d];
        float* srow = g_scores + ((size_t)bh*SS + q)*SS;
        for (int k = 0; k < SS; k++) {
            const float4* k4 = (const float4*)ks[k];
            float a = 0.f;
#pragma unroll
            for (int dq = 0; dq < 16; dq++) {
                float4 kv = k4[dq];
                a += qr[4*dq+0]*kv.x + qr[4*dq+1]*kv.y + qr[4*dq+2]*kv.z + qr[4*dq+3]*kv.w;
            }
            srow[k] = a * 0.125f;
        }
    }
}

__global__ void attn_softmax() {
    int row = blockIdx.x*4 + threadIdx.x/32;
    int lane = threadIdx.x % 32;
    if (row >= BB*HH*SS) return;
    float* p = g_scores + (size_t)row*SS;
    float v[5];
    float mx = -1e30f;
    int cnt = 0;
    for (int i = lane; i < SS; i += 32) { v[cnt] = p[i]; mx = fmaxf(mx, v[cnt]); cnt++; }
#pragma unroll
    for (int off = 16; off; off >>= 1) mx = fmaxf(mx, __shfl_xor_sync(0xffffffffu, mx, off));
    float se = 0.f;
    for (int c = 0; c < cnt; c++) { v[c] = expf(v[c]-mx); se += v[c]; }
#pragma unroll
    for (int off = 16; off; off >>= 1) se += __shfl_xor_sync(0xffffffffu, se, off);
    float inv = 1.f/se;
    cnt = 0;
    for (int i = lane; i < SS; i += 32) { p[i] = v[cnt]*inv; cnt++; }
}

// ctx with float2 per thread; writes packed bf16 directly
__global__ void attn_ctx2() {
    int bh = blockIdx.x; int b = bh / HH, h = bh % HH;
    __shared__ float vs[SS][HD];
    const float* base = g_qkv + (size_t)b*SS*3*DD + 2*DD + h*HD;
    for (int i = threadIdx.x; i < SS*HD; i += blockDim.x) {
        int s = i / HD, d = i % HD;
        vs[s][d] = base[(size_t)s*3*DD + d];
    }
    __syncthreads();
    for (int i = threadIdx.x; i < SS*(HD/2); i += blockDim.x) {
        int q = i / (HD/2), dp = i % (HD/2);
        const float* pr = g_scores + ((size_t)bh*SS + q)*SS;
        float a0 = 0.f, a1 = 0.f;
        for (int k = 0; k < SS; k++) {
            float pkv = pr[k];
            float2 v = *(const float2*)&vs[k][2*dp];
            a0 += pkv*v.x; a1 += pkv*v.y;
        }
        int m = b*SS + q;
        __nv_bfloat162 o = __float22bfloat162_rn(make_float2(a0, a1));
        *(__nv_bfloat162*)(g_ctxpk + (((size_t)(m >> 7)*8 + h)*TILE_ELEMS
                           + (size_t)(m & 127)*TROW + 2*dp)) = o;
    }
}

// ------------------- residual + layernorm (fp32 + packed bf16 out) -----------
__global__ void ln_kernel(float* __restrict__ x, __nv_bfloat16* __restrict__ xpk,
                          const float* __restrict__ add,
                          const float* __restrict__ gam, const float* __restrict__ bet) {
    __shared__ float red[256];
    __shared__ float stats[2];
    int tid = threadIdx.x;
    int row = blockIdx.x;
    float2 xv = ((float2*)(x + (size_t)row*DD))[tid];
    float2 av = ((const float2*)(add + (size_t)row*DD))[tid];
    float v0 = xv.x + av.x;
    float v1 = xv.y + av.y;
    red[tid] = v0 + v1;
    __syncthreads();
    for (int st = 128; st; st >>= 1) { if (tid < st) red[tid] += red[tid+st]; __syncthreads(); }
    if (tid == 0) stats[0] = red[0] * (1.f/DD);
    __syncthreads();
    float mean = stats[0];
    float d0 = v0 - mean, d1 = v1 - mean;
    red[tid] = d0*d0 + d1*d1;
    __syncthreads();
    for (int st = 128; st; st >>= 1) { if (tid < st) red[tid] += red[tid+st]; __syncthreads(); }
    if (tid == 0) stats[1] = rsqrtf(red[0]*(1.f/DD) + EPSV);
    __syncthreads();
    float inv = stats[1];
    float o0 = d0*inv*gam[2*tid]   + bet[2*tid];
    float o1 = d1*inv*gam[2*tid+1] + bet[2*tid+1];
    ((float2*)(x + (size_t)row*DD))[tid] = make_float2(o0, o1);
    __nv_bfloat162 ob = __float22bfloat162_rn(make_float2(o0, o1));
    *(__nv_bfloat162*)(xpk + pk(row, 2*tid, 8)) = ob;
}

// ------------------- velocity loss partials + pred_x1 (packed) ---------------
__global__ void velpred_kernel(const float* __restrict__ t, const float* __restrict__ x0) {
    int nv = g_nvalid;
    int total = nv * DD;
    float lsum = 0.f;
    for (int e = blockIdx.x*blockDim.x + threadIdx.x; e < total; e += gridDim.x*blockDim.x) {
        int r = e / DD, d = e % DD;
        int orig = g_comporig[r];
        int b = orig / WIN;
        int j = orig % WIN;
        float pv = g_predv[((size_t)(b*SS + 1 + j))*DD + d];
        float diff = pv - (g_x1[(size_t)orig*DD + d] - x0[(size_t)orig*DD + d]);
        lsum += diff*diff;
        g_px1pk[pk(r, d, 8)] = __float2bfloat16(g_xt[(size_t)orig*DD + d] + (1.f - t[b])*pv);
    }
    __shared__ float sm[256];
    sm[threadIdx.x] = lsum;
    __syncthreads();
    for (int st = 128; st; st >>= 1) { if (threadIdx.x < st) sm[threadIdx.x] += sm[threadIdx.x+st]; __syncthreads(); }
    if (threadIdx.x == 0) g_velred[blockIdx.x] = sm[0];
}

// ------------------- picked logit (packed operands) --------------------------
__global__ void picked_kernel(const float* __restrict__ decB) {
    int r = blockIdx.x*8 + threadIdx.x/32;
    int lane = threadIdx.x % 32;
    if (r >= g_nvalid) return;
    int lab = g_complabel[r];
    float s = 0.f;
    for (int i = lane; i < DD; i += 32) {
        __nv_bfloat16 a = g_habpk[pk(r, i, 8)];
        __nv_bfloat16 w = g_wdecP[pk(lab, i, 8)];
        s += __bfloat162float(a) * __bfloat162float(w);
    }
#pragma unroll
    for (int off = 16; off; off >>= 1) s += __shfl_xor_sync(0xffffffffu, s, off);
    if (lane == 0) g_picked[r] = s + decB[lab];
}

// ------------------- logsumexp combine ---------------------------------------
__global__ void combine_kernel() {
    int r = blockIdx.x;
    int nv = g_nvalid;
    float m = -1e30f, s = 0.f;
    if (r < nv) {
        for (int i = threadIdx.x; i < NCH2; i += blockDim.x) {
            float2 p = g_smpart[(size_t)r*NCH2 + i];
            if (p.x > m) { s = s*expf(m - p.x) + p.y; m = p.x; }
            else         { s += p.y*expf(p.x - m); }
        }
    }
    __shared__ float sm[128], ss[128];
    sm[threadIdx.x] = m; ss[threadIdx.x] = s;
    __syncthreads();
    for (int st = 64; st; st >>= 1) {
        if (threadIdx.x < st) {
            float m1 = sm[threadIdx.x], s1 = ss[threadIdx.x];
            float m2 = sm[threadIdx.x+st], s2 = ss[threadIdx.x+st];
            float M = fmaxf(m1, m2);
            sm[threadIdx.x] = M;
            ss[threadIdx.x] = s1*expf(m1 - M) + s2*expf(m2 - M);
        }
        __syncthreads();
    }
    if (threadIdx.x == 0) {
        if (r < nv) {
            float lse = sm[0] + logf(ss[0]);
            g_rowrecon[r] = lse - g_picked[r];
        } else {
            g_rowrecon[r] = 0.f;
        }
    }
}

// ------------------- final loss ----------------------------------------------
__global__ void final_kernel(float* __restrict__ out) {
    __shared__ float sm[256];
    int tid = threadIdx.x;
    int nv = g_nvalid;
    sm[tid] = g_velred[tid];
    __syncthreads();
    for (int st = 128; st; st >>= 1) { if (tid < st) sm[tid] += sm[tid+st]; __syncthreads(); }
    float vel = sm[0] / ((float)nv * (float)DD);
    __syncthreads();
    float r = 0.f;
    for (int i = tid; i < nv; i += 256) r += g_rowrecon[i];
    sm[tid] = r;
    __syncthreads();
    for (int st = 128; st; st >>= 1) { if (tid < st) sm[tid] += sm[tid+st]; __syncthreads(); }
    if (tid == 0) out[0] = vel + 0.1f * (sm[0] / (float)nv);
}

// ------------------- host side -----------------------------------------------
extern "C" void kernel_launch(void* const* d_in, const int* in_sizes, int n_in,
                              void* d_out, int out_size) {
    (void)in_sizes; (void)n_in; (void)out_size;
    const int*   tok       = (const int*)  d_in[0];
    const int*   motif_ids = (const int*)  d_in[1];
    const int*   motif_len = (const int*)  d_in[2];
    const int*   ws        = (const int*)  d_in[3];
    const int*   we        = (const int*)  d_in[4];
    const float* t         = (const float*)d_in[5];
    const float* x0        = (const float*)d_in[6];
    const float* emb       = (const float*)d_in[7];
    const float* decW      = (const float*)d_in[8];
    const float* decB      = (const float*)d_in[9];
    const float* adW       = (const float*)d_in[10];
    const float* adB       = (const float*)d_in[11];
    const float* tpW       = (const float*)d_in[12];
    const float* tpB       = (const float*)d_in[13];
    const float* cpW       = (const float*)d_in[14];
    const float* cpB       = (const float*)d_in[15];
    const float* qkvW      = (const float*)d_in[16];
    const float* qkvB      = (const float*)d_in[17];
    const float* aoW       = (const float*)d_in[18];
    const float* aoB       = (const float*)d_in[19];
    const float* f1W       = (const float*)d_in[20];
    const float* f1B       = (const float*)d_in[21];
    const float* f2W       = (const float*)d_in[22];
    const float* f2B       = (const float*)d_in[23];
    const float* ln1g      = (const float*)d_in[24];
    const float* ln1b      = (const float*)d_in[25];
    const float* ln2g      = (const float*)d_in[26];
    const float* ln2b      = (const float*)d_in[27];
    const float* outW      = (const float*)d_in[28];
    const float* outB      = (const float*)d_in[29];

    static bool inited = false;
    static float *p_x, *p_tmp, *p_predv, *p_qkv;
    static __nv_bfloat16 *p_xpk, *p_ctxpk, *p_ffpk, *p_px1pk, *p_habpk;
    static __nv_bfloat16 *p_wqkvP, *p_waoP, *p_wf1P, *p_wf2P, *p_woutP, *p_wadP, *p_wdecP;
    if (!inited) {
        cudaGetSymbolAddress((void**)&p_x,      g_x);
        cudaGetSymbolAddress((void**)&p_tmp,    g_tmp);
        cudaGetSymbolAddress((void**)&p_predv,  g_predv);
        cudaGetSymbolAddress((void**)&p_qkv,    g_qkv);
        cudaGetSymbolAddress((void**)&p_xpk,    g_xpk);
        cudaGetSymbolAddress((void**)&p_ctxpk,  g_ctxpk);
        cudaGetSymbolAddress((void**)&p_ffpk,   g_ffpk);
        cudaGetSymbolAddress((void**)&p_px1pk,  g_px1pk);
        cudaGetSymbolAddress((void**)&p_habpk,  g_habpk);
        cudaGetSymbolAddress((void**)&p_wqkvP,  g_wqkvP);
        cudaGetSymbolAddress((void**)&p_waoP,   g_waoP);
        cudaGetSymbolAddress((void**)&p_wf1P,   g_wf1P);
        cudaGetSymbolAddress((void**)&p_wf2P,   g_wf2P);
        cudaGetSymbolAddress((void**)&p_woutP,  g_woutP);
        cudaGetSymbolAddress((void**)&p_wadP,   g_wadP);
        cudaGetSymbolAddress((void**)&p_wdecP,  g_wdecP);
        cudaFuncSetAttribute(gemm64, cudaFuncAttributeMaxDynamicSharedMemorySize, DYNSM);
        cudaFuncSetAttribute(decode64, cudaFuncAttributeMaxDynamicSharedMemorySize, DYNSM);
        inited = true;
    }

    // 0: weights fp32 -> packed bf16 (one launch)
    wpack_all<<<12864, 256>>>(qkvW, aoW, f1W, f2W, outW, adW, decW);
    // 1-2: pools + prep
    pool_partial<<<dim3(BB, 8), 512>>>(tok, ws, we, emb);
    prep_kernel<<<BB, 512>>>(motif_ids, motif_len, ws, we, emb, t);
    // 3: temb + cond projections
    gemm_small2<<<16, 256>>>(tpW, tpB, cpW, cpB);
    // 4: build x (+ cond rows + compaction)
    build_all2<<<4129, 256>>>(tok, ws, we, t, x0, emb);

    // transformer layers
    for (int i = 0; i < NLAYER; i++) {
        gemm64<<<dim3(12, 34), 256, DYNSM>>>(
            p_xpk, p_wqkvP + (size_t)i*12*8*TILE_ELEMS, qkvB + (size_t)i*3*DD,
            p_qkv, (__nv_bfloat16*)0, RT, 3*DD, 8, 0, 0);
        attn_scores<<<BB*HH, 256>>>();
        attn_softmax<<<(BB*HH*SS + 3)/4, 128>>>();
        attn_ctx2<<<BB*HH, 256>>>();
        gemm64<<<dim3(4, 34), 256, DYNSM>>>(
            p_ctxpk, p_waoP + (size_t)i*4*8*TILE_ELEMS, aoB + (size_t)i*DD,
            p_tmp, (__nv_bfloat16*)0, RT, DD, 8, 0, 0);
        ln_kernel<<<RT, 256>>>(p_x, p_xpk, p_tmp, ln1g + (size_t)i*DD, ln1b + (size_t)i*DD);
        gemm64<<<dim3(16, 34), 256, DYNSM>>>(
            p_xpk, p_wf1P + (size_t)i*16*8*TILE_ELEMS, f1B + (size_t)i*FF,
            (float*)0, p_ffpk, RT, FF, 8, 0, 1);
        gemm64<<<dim3(4, 34), 256, DYNSM>>>(
            p_ffpk, p_wf2P + (size_t)i*4*32*TILE_ELEMS, f2B + (size_t)i*DD,
            p_tmp, (__nv_bfloat16*)0, RT, DD, 32, 0, 0);
        ln_kernel<<<RT, 256>>>(p_x, p_xpk, p_tmp, ln2g + (size_t)i*DD, ln2b + (size_t)i*DD);
    }

    // pred_v over all transformer rows (valid rows consumed by velpred)
    gemm64<<<dim3(4, 34), 256, DYNSM>>>(
        p_xpk, p_woutP, outB, p_predv, (__nv_bfloat16*)0, RT, DD, 8, 0, 0);
    velpred_kernel<<<256, 256>>>(t, x0);
    // adapter over compact valid rows -> packed hab
    gemm64<<<dim3(4, 32), 256, DYNSM>>>(
        p_px1pk, p_wadP, adB, (float*)0, p_habpk, WR, DD, 8, 1, 0);
    // decode GEMM with fused online softmax partials
    decode64<<<dim3(NCH2, 32), 256, DYNSM>>>(p_habpk, p_wdecP, decB);
    picked_kernel<<<WR/8, 256>>>(decB);
    combine_kernel<<<WR, 128>>>();
    final_kernel<<<1, 256>>>((float*)d_out);
}

// round 7
// speedup vs baseline: 3.3237x; 1.3586x over previous
#include <cuda_runtime.h>
#include <cuda_bf16.h>
#include <mma.h>
#include <math.h>
#include <stdint.h>

using namespace nvcuda;

#define BB 16
#define LL 2048
#define WIN 128
#define DD 512
#define HH 8
#define HD 64
#define FF 2048
#define NLAYER 3
#define VV 32000
#define MMOT 32
#define SS 129            // WIN + 1 (cond row)
#define RT (BB*SS)        // 2064 transformer rows
#define RTP 2176          // RT padded to 128
#define WR (BB*WIN)       // 2048 window rows
#define EPSV 1e-5f
#define NCH2 (VV/128)     // 250 softmax partial chunks

#define TROW 72                    // padded tile row stride (elems)
#define TILE_ELEMS (128*TROW)      // 9216
#define STG (64*TROW*2 + 128*TROW*2)   // 27648 bytes per stage (A64 + B128)
#define DYNSM (4*STG + 32)

// ---------------- mbarrier / bulk-copy PTX macros ----------------------------
#define MBARRIER_INIT(mbar_smem_addr, count) \
    asm volatile("mbarrier.init.shared.b64 [%0], %1;" \
        :: "r"((uint32_t)(mbar_smem_addr)), "r"((uint32_t)(count)) : "memory")

#define MBARRIER_EXPECT_TX(mbar_smem_addr, tx_bytes) \
    asm volatile("mbarrier.arrive.expect_tx.shared.b64 _, [%0], %1;" \
        :: "r"((uint32_t)(mbar_smem_addr)), "r"((uint32_t)(tx_bytes)) : "memory")

#define MBARRIER_WAIT_PARITY(mbar_smem_addr, phase_parity) do { \
    uint32_t _mbar = (uint32_t)(mbar_smem_addr); \
    uint32_t _parity = (uint32_t)(phase_parity); \
    uint32_t _done; \
    asm volatile( \
        "{\n\t" \
        ".reg .pred p;\n\t" \
        "mbarrier.try_wait.parity.acquire.cta.shared::cta.b64 p, [%1], %2;\n\t" \
        "selp.b32 %0, 1, 0, p;\n\t" \
        "}" \
        : "=r"(_done) : "r"(_mbar), "r"(_parity) : "memory"); \
    if (!_done) { \
        asm volatile( \
            "{\n\t" \
            ".reg .pred P1;\n\t" \
            "WAIT_LOOP_%=:\n\t" \
            "mbarrier.try_wait.parity.acquire.cta.shared::cta.b64 P1, [%0], %1, 0x989680;\n\t" \
            "@P1 bra.uni WAIT_DONE_%=;\n\t" \
            "bra.uni WAIT_LOOP_%=;\n\t" \
            "WAIT_DONE_%=:\n\t" \
            "}" \
            :: "r"(_mbar), "r"(_parity) : "memory"); \
    } \
} while(0)

#define BULK_LOAD(dst_smem, src_gmem, nbytes, mbar_smem) \
    asm volatile("cp.async.bulk.shared::cluster.global.mbarrier::complete_tx::bytes [%0], [%1], %2, [%3];" \
        :: "r"((uint32_t)(dst_smem)), "l"(src_gmem), "r"((uint32_t)(nbytes)), \
           "r"((uint32_t)(mbar_smem)) : "memory")

#define FENCE_PROXY_ASYNC() \
    asm volatile("fence.proxy.async.shared::cta;" ::: "memory")

__device__ __forceinline__ uint32_t sptr(const void* p) {
    return (uint32_t)__cvta_generic_to_shared(p);
}

// packed layout offset: tiles [m/128][k/64] of [128][TROW]
__device__ __forceinline__ size_t pk(int m, int k, int KC) {
    return ((size_t)(m >> 7)*KC + (k >> 6))*TILE_ELEMS + (size_t)(m & 127)*TROW + (k & 63);
}

// ------------------- device scratch (static, no allocation) -------------------
__device__ float g_condin[BB*4*DD];
__device__ float g_poolpart[BB*8*3*DD];
__device__ float g_tin[BB*DD];
__device__ float g_temb[BB*DD];
__device__ float g_condout[BB*DD];
__device__ float g_x[RT*DD];
__device__ float g_xt[WR*DD];
__device__ float g_x1[WR*DD];
__device__ float g_qkv[RT*3*DD];
__device__ float g_scores[BB*HH*SS*SS];
__device__ float g_tmp[RT*DD];
__device__ float g_predv[RTP*DD];
__device__ float2 g_smpart[(size_t)WR*NCH2];
__device__ float g_picked[WR];
__device__ float g_rowrecon[WR];
__device__ float g_velred[256];
__device__ int g_comporig[WR];
__device__ int g_complabel[WR];
__device__ int g_amap[WR];
__device__ int g_nvalid;

// packed bf16 activations
__device__ __align__(16) __nv_bfloat16 g_xpk[17*8*TILE_ELEMS];
__device__ __align__(16) __nv_bfloat16 g_ctxpk[17*8*TILE_ELEMS];
__device__ __align__(16) __nv_bfloat16 g_ffpk[17*32*TILE_ELEMS];
__device__ __align__(16) __nv_bfloat16 g_px1pk[16*8*TILE_ELEMS];
__device__ __align__(16) __nv_bfloat16 g_habpk[16*8*TILE_ELEMS];
// packed bf16 weights
__device__ __align__(16) __nv_bfloat16 g_wqkvP[NLAYER*12*8*TILE_ELEMS];
__device__ __align__(16) __nv_bfloat16 g_waoP[NLAYER*4*8*TILE_ELEMS];
__device__ __align__(16) __nv_bfloat16 g_wf1P[NLAYER*16*8*TILE_ELEMS];
__device__ __align__(16) __nv_bfloat16 g_wf2P[NLAYER*4*32*TILE_ELEMS];
__device__ __align__(16) __nv_bfloat16 g_woutP[4*8*TILE_ELEMS];
__device__ __align__(16) __nv_bfloat16 g_wadP[4*8*TILE_ELEMS];
__device__ __align__(16) __nv_bfloat16 g_wdecP[250*8*TILE_ELEMS];

// ------------------- fused weight packing ------------------------------------
__device__ __forceinline__ void packone(const float4* __restrict__ W,
                                        __nv_bfloat16* __restrict__ dst, int idx, int K) {
    int ck = K >> 3;
    int n = idx / ck, q = idx - n*ck;
    int k = q << 3;
    int kc = k >> 6, c8 = (k >> 3) & 7;
    int KC = K >> 6;
    size_t doff = ((size_t)(n >> 7)*KC + kc)*TILE_ELEMS + (size_t)(n & 127)*TROW + c8*8;
    float4 a = W[(size_t)idx*2], b = W[(size_t)idx*2 + 1];
    __nv_bfloat162 r0 = __float22bfloat162_rn(make_float2(a.x, a.y));
    __nv_bfloat162 r1 = __float22bfloat162_rn(make_float2(a.z, a.w));
    __nv_bfloat162 r2 = __float22bfloat162_rn(make_float2(b.x, b.y));
    __nv_bfloat162 r3 = __float22bfloat162_rn(make_float2(b.z, b.w));
    uint4 v;
    v.x = *(uint32_t*)&r0; v.y = *(uint32_t*)&r1;
    v.z = *(uint32_t*)&r2; v.w = *(uint32_t*)&r3;
    ((uint4*)dst)[doff >> 3] = v;
}

__global__ void wpack_all(const float* qkvW, const float* aoW, const float* f1W,
                          const float* f2W, const float* outW, const float* adW,
                          const float* decW) {
    int idx = blockIdx.x*blockDim.x + threadIdx.x;
    if      (idx <  294912) packone((const float4*)qkvW, g_wqkvP, idx,           512);
    else if (idx <  393216) packone((const float4*)aoW,  g_waoP,  idx - 294912,  512);
    else if (idx <  786432) packone((const float4*)f1W,  g_wf1P,  idx - 393216,  512);
    else if (idx < 1179648) packone((const float4*)f2W,  g_wf2P,  idx - 786432,  2048);
    else if (idx < 1212416) packone((const float4*)outW, g_woutP, idx - 1179648, 512);
    else if (idx < 1245184) packone((const float4*)adW,  g_wadP,  idx - 1212416, 512);
    else if (idx < 3293184) packone((const float4*)decW, g_wdecP, idx - 1245184, 512);
}

// ------------------- pools -----------------------------------------------------
__global__ void pool_partial(const int* __restrict__ tok, const int* __restrict__ ws,
                             const int* __restrict__ we, const float* __restrict__ emb) {
    int b = blockIdx.x, c = blockIdx.y, d = threadIdx.x;
    int s0 = ws[b], e0 = we[b];
    float gl = 0.f, lf = 0.f, rt = 0.f;
    int l0 = c * (LL/8);
#pragma unroll 4
    for (int i = 0; i < LL/8; i++) {
        int l = l0 + i;
        int t = tok[b*LL + l];
        float v = emb[(size_t)t*DD + d];
        gl += v;
        if (l < s0)  lf += v;
        if (l >= e0) rt += v;
    }
    float* p = g_poolpart + ((size_t)(b*8 + c)*3)*DD;
    p[d] = lf; p[DD + d] = rt; p[2*DD + d] = gl;
}

// pool_reduce + motif + time-embedding input fused
__global__ void prep_kernel(const int* __restrict__ mot, const int* __restrict__ mlen,
                            const int* __restrict__ ws, const int* __restrict__ we,
                            const float* __restrict__ emb, const float* __restrict__ t) {
    int b = blockIdx.x, d = threadIdx.x;
    float lf = 0.f, rt = 0.f, gl = 0.f;
    for (int c = 0; c < 8; c++) {
        const float* p = g_poolpart + ((size_t)(b*8 + c)*3)*DD;
        lf += p[d]; rt += p[DD + d]; gl += p[2*DD + d];
    }
    int ml = mlen[b];
    float mo = 0.f;
    for (int i = 0; i < MMOT; i++)
        if (i < ml) mo += emb[(size_t)mot[b*MMOT + i]*DD + d];
    mo /= (float)(ml > 1 ? ml : 1);
    float lden = (float)(ws[b] > 1 ? ws[b] : 1);
    int rc = LL - we[b];
    float rden = (float)(rc > 1 ? rc : 1);
    float* o = g_condin + (size_t)b*4*DD;
    o[d]        = mo;
    o[DD + d]   = lf / lden;
    o[2*DD + d] = rt / rden;
    o[3*DD + d] = gl / (float)LL;
    // time embedding input
    int k = d % (DD/2);
    float f = expf(-logf(10000.f) * (float)k / (float)(DD/2 - 1));
    float a = t[b] * f;
    g_tin[b*DD + d] = (d < DD/2) ? sinf(a) : cosf(a);
}

// ------------------- small fp32 GEMMs: warp-per-column -----------------------
// 1024 warps: 0..511 -> temb (K=512), 512..1023 -> condout (K=2048)
__global__ void gemm_small3(const float* __restrict__ tpW, const float* __restrict__ tpB,
                            const float* __restrict__ cpW, const float* __restrict__ cpB) {
    int gw = blockIdx.x*8 + (threadIdx.x >> 5);
    int lane = threadIdx.x & 31;
    const float* A; const float* Wt; const float* bias; float* C; int K; int col;
    if (gw < 512) { A = g_tin;    Wt = tpW; bias = tpB; C = g_temb;    K = 512;  col = gw; }
    else          { A = g_condin; Wt = cpW; bias = cpB; C = g_condout; K = 2048; col = gw - 512; }
    const float* w = Wt + (size_t)col*K;
    float b = bias[col];
    for (int row = 0; row < BB; row++) {
        const float* a = A + (size_t)row*K;
        float s = 0.f;
        for (int k = lane*4; k < K; k += 128) {
            float4 av = *(const float4*)(a + k);
            float4 wv = *(const float4*)(w + k);
            s += av.x*wv.x + av.y*wv.y + av.z*wv.z + av.w*wv.w;
        }
#pragma unroll
        for (int off = 16; off; off >>= 1) s += __shfl_xor_sync(0xffffffffu, s, off);
        if (lane == 0) C[(size_t)row*DD + col] = s + b;
    }
}

// ------------------- fused build: x_t/x1/x + cond rows + compaction ----------
__global__ void build_all2(const int* __restrict__ tok, const int* __restrict__ ws,
                           const int* __restrict__ we, const float* __restrict__ t,
                           const float* __restrict__ x0, const float* __restrict__ emb) {
    int bid = blockIdx.x;
    int tid = threadIdx.x;
    if (bid < 4096) {
        int idx = bid*256 + tid;
        int d = idx % DD; int r = idx / DD; int j = r % WIN; int b = r / WIN;
        int s0 = ws[b];
        int act = we[b] - s0;
        float x1v = 0.f;
        if (j < act) {
            int tk = tok[b*LL + s0 + j];
            x1v = emb[(size_t)tk*DD + d];
        }
        float tv = t[b];
        float xt = (1.f - tv)*x0[idx] + tv*x1v;
        g_x1[idx] = x1v;
        g_xt[idx] = xt;
        float xv = xt + g_temb[b*DD + d];
        int m = b*SS + 1 + j;
        g_x[(size_t)m*DD + d] = xv;
        g_xpk[pk(m, d, 8)] = __float2bfloat16(xv);
    } else if (bid < 4128) {
        int local = (bid - 4096)*256 + tid;   // < 8192
        int b = local >> 9, d = local & 511;
        float v = g_condout[b*DD + d];
        int m = b*SS;
        g_x[(size_t)m*DD + d] = v;
        g_xpk[pk(m, d, 8)] = __float2bfloat16(v);
    } else {
        __shared__ int off[BB+1];
        if (tid == 0) {
            off[0] = 0;
            for (int b = 0; b < BB; b++) {
                int a = we[b] - ws[b];
                if (a < 0) a = 0;
                if (a > WIN) a = WIN;
                off[b+1] = off[b] + a;
            }
            g_nvalid = off[BB];
        }
        __syncthreads();
        for (int idx = tid; idx < BB*WIN; idx += 256) {
            int b = idx / WIN, j = idx % WIN;
            int a = off[b+1] - off[b];
            if (j < a) {
                int r = off[b] + j;
                g_comporig[r]  = idx;
                g_amap[r]      = b*SS + 1 + j;
                g_complabel[r] = tok[b*LL + ws[b] + j];
            }
        }
    }
}

// ------------------- wmma compute on one 64x128x64 chunk ---------------------
using FragAcc = wmma::fragment<wmma::accumulator, 16, 16, 16, float>;

__device__ __forceinline__ void compute64(const __nv_bfloat16* sa, const __nv_bfloat16* sb,
                                          int warp_m, int warp_n, FragAcc (&acc)[2][2]) {
#pragma unroll
    for (int kk = 0; kk < 64; kk += 16) {
        wmma::fragment<wmma::matrix_a, 16, 16, 16, __nv_bfloat16, wmma::row_major> af[2];
#pragma unroll
        for (int am = 0; am < 2; am++)
            wmma::load_matrix_sync(af[am], sa + (warp_m*32 + am*16)*TROW + kk, TROW);
#pragma unroll
        for (int an = 0; an < 2; an++) {
            wmma::fragment<wmma::matrix_b, 16, 16, 16, __nv_bfloat16, wmma::col_major> bf;
            wmma::load_matrix_sync(bf, sb + (warp_n*32 + an*16)*TROW + kk, TROW);
#pragma unroll
            for (int am = 0; am < 2; am++)
                wmma::mma_sync(acc[am][an], af[am], bf, acc[am][an]);
        }
    }
}

__device__ __forceinline__ void mainloop64(const __nv_bfloat16* Abase,
        const __nv_bfloat16* Bbase, unsigned char* dynsm, int nk, int tid,
        int warp_m, int warp_n, FragAcc (&acc)[2][2]) {
    uint32_t mb = sptr(dynsm + 4*STG);
    if (tid == 0) {
        MBARRIER_INIT(mb,      1);
        MBARRIER_INIT(mb + 8,  1);
        MBARRIER_INIT(mb + 16, 1);
        MBARRIER_INIT(mb + 24, 1);
    }
    __syncthreads();
    if (tid == 0) {
        FENCE_PROXY_ASYNC();
#pragma unroll
        for (int s = 0; s < 3; s++) {
            MBARRIER_EXPECT_TX(mb + 8*s, STG);
            BULK_LOAD(sptr(dynsm + s*STG), Abase + (size_t)s*TILE_ELEMS, 64*TROW*2, mb + 8*s);
            BULK_LOAD(sptr(dynsm + s*STG + 64*TROW*2), Bbase + (size_t)s*TILE_ELEMS, 128*TROW*2, mb + 8*s);
        }
    }
    for (int i = 0; i < nk; i++) {
        int s = i & 3;
        int ph = (i >> 2) & 1;
        MBARRIER_WAIT_PARITY(mb + 8*s, ph);
        compute64((const __nv_bfloat16*)(dynsm + s*STG),
                  (const __nv_bfloat16*)(dynsm + s*STG + 64*TROW*2),
                  warp_m, warp_n, acc);
        __syncthreads();
        if (tid == 0 && i + 3 < nk) {
            FENCE_PROXY_ASYNC();
            int s2 = (i + 3) & 3;
            MBARRIER_EXPECT_TX(mb + 8*s2, STG);
            BULK_LOAD(sptr(dynsm + s2*STG), Abase + (size_t)(i+3)*TILE_ELEMS, 64*TROW*2, mb + 8*s2);
            BULK_LOAD(sptr(dynsm + s2*STG + 64*TROW*2), Bbase + (size_t)(i+3)*TILE_ELEMS, 128*TROW*2, mb + 8*s2);
        }
    }
}

// ------------------- packed GEMM: C = A @ W^T + bias -------------------------
__global__ void __launch_bounds__(256) gemm64(const __nv_bfloat16* __restrict__ Ap,
        const __nv_bfloat16* __restrict__ Wp, const float* __restrict__ bias,
        float* C, __nv_bfloat16* Cpk, int Mh, int N, int KC, int use_nv, int relu) {
    extern __shared__ __align__(16) unsigned char dynsm[];
    int Mact = use_nv ? g_nvalid : Mh;
    int by = blockIdx.y, bx = blockIdx.x;
    if (by*64 >= Mact) return;
    int tid = threadIdx.x, lane = tid & 31, wid = tid >> 5;
    int warp_m = wid & 1, warp_n = wid >> 1;

    FragAcc acc[2][2];
    for (int i = 0; i < 2; i++)
        for (int j = 0; j < 2; j++)
            wmma::fill_fragment(acc[i][j], 0.0f);

    const __nv_bfloat16* Abase = Ap + ((size_t)(by >> 1)*KC)*TILE_ELEMS + (size_t)(by & 1)*64*TROW;
    const __nv_bfloat16* Bbase = Wp + (size_t)bx*KC*TILE_ELEMS;
    mainloop64(Abase, Bbase, dynsm, KC, tid, warp_m, warp_n, acc);

    float* stage = ((float*)dynsm) + wid*256;
    int r = lane >> 1, halfc = (lane & 1)*8;
    int KCo = N >> 6;
    for (int am = 0; am < 2; am++) {
        for (int an = 0; an < 2; an++) {
            wmma::store_matrix_sync(stage, acc[am][an], 16, wmma::mem_row_major);
            __syncwarp();
            int grow = by*64 + warp_m*32 + am*16 + r;
            int gcol = bx*128 + warp_n*32 + an*16 + halfc;
            if (grow < Mact) {
                float v[8];
                for (int j = 0; j < 8; j++) {
                    v[j] = stage[r*16 + halfc + j] + bias[gcol + j];
                    if (relu) v[j] = fmaxf(v[j], 0.f);
                }
                if (C) {
                    float4* p = (float4*)(C + (size_t)grow*N + gcol);
                    p[0] = make_float4(v[0], v[1], v[2], v[3]);
                    p[1] = make_float4(v[4], v[5], v[6], v[7]);
                }
                if (Cpk) {
                    __nv_bfloat162 b0 = __float22bfloat162_rn(make_float2(v[0], v[1]));
                    __nv_bfloat162 b1 = __float22bfloat162_rn(make_float2(v[2], v[3]));
                    __nv_bfloat162 b2 = __float22bfloat162_rn(make_float2(v[4], v[5]));
                    __nv_bfloat162 b3 = __float22bfloat162_rn(make_float2(v[6], v[7]));
                    uint4 u;
                    u.x = *(uint32_t*)&b0; u.y = *(uint32_t*)&b1;
                    u.z = *(uint32_t*)&b2; u.w = *(uint32_t*)&b3;
                    *(uint4*)(Cpk + pk(grow, gcol, KCo)) = u;
                }
            }
            __syncwarp();
        }
    }
}

// ------------------- packed decode GEMM + fused online-softmax ---------------
__global__ void __launch_bounds__(256) decode64(const __nv_bfloat16* __restrict__ Ap,
        const __nv_bfloat16* __restrict__ Wp, const float* __restrict__ bias) {
    extern __shared__ __align__(16) unsigned char dynsm[];
    __shared__ float bias_s[128];
    __shared__ float2 red[64][4];
    int Mact = g_nvalid;
    int by = blockIdx.y, bx = blockIdx.x;
    if (by*64 >= Mact) return;
    int tid = threadIdx.x, lane = tid & 31, wid = tid >> 5;
    int warp_m = wid & 1, warp_n = wid >> 1;
    if (tid < 128) bias_s[tid] = bias[bx*128 + tid];

    FragAcc acc[2][2];
    for (int i = 0; i < 2; i++)
        for (int j = 0; j < 2; j++)
            wmma::fill_fragment(acc[i][j], 0.0f);

    const int KC = DD/64;
    const __nv_bfloat16* Abase = Ap + ((size_t)(by >> 1)*KC)*TILE_ELEMS + (size_t)(by & 1)*64*TROW;
    const __nv_bfloat16* Bbase = Wp + (size_t)bx*KC*TILE_ELEMS;
    mainloop64(Abase, Bbase, dynsm, KC, tid, warp_m, warp_n, acc);

    float* stage = ((float*)dynsm) + wid*256;
    int r = lane >> 1, halfc = (lane & 1)*8;
    float rm[2], rs[2];
    rm[0] = rm[1] = -1e30f; rs[0] = rs[1] = 0.f;
    for (int am = 0; am < 2; am++) {
        for (int an = 0; an < 2; an++) {
            wmma::store_matrix_sync(stage, acc[am][an], 16, wmma::mem_row_major);
            __syncwarp();
            int coll = warp_n*32 + an*16 + halfc;
            float vv[8];
            float mx = -1e30f;
            for (int j = 0; j < 8; j++) {
                vv[j] = stage[r*16 + halfc + j] + bias_s[coll + j];
                mx = fmaxf(mx, vv[j]);
            }
            float mxo = __shfl_xor_sync(0xffffffffu, mx, 1);
            float mxa = fmaxf(mx, mxo);
            float se = 0.f;
            for (int j = 0; j < 8; j++) se += expf(vv[j] - mxa);
            se += __shfl_xor_sync(0xffffffffu, se, 1);
            if (mxa > rm[am]) { rs[am] = rs[am]*expf(rm[am] - mxa) + se; rm[am] = mxa; }
            else              { rs[am] += se*expf(mxa - rm[am]); }
            __syncwarp();
        }
    }
    for (int am = 0; am < 2; am++) {
        int rl = warp_m*32 + am*16 + r;
        if ((lane & 1) == 0) red[rl][warp_n] = make_float2(rm[am], rs[am]);
    }
    __syncthreads();
    if (tid < 64) {
        int grow = by*64 + tid;
        if (grow < Mact) {
            float m = -1e30f, s = 0.f;
            for (int w = 0; w < 4; w++) {
                float2 p = red[tid][w];
                if (p.x > m) { s = s*expf(m - p.x) + p.y; m = p.x; }
                else         { s += p.y*expf(p.x - m); }
            }
            g_smpart[(size_t)grow*NCH2 + bx] = make_float2(m, s);
        }
    }
}

// ------------------- attention ----------------------------------------------
__global__ void attn_scores() {
    int bh = blockIdx.x; int b = bh / HH, h = bh % HH;
    __shared__ float ks[SS][HD];
    const float* base = g_qkv + (size_t)b*SS*3*DD;
    for (int i = threadIdx.x; i < SS*HD; i += blockDim.x) {
        int s = i / HD, d = i % HD;
        ks[s][d] = base[(size_t)s*3*DD + DD + h*HD + d];
    }
    __syncthreads();
    int q = threadIdx.x;
    if (q < SS) {
        float qr[HD];
#pragma unroll
        for (int d = 0; d < HD; d++) qr[d] = base[(size_t)q*3*DD + h*HD + d];
        float* srow = g_scores + ((size_t)bh*SS + q)*SS;
        for (int k = 0; k < SS; k++) {
            const float4* k4 = (const float4*)ks[k];
            float a = 0.f;
#pragma unroll
            for (int dq = 0; dq < 16; dq++) {
                float4 kv = k4[dq];
                a += qr[4*dq+0]*kv.x + qr[4*dq+1]*kv.y + qr[4*dq+2]*kv.z + qr[4*dq+3]*kv.w;
            }
            srow[k] = a * 0.125f;
        }
    }
}

__global__ void attn_softmax() {
    int row = blockIdx.x*4 + threadIdx.x/32;
    int lane = threadIdx.x % 32;
    if (row >= BB*HH*SS) return;
    float* p = g_scores + (size_t)row*SS;
    float v[5];
    float mx = -1e30f;
    int cnt = 0;
    for (int i = lane; i < SS; i += 32) { v[cnt] = p[i]; mx = fmaxf(mx, v[cnt]); cnt++; }
#pragma unroll
    for (int off = 16; off; off >>= 1) mx = fmaxf(mx, __shfl_xor_sync(0xffffffffu, mx, off));
    float se = 0.f;
    for (int c = 0; c < cnt; c++) { v[c] = expf(v[c]-mx); se += v[c]; }
#pragma unroll
    for (int off = 16; off; off >>= 1) se += __shfl_xor_sync(0xffffffffu, se, off);
    float inv = 1.f/se;
    cnt = 0;
    for (int i = lane; i < SS; i += 32) { p[i] = v[cnt]*inv; cnt++; }
}

// ctx with float2 per thread; writes packed bf16 directly
__global__ void attn_ctx2() {
    int bh = blockIdx.x; int b = bh / HH, h = bh % HH;
    __shared__ float vs[SS][HD];
    const float* base = g_qkv + (size_t)b*SS*3*DD + 2*DD + h*HD;
    for (int i = threadIdx.x; i < SS*HD; i += blockDim.x) {
        int s = i / HD, d = i % HD;
        vs[s][d] = base[(size_t)s*3*DD + d];
    }
    __syncthreads();
    for (int i = threadIdx.x; i < SS*(HD/2); i += blockDim.x) {
        int q = i / (HD/2), dp = i % (HD/2);
        const float* pr = g_scores + ((size_t)bh*SS + q)*SS;
        float a0 = 0.f, a1 = 0.f;
        for (int k = 0; k < SS; k++) {
            float pkv = pr[k];
            float2 v = *(const float2*)&vs[k][2*dp];
            a0 += pkv*v.x; a1 += pkv*v.y;
        }
        int m = b*SS + q;
        __nv_bfloat162 o = __float22bfloat162_rn(make_float2(a0, a1));
        *(__nv_bfloat162*)(g_ctxpk + (((size_t)(m >> 7)*8 + h)*TILE_ELEMS
                           + (size_t)(m & 127)*TROW + 2*dp)) = o;
    }
}

// ------------------- residual + layernorm (fp32 + packed bf16 out) -----------
__global__ void ln_kernel(float* __restrict__ x, __nv_bfloat16* __restrict__ xpk,
                          const float* __restrict__ add,
                          const float* __restrict__ gam, const float* __restrict__ bet) {
    __shared__ float red[256];
    __shared__ float stats[2];
    int tid = threadIdx.x;
    int row = blockIdx.x;
    float2 xv = ((float2*)(x + (size_t)row*DD))[tid];
    float2 av = ((const float2*)(add + (size_t)row*DD))[tid];
    float v0 = xv.x + av.x;
    float v1 = xv.y + av.y;
    red[tid] = v0 + v1;
    __syncthreads();
    for (int st = 128; st; st >>= 1) { if (tid < st) red[tid] += red[tid+st]; __syncthreads(); }
    if (tid == 0) stats[0] = red[0] * (1.f/DD);
    __syncthreads();
    float mean = stats[0];
    float d0 = v0 - mean, d1 = v1 - mean;
    red[tid] = d0*d0 + d1*d1;
    __syncthreads();
    for (int st = 128; st; st >>= 1) { if (tid < st) red[tid] += red[tid+st]; __syncthreads(); }
    if (tid == 0) stats[1] = rsqrtf(red[0]*(1.f/DD) + EPSV);
    __syncthreads();
    float inv = stats[1];
    float o0 = d0*inv*gam[2*tid]   + bet[2*tid];
    float o1 = d1*inv*gam[2*tid+1] + bet[2*tid+1];
    ((float2*)(x + (size_t)row*DD))[tid] = make_float2(o0, o1);
    __nv_bfloat162 ob = __float22bfloat162_rn(make_float2(o0, o1));
    *(__nv_bfloat162*)(xpk + pk(row, 2*tid, 8)) = ob;
}

// ------------------- velocity loss partials + pred_x1 (packed) ---------------
__global__ void velpred_kernel(const float* __restrict__ t, const float* __restrict__ x0) {
    int nv = g_nvalid;
    int total = nv * DD;
    float lsum = 0.f;
    for (int e = blockIdx.x*blockDim.x + threadIdx.x; e < total; e += gridDim.x*blockDim.x) {
        int r = e / DD, d = e % DD;
        int orig = g_comporig[r];
        int b = orig / WIN;
        int j = orig % WIN;
        float pv = g_predv[((size_t)(b*SS + 1 + j))*DD + d];
        float diff = pv - (g_x1[(size_t)orig*DD + d] - x0[(size_t)orig*DD + d]);
        lsum += diff*diff;
        g_px1pk[pk(r, d, 8)] = __float2bfloat16(g_xt[(size_t)orig*DD + d] + (1.f - t[b])*pv);
    }
    __shared__ float sm[256];
    sm[threadIdx.x] = lsum;
    __syncthreads();
    for (int st = 128; st; st >>= 1) { if (threadIdx.x < st) sm[threadIdx.x] += sm[threadIdx.x+st]; __syncthreads(); }
    if (threadIdx.x == 0) g_velred[blockIdx.x] = sm[0];
}

// ------------------- picked logit (packed operands) --------------------------
__global__ void picked_kernel(const float* __restrict__ decB) {
    int r = blockIdx.x*8 + threadIdx.x/32;
    int lane = threadIdx.x % 32;
    if (r >= g_nvalid) return;
    int lab = g_complabel[r];
    float s = 0.f;
    for (int i = lane; i < DD; i += 32) {
        __nv_bfloat16 a = g_habpk[pk(r, i, 8)];
        __nv_bfloat16 w = g_wdecP[pk(lab, i, 8)];
        s += __bfloat162float(a) * __bfloat162float(w);
    }
#pragma unroll
    for (int off = 16; off; off >>= 1) s += __shfl_xor_sync(0xffffffffu, s, off);
    if (lane == 0) g_picked[r] = s + decB[lab];
}

// ------------------- logsumexp combine ---------------------------------------
__global__ void combine_kernel() {
    int r = blockIdx.x;
    int nv = g_nvalid;
    float m = -1e30f, s = 0.f;
    if (r < nv) {
        for (int i = threadIdx.x; i < NCH2; i += blockDim.x) {
            float2 p = g_smpart[(size_t)r*NCH2 + i];
            if (p.x > m) { s = s*expf(m - p.x) + p.y; m = p.x; }
            else         { s += p.y*expf(p.x - m); }
        }
    }
    __shared__ float sm[128], ss[128];
    sm[threadIdx.x] = m; ss[threadIdx.x] = s;
    __syncthreads();
    for (int st = 64; st; st >>= 1) {
        if (threadIdx.x < st) {
            float m1 = sm[threadIdx.x], s1 = ss[threadIdx.x];
            float m2 = sm[threadIdx.x+st], s2 = ss[threadIdx.x+st];
            float M = fmaxf(m1, m2);
            sm[threadIdx.x] = M;
            ss[threadIdx.x] = s1*expf(m1 - M) + s2*expf(m2 - M);
        }
        __syncthreads();
    }
    if (threadIdx.x == 0) {
        if (r < nv) {
            float lse = sm[0] + logf(ss[0]);
            g_rowrecon[r] = lse - g_picked[r];
        } else {
            g_rowrecon[r] = 0.f;
        }
    }
}

// ------------------- final loss ----------------------------------------------
__global__ void final_kernel(float* __restrict__ out) {
    __shared__ float sm[256];
    int tid = threadIdx.x;
    int nv = g_nvalid;
    sm[tid] = g_velred[tid];
    __syncthreads();
    for (int st = 128; st; st >>= 1) { if (tid < st) sm[tid] += sm[tid+st]; __syncthreads(); }
    float vel = sm[0] / ((float)nv * (float)DD);
    __syncthreads();
    float r = 0.f;
    for (int i = tid; i < nv; i += 256) r += g_rowrecon[i];
    sm[tid] = r;
    __syncthreads();
    for (int st = 128; st; st >>= 1) { if (tid < st) sm[tid] += sm[tid+st]; __syncthreads(); }
    if (tid == 0) out[0] = vel + 0.1f * (sm[0] / (float)nv);
}

// ------------------- host side -----------------------------------------------
extern "C" void kernel_launch(void* const* d_in, const int* in_sizes, int n_in,
                              void* d_out, int out_size) {
    (void)in_sizes; (void)n_in; (void)out_size;
    const int*   tok       = (const int*)  d_in[0];
    const int*   motif_ids = (const int*)  d_in[1];
    const int*   motif_len = (const int*)  d_in[2];
    const int*   ws        = (const int*)  d_in[3];
    const int*   we        = (const int*)  d_in[4];
    const float* t         = (const float*)d_in[5];
    const float* x0        = (const float*)d_in[6];
    const float* emb       = (const float*)d_in[7];
    const float* decW      = (const float*)d_in[8];
    const float* decB      = (const float*)d_in[9];
    const float* adW       = (const float*)d_in[10];
    const float* adB       = (const float*)d_in[11];
    const float* tpW       = (const float*)d_in[12];
    const float* tpB       = (const float*)d_in[13];
    const float* cpW       = (const float*)d_in[14];
    const float* cpB       = (const float*)d_in[15];
    const float* qkvW      = (const float*)d_in[16];
    const float* qkvB      = (const float*)d_in[17];
    const float* aoW       = (const float*)d_in[18];
    const float* aoB       = (const float*)d_in[19];
    const float* f1W       = (const float*)d_in[20];
    const float* f1B       = (const float*)d_in[21];
    const float* f2W       = (const float*)d_in[22];
    const float* f2B       = (const float*)d_in[23];
    const float* ln1g      = (const float*)d_in[24];
    const float* ln1b      = (const float*)d_in[25];
    const float* ln2g      = (const float*)d_in[26];
    const float* ln2b      = (const float*)d_in[27];
    const float* outW      = (const float*)d_in[28];
    const float* outB      = (const float*)d_in[29];

    static bool inited = false;
    static float *p_x, *p_tmp, *p_predv, *p_qkv;
    static __nv_bfloat16 *p_xpk, *p_ctxpk, *p_ffpk, *p_px1pk, *p_habpk;
    static __nv_bfloat16 *p_wqkvP, *p_waoP, *p_wf1P, *p_wf2P, *p_woutP, *p_wadP, *p_wdecP;
    if (!inited) {
        cudaGetSymbolAddress((void**)&p_x,      g_x);
        cudaGetSymbolAddress((void**)&p_tmp,    g_tmp);
        cudaGetSymbolAddress((void**)&p_predv,  g_predv);
        cudaGetSymbolAddress((void**)&p_qkv,    g_qkv);
        cudaGetSymbolAddress((void**)&p_xpk,    g_xpk);
        cudaGetSymbolAddress((void**)&p_ctxpk,  g_ctxpk);
        cudaGetSymbolAddress((void**)&p_ffpk,   g_ffpk);
        cudaGetSymbolAddress((void**)&p_px1pk,  g_px1pk);
        cudaGetSymbolAddress((void**)&p_habpk,  g_habpk);
        cudaGetSymbolAddress((void**)&p_wqkvP,  g_wqkvP);
        cudaGetSymbolAddress((void**)&p_waoP,   g_waoP);
        cudaGetSymbolAddress((void**)&p_wf1P,   g_wf1P);
        cudaGetSymbolAddress((void**)&p_wf2P,   g_wf2P);
        cudaGetSymbolAddress((void**)&p_woutP,  g_woutP);
        cudaGetSymbolAddress((void**)&p_wadP,   g_wadP);
        cudaGetSymbolAddress((void**)&p_wdecP,  g_wdecP);
        cudaFuncSetAttribute(gemm64, cudaFuncAttributeMaxDynamicSharedMemorySize, DYNSM);
        cudaFuncSetAttribute(decode64, cudaFuncAttributeMaxDynamicSharedMemorySize, DYNSM);
        inited = true;
    }

    // 0: weights fp32 -> packed bf16 (one launch)
    wpack_all<<<12864, 256>>>(qkvW, aoW, f1W, f2W, outW, adW, decW);
    // 1-2: pools + prep
    pool_partial<<<dim3(BB, 8), 512>>>(tok, ws, we, emb);
    prep_kernel<<<BB, 512>>>(motif_ids, motif_len, ws, we, emb, t);
    // 3: temb + cond projections (warp-per-column, full chip)
    gemm_small3<<<128, 256>>>(tpW, tpB, cpW, cpB);
    // 4: build x (+ cond rows + compaction)
    build_all2<<<4129, 256>>>(tok, ws, we, t, x0, emb);

    // transformer layers
    for (int i = 0; i < NLAYER; i++) {
        gemm64<<<dim3(12, 34), 256, DYNSM>>>(
            p_xpk, p_wqkvP + (size_t)i*12*8*TILE_ELEMS, qkvB + (size_t)i*3*DD,
            p_qkv, (__nv_bfloat16*)0, RT, 3*DD, 8, 0, 0);
        attn_scores<<<BB*HH, 256>>>();
        attn_softmax<<<(BB*HH*SS + 3)/4, 128>>>();
        attn_ctx2<<<BB*HH, 256>>>();
        gemm64<<<dim3(4, 34), 256, DYNSM>>>(
            p_ctxpk, p_waoP + (size_t)i*4*8*TILE_ELEMS, aoB + (size_t)i*DD,
            p_tmp, (__nv_bfloat16*)0, RT, DD, 8, 0, 0);
        ln_kernel<<<RT, 256>>>(p_x, p_xpk, p_tmp, ln1g + (size_t)i*DD, ln1b + (size_t)i*DD);
        gemm64<<<dim3(16, 34), 256, DYNSM>>>(
            p_xpk, p_wf1P + (size_t)i*16*8*TILE_ELEMS, f1B + (size_t)i*FF,
            (float*)0, p_ffpk, RT, FF, 8, 0, 1);
        gemm64<<<dim3(4, 34), 256, DYNSM>>>(
            p_ffpk, p_wf2P + (size_t)i*4*32*TILE_ELEMS, f2B + (size_t)i*DD,
            p_tmp, (__nv_bfloat16*)0, RT, DD, 32, 0, 0);
        ln_kernel<<<RT, 256>>>(p_x, p_xpk, p_tmp, ln2g + (size_t)i*DD, ln2b + (size_t)i*DD);
    }

    // pred_v over all transformer rows (valid rows consumed by velpred)
    gemm64<<<dim3(4, 34), 256, DYNSM>>>(
        p_xpk, p_woutP, outB, p_predv, (__nv_bfloat16*)0, RT, DD, 8, 0, 0);
    velpred_kernel<<<256, 256>>>(t, x0);
    // adapter over compact valid rows -> packed hab
    gemm64<<<dim3(4, 32), 256, DYNSM>>>(
        p_px1pk, p_wadP, adB, (float*)0, p_habpk, WR, DD, 8, 1, 0);
    // decode GEMM with fused online softmax partials
    decode64<<<dim3(NCH2, 32), 256, DYNSM>>>(p_habpk, p_wdecP, decB);
    picked_kernel<<<WR/8, 256>>>(decB);
    combine_kernel<<<WR, 128>>>();
    final_kernel<<<1, 256>>>((float*)d_out);
}

// round 8
// speedup vs baseline: 3.3856x; 1.0186x over previous
#include <cuda_runtime.h>
#include <cuda_bf16.h>
#include <mma.h>
#include <math.h>
#include <stdint.h>

using namespace nvcuda;

#define BB 16
#define LL 2048
#define WIN 128
#define DD 512
#define HH 8
#define HD 64
#define FF 2048
#define NLAYER 3
#define VV 32000
#define MMOT 32
#define SS 129            // WIN + 1 (cond row)
#define RT (BB*SS)        // 2064 transformer rows
#define RTP 2176          // RT padded to 128
#define WR (BB*WIN)       // 2048 window rows
#define EPSV 1e-5f
#define NCH2 (VV/128)     // 250 softmax partial chunks

#define TROW 72                    // padded tile row stride (elems)
#define TILE_ELEMS (128*TROW)      // 9216
#define STG (64*TROW*2 + 128*TROW*2)   // 27648 bytes per stage (A64 + B128)
#define DYNSM (4*STG + 32)

// ---------------- mbarrier / bulk-copy PTX macros ----------------------------
#define MBARRIER_INIT(mbar_smem_addr, count) \
    asm volatile("mbarrier.init.shared.b64 [%0], %1;" \
        :: "r"((uint32_t)(mbar_smem_addr)), "r"((uint32_t)(count)) : "memory")

#define MBARRIER_EXPECT_TX(mbar_smem_addr, tx_bytes) \
    asm volatile("mbarrier.arrive.expect_tx.shared.b64 _, [%0], %1;" \
        :: "r"((uint32_t)(mbar_smem_addr)), "r"((uint32_t)(tx_bytes)) : "memory")

#define MBARRIER_WAIT_PARITY(mbar_smem_addr, phase_parity) do { \
    uint32_t _mbar = (uint32_t)(mbar_smem_addr); \
    uint32_t _parity = (uint32_t)(phase_parity); \
    uint32_t _done; \
    asm volatile( \
        "{\n\t" \
        ".reg .pred p;\n\t" \
        "mbarrier.try_wait.parity.acquire.cta.shared::cta.b64 p, [%1], %2;\n\t" \
        "selp.b32 %0, 1, 0, p;\n\t" \
        "}" \
        : "=r"(_done) : "r"(_mbar), "r"(_parity) : "memory"); \
    if (!_done) { \
        asm volatile( \
            "{\n\t" \
            ".reg .pred P1;\n\t" \
            "WAIT_LOOP_%=:\n\t" \
            "mbarrier.try_wait.parity.acquire.cta.shared::cta.b64 P1, [%0], %1, 0x989680;\n\t" \
            "@P1 bra.uni WAIT_DONE_%=;\n\t" \
            "bra.uni WAIT_LOOP_%=;\n\t" \
            "WAIT_DONE_%=:\n\t" \
            "}" \
            :: "r"(_mbar), "r"(_parity) : "memory"); \
    } \
} while(0)

#define BULK_LOAD(dst_smem, src_gmem, nbytes, mbar_smem) \
    asm volatile("cp.async.bulk.shared::cluster.global.mbarrier::complete_tx::bytes [%0], [%1], %2, [%3];" \
        :: "r"((uint32_t)(dst_smem)), "l"(src_gmem), "r"((uint32_t)(nbytes)), \
           "r"((uint32_t)(mbar_smem)) : "memory")

#define FENCE_PROXY_ASYNC() \
    asm volatile("fence.proxy.async.shared::cta;" ::: "memory")

__device__ __forceinline__ uint32_t sptr(const void* p) {
    return (uint32_t)__cvta_generic_to_shared(p);
}

// packed layout offset: tiles [m/128][k/64] of [128][TROW]
__device__ __forceinline__ size_t pk(int m, int k, int KC) {
    return ((size_t)(m >> 7)*KC + (k >> 6))*TILE_ELEMS + (size_t)(m & 127)*TROW + (k & 63);
}

// ------------------- device scratch (static, no allocation) -------------------
__device__ float g_condin[BB*4*DD];
__device__ float g_poolpart[BB*8*3*DD];
__device__ float g_tin[BB*DD];
__device__ float g_temb[BB*DD];
__device__ float g_condout[BB*DD];
__device__ float g_x[RT*DD];
__device__ float g_xt[WR*DD];
__device__ float g_x1[WR*DD];
__device__ float g_qkv[RT*3*DD];
__device__ float g_scores[BB*HH*SS*SS];
__device__ float g_tmp[RT*DD];
__device__ float g_predv[RTP*DD];
__device__ float2 g_smpart[(size_t)WR*NCH2];
__device__ float g_picked[WR];
__device__ float g_rowrecon[WR];
__device__ float g_velred[256];
__device__ int g_comporig[WR];
__device__ int g_complabel[WR];
__device__ int g_amap[WR];
__device__ int g_nvalid;

// packed bf16 activations
__device__ __align__(16) __nv_bfloat16 g_xpk[17*8*TILE_ELEMS];
__device__ __align__(16) __nv_bfloat16 g_ctxpk[17*8*TILE_ELEMS];
__device__ __align__(16) __nv_bfloat16 g_ffpk[17*32*TILE_ELEMS];
__device__ __align__(16) __nv_bfloat16 g_px1pk[16*8*TILE_ELEMS];
__device__ __align__(16) __nv_bfloat16 g_habpk[16*8*TILE_ELEMS];
// packed bf16 weights
__device__ __align__(16) __nv_bfloat16 g_wqkvP[NLAYER*12*8*TILE_ELEMS];
__device__ __align__(16) __nv_bfloat16 g_waoP[NLAYER*4*8*TILE_ELEMS];
__device__ __align__(16) __nv_bfloat16 g_wf1P[NLAYER*16*8*TILE_ELEMS];
__device__ __align__(16) __nv_bfloat16 g_wf2P[NLAYER*4*32*TILE_ELEMS];
__device__ __align__(16) __nv_bfloat16 g_woutP[4*8*TILE_ELEMS];
__device__ __align__(16) __nv_bfloat16 g_wadP[4*8*TILE_ELEMS];
__device__ __align__(16) __nv_bfloat16 g_wdecP[250*8*TILE_ELEMS];

// ------------------- fused weight packing ------------------------------------
__device__ __forceinline__ void packone(const float4* __restrict__ W,
                                        __nv_bfloat16* __restrict__ dst, int idx, int K) {
    int ck = K >> 3;
    int n = idx / ck, q = idx - n*ck;
    int k = q << 3;
    int kc = k >> 6, c8 = (k >> 3) & 7;
    int KC = K >> 6;
    size_t doff = ((size_t)(n >> 7)*KC + kc)*TILE_ELEMS + (size_t)(n & 127)*TROW + c8*8;
    float4 a = W[(size_t)idx*2], b = W[(size_t)idx*2 + 1];
    __nv_bfloat162 r0 = __float22bfloat162_rn(make_float2(a.x, a.y));
    __nv_bfloat162 r1 = __float22bfloat162_rn(make_float2(a.z, a.w));
    __nv_bfloat162 r2 = __float22bfloat162_rn(make_float2(b.x, b.y));
    __nv_bfloat162 r3 = __float22bfloat162_rn(make_float2(b.z, b.w));
    uint4 v;
    v.x = *(uint32_t*)&r0; v.y = *(uint32_t*)&r1;
    v.z = *(uint32_t*)&r2; v.w = *(uint32_t*)&r3;
    ((uint4*)dst)[doff >> 3] = v;
}

__global__ void wpack_all(const float* qkvW, const float* aoW, const float* f1W,
                          const float* f2W, const float* outW, const float* adW,
                          const float* decW) {
    int idx = blockIdx.x*blockDim.x + threadIdx.x;
    if      (idx <  294912) packone((const float4*)qkvW, g_wqkvP, idx,           512);
    else if (idx <  393216) packone((const float4*)aoW,  g_waoP,  idx - 294912,  512);
    else if (idx <  786432) packone((const float4*)f1W,  g_wf1P,  idx - 393216,  512);
    else if (idx < 1179648) packone((const float4*)f2W,  g_wf2P,  idx - 786432,  2048);
    else if (idx < 1212416) packone((const float4*)outW, g_woutP, idx - 1179648, 512);
    else if (idx < 1245184) packone((const float4*)adW,  g_wadP,  idx - 1212416, 512);
    else if (idx < 3293184) packone((const float4*)decW, g_wdecP, idx - 1245184, 512);
}

// ------------------- pools -----------------------------------------------------
__global__ void pool_partial(const int* __restrict__ tok, const int* __restrict__ ws,
                             const int* __restrict__ we, const float* __restrict__ emb) {
    int b = blockIdx.x, c = blockIdx.y, d = threadIdx.x;
    int s0 = ws[b], e0 = we[b];
    float gl = 0.f, lf = 0.f, rt = 0.f;
    int l0 = c * (LL/8);
#pragma unroll 4
    for (int i = 0; i < LL/8; i++) {
        int l = l0 + i;
        int t = tok[b*LL + l];
        float v = emb[(size_t)t*DD + d];
        gl += v;
        if (l < s0)  lf += v;
        if (l >= e0) rt += v;
    }
    float* p = g_poolpart + ((size_t)(b*8 + c)*3)*DD;
    p[d] = lf; p[DD + d] = rt; p[2*DD + d] = gl;
}

// pool_reduce + motif + time-embedding input fused
__global__ void prep_kernel(const int* __restrict__ mot, const int* __restrict__ mlen,
                            const int* __restrict__ ws, const int* __restrict__ we,
                            const float* __restrict__ emb, const float* __restrict__ t) {
    int b = blockIdx.x, d = threadIdx.x;
    float lf = 0.f, rt = 0.f, gl = 0.f;
    for (int c = 0; c < 8; c++) {
        const float* p = g_poolpart + ((size_t)(b*8 + c)*3)*DD;
        lf += p[d]; rt += p[DD + d]; gl += p[2*DD + d];
    }
    int ml = mlen[b];
    float mo = 0.f;
    for (int i = 0; i < MMOT; i++)
        if (i < ml) mo += emb[(size_t)mot[b*MMOT + i]*DD + d];
    mo /= (float)(ml > 1 ? ml : 1);
    float lden = (float)(ws[b] > 1 ? ws[b] : 1);
    int rc = LL - we[b];
    float rden = (float)(rc > 1 ? rc : 1);
    float* o = g_condin + (size_t)b*4*DD;
    o[d]        = mo;
    o[DD + d]   = lf / lden;
    o[2*DD + d] = rt / rden;
    o[3*DD + d] = gl / (float)LL;
    // time embedding input
    int k = d % (DD/2);
    float f = expf(-logf(10000.f) * (float)k / (float)(DD/2 - 1));
    float a = t[b] * f;
    g_tin[b*DD + d] = (d < DD/2) ? sinf(a) : cosf(a);
}

// ------------------- small fp32 GEMMs: warp per (column, row-pair) -----------
// 8192 warps = 1024 blocks: gw < 4096 -> temb (K=512), else -> condout (K=2048)
__global__ void gemm_small4(const float* __restrict__ tpW, const float* __restrict__ tpB,
                            const float* __restrict__ cpW, const float* __restrict__ cpB) {
    int gw = blockIdx.x*8 + (threadIdx.x >> 5);
    int lane = threadIdx.x & 31;
    const float* A; const float* Wt; const float* bias; float* C; int K; int col;
    if (gw < 4096) { A = g_tin;    Wt = tpW; bias = tpB; C = g_temb;    K = 512;  col = gw >> 3; }
    else           { A = g_condin; Wt = cpW; bias = cpB; C = g_condout; K = 2048; col = (gw - 4096) >> 3; }
    int row0 = (gw & 7)*2;
    const float* w = Wt + (size_t)col*K;
    float b = bias[col];
#pragma unroll
    for (int rr = 0; rr < 2; rr++) {
        int row = row0 + rr;
        const float* a = A + (size_t)row*K;
        float s = 0.f;
        for (int k = lane*4; k < K; k += 128) {
            float4 av = *(const float4*)(a + k);
            float4 wv = *(const float4*)(w + k);
            s += av.x*wv.x + av.y*wv.y + av.z*wv.z + av.w*wv.w;
        }
#pragma unroll
        for (int off = 16; off; off >>= 1) s += __shfl_xor_sync(0xffffffffu, s, off);
        if (lane == 0) C[(size_t)row*DD + col] = s + b;
    }
}

// ------------------- fused build: x_t/x1/x + cond rows + compaction ----------
__global__ void build_all2(const int* __restrict__ tok, const int* __restrict__ ws,
                           const int* __restrict__ we, const float* __restrict__ t,
                           const float* __restrict__ x0, const float* __restrict__ emb) {
    int bid = blockIdx.x;
    int tid = threadIdx.x;
    if (bid < 4096) {
        int idx = bid*256 + tid;
        int d = idx % DD; int r = idx / DD; int j = r % WIN; int b = r / WIN;
        int s0 = ws[b];
        int act = we[b] - s0;
        float x1v = 0.f;
        if (j < act) {
            int tk = tok[b*LL + s0 + j];
            x1v = emb[(size_t)tk*DD + d];
        }
        float tv = t[b];
        float xt = (1.f - tv)*x0[idx] + tv*x1v;
        g_x1[idx] = x1v;
        g_xt[idx] = xt;
        float xv = xt + g_temb[b*DD + d];
        int m = b*SS + 1 + j;
        g_x[(size_t)m*DD + d] = xv;
        g_xpk[pk(m, d, 8)] = __float2bfloat16(xv);
    } else if (bid < 4128) {
        int local = (bid - 4096)*256 + tid;   // < 8192
        int b = local >> 9, d = local & 511;
        float v = g_condout[b*DD + d];
        int m = b*SS;
        g_x[(size_t)m*DD + d] = v;
        g_xpk[pk(m, d, 8)] = __float2bfloat16(v);
    } else {
        __shared__ int off[BB+1];
        if (tid == 0) {
            off[0] = 0;
            for (int b = 0; b < BB; b++) {
                int a = we[b] - ws[b];
                if (a < 0) a = 0;
                if (a > WIN) a = WIN;
                off[b+1] = off[b] + a;
            }
            g_nvalid = off[BB];
        }
        __syncthreads();
        for (int idx = tid; idx < BB*WIN; idx += 256) {
            int b = idx / WIN, j = idx % WIN;
            int a = off[b+1] - off[b];
            if (j < a) {
                int r = off[b] + j;
                g_comporig[r]  = idx;
                g_amap[r]      = b*SS + 1 + j;
                g_complabel[r] = tok[b*LL + ws[b] + j];
            }
        }
    }
}

// ------------------- wmma compute on one 64x128x64 chunk ---------------------
using FragAcc = wmma::fragment<wmma::accumulator, 16, 16, 16, float>;

__device__ __forceinline__ void compute64(const __nv_bfloat16* sa, const __nv_bfloat16* sb,
                                          int warp_m, int warp_n, FragAcc (&acc)[2][2]) {
#pragma unroll
    for (int kk = 0; kk < 64; kk += 16) {
        wmma::fragment<wmma::matrix_a, 16, 16, 16, __nv_bfloat16, wmma::row_major> af[2];
#pragma unroll
        for (int am = 0; am < 2; am++)
            wmma::load_matrix_sync(af[am], sa + (warp_m*32 + am*16)*TROW + kk, TROW);
#pragma unroll
        for (int an = 0; an < 2; an++) {
            wmma::fragment<wmma::matrix_b, 16, 16, 16, __nv_bfloat16, wmma::col_major> bf;
            wmma::load_matrix_sync(bf, sb + (warp_n*32 + an*16)*TROW + kk, TROW);
#pragma unroll
            for (int am = 0; am < 2; am++)
                wmma::mma_sync(acc[am][an], af[am], bf, acc[am][an]);
        }
    }
}

__device__ __forceinline__ void mainloop64(const __nv_bfloat16* Abase,
        const __nv_bfloat16* Bbase, unsigned char* dynsm, int nk, int tid,
        int warp_m, int warp_n, FragAcc (&acc)[2][2]) {
    uint32_t mb = sptr(dynsm + 4*STG);
    if (tid == 0) {
        MBARRIER_INIT(mb,      1);
        MBARRIER_INIT(mb + 8,  1);
        MBARRIER_INIT(mb + 16, 1);
        MBARRIER_INIT(mb + 24, 1);
    }
    __syncthreads();
    if (tid == 0) {
        FENCE_PROXY_ASYNC();
#pragma unroll
        for (int s = 0; s < 3; s++) {
            MBARRIER_EXPECT_TX(mb + 8*s, STG);
            BULK_LOAD(sptr(dynsm + s*STG), Abase + (size_t)s*TILE_ELEMS, 64*TROW*2, mb + 8*s);
            BULK_LOAD(sptr(dynsm + s*STG + 64*TROW*2), Bbase + (size_t)s*TILE_ELEMS, 128*TROW*2, mb + 8*s);
        }
    }
    for (int i = 0; i < nk; i++) {
        int s = i & 3;
        int ph = (i >> 2) & 1;
        MBARRIER_WAIT_PARITY(mb + 8*s, ph);
        compute64((const __nv_bfloat16*)(dynsm + s*STG),
                  (const __nv_bfloat16*)(dynsm + s*STG + 64*TROW*2),
                  warp_m, warp_n, acc);
        __syncthreads();
        if (tid == 0 && i + 3 < nk) {
            FENCE_PROXY_ASYNC();
            int s2 = (i + 3) & 3;
            MBARRIER_EXPECT_TX(mb + 8*s2, STG);
            BULK_LOAD(sptr(dynsm + s2*STG), Abase + (size_t)(i+3)*TILE_ELEMS, 64*TROW*2, mb + 8*s2);
            BULK_LOAD(sptr(dynsm + s2*STG + 64*TROW*2), Bbase + (size_t)(i+3)*TILE_ELEMS, 128*TROW*2, mb + 8*s2);
        }
    }
}

// ------------------- packed GEMM: C = A @ W^T + bias -------------------------
__global__ void __launch_bounds__(256) gemm64(const __nv_bfloat16* __restrict__ Ap,
        const __nv_bfloat16* __restrict__ Wp, const float* __restrict__ bias,
        float* C, __nv_bfloat16* Cpk, int Mh, int N, int KC, int use_nv, int relu) {
    extern __shared__ __align__(16) unsigned char dynsm[];
    int Mact = use_nv ? g_nvalid : Mh;
    int by = blockIdx.y, bx = blockIdx.x;
    if (by*64 >= Mact) return;
    int tid = threadIdx.x, lane = tid & 31, wid = tid >> 5;
    int warp_m = wid & 1, warp_n = wid >> 1;

    FragAcc acc[2][2];
    for (int i = 0; i < 2; i++)
        for (int j = 0; j < 2; j++)
            wmma::fill_fragment(acc[i][j], 0.0f);

    const __nv_bfloat16* Abase = Ap + ((size_t)(by >> 1)*KC)*TILE_ELEMS + (size_t)(by & 1)*64*TROW;
    const __nv_bfloat16* Bbase = Wp + (size_t)bx*KC*TILE_ELEMS;
    mainloop64(Abase, Bbase, dynsm, KC, tid, warp_m, warp_n, acc);

    float* stage = ((float*)dynsm) + wid*256;
    int r = lane >> 1, halfc = (lane & 1)*8;
    int KCo = N >> 6;
    for (int am = 0; am < 2; am++) {
        for (int an = 0; an < 2; an++) {
            wmma::store_matrix_sync(stage, acc[am][an], 16, wmma::mem_row_major);
            __syncwarp();
            int grow = by*64 + warp_m*32 + am*16 + r;
            int gcol = bx*128 + warp_n*32 + an*16 + halfc;
            if (grow < Mact) {
                float v[8];
                for (int j = 0; j < 8; j++) {
                    v[j] = stage[r*16 + halfc + j] + bias[gcol + j];
                    if (relu) v[j] = fmaxf(v[j], 0.f);
                }
                if (C) {
                    float4* p = (float4*)(C + (size_t)grow*N + gcol);
                    p[0] = make_float4(v[0], v[1], v[2], v[3]);
                    p[1] = make_float4(v[4], v[5], v[6], v[7]);
                }
                if (Cpk) {
                    __nv_bfloat162 b0 = __float22bfloat162_rn(make_float2(v[0], v[1]));
                    __nv_bfloat162 b1 = __float22bfloat162_rn(make_float2(v[2], v[3]));
                    __nv_bfloat162 b2 = __float22bfloat162_rn(make_float2(v[4], v[5]));
                    __nv_bfloat162 b3 = __float22bfloat162_rn(make_float2(v[6], v[7]));
                    uint4 u;
                    u.x = *(uint32_t*)&b0; u.y = *(uint32_t*)&b1;
                    u.z = *(uint32_t*)&b2; u.w = *(uint32_t*)&b3;
                    *(uint4*)(Cpk + pk(grow, gcol, KCo)) = u;
                }
            }
            __syncwarp();
        }
    }
}

// ------------------- packed decode GEMM + fused online-softmax ---------------
__global__ void __launch_bounds__(256) decode64(const __nv_bfloat16* __restrict__ Ap,
        const __nv_bfloat16* __restrict__ Wp, const float* __restrict__ bias) {
    extern __shared__ __align__(16) unsigned char dynsm[];
    __shared__ float bias_s[128];
    __shared__ float2 red[64][4];
    int Mact = g_nvalid;
    int by = blockIdx.y, bx = blockIdx.x;
    if (by*64 >= Mact) return;
    int tid = threadIdx.x, lane = tid & 31, wid = tid >> 5;
    int warp_m = wid & 1, warp_n = wid >> 1;
    if (tid < 128) bias_s[tid] = bias[bx*128 + tid];

    FragAcc acc[2][2];
    for (int i = 0; i < 2; i++)
        for (int j = 0; j < 2; j++)
            wmma::fill_fragment(acc[i][j], 0.0f);

    const int KC = DD/64;
    const __nv_bfloat16* Abase = Ap + ((size_t)(by >> 1)*KC)*TILE_ELEMS + (size_t)(by & 1)*64*TROW;
    const __nv_bfloat16* Bbase = Wp + (size_t)bx*KC*TILE_ELEMS;
    mainloop64(Abase, Bbase, dynsm, KC, tid, warp_m, warp_n, acc);

    float* stage = ((float*)dynsm) + wid*256;
    int r = lane >> 1, halfc = (lane & 1)*8;
    float rm[2], rs[2];
    rm[0] = rm[1] = -1e30f; rs[0] = rs[1] = 0.f;
    for (int am = 0; am < 2; am++) {
        for (int an = 0; an < 2; an++) {
            wmma::store_matrix_sync(stage, acc[am][an], 16, wmma::mem_row_major);
            __syncwarp();
            int coll = warp_n*32 + an*16 + halfc;
            float vv[8];
            float mx = -1e30f;
            for (int j = 0; j < 8; j++) {
                vv[j] = stage[r*16 + halfc + j] + bias_s[coll + j];
                mx = fmaxf(mx, vv[j]);
            }
            float mxo = __shfl_xor_sync(0xffffffffu, mx, 1);
            float mxa = fmaxf(mx, mxo);
            float se = 0.f;
            for (int j = 0; j < 8; j++) se += expf(vv[j] - mxa);
            se += __shfl_xor_sync(0xffffffffu, se, 1);
            if (mxa > rm[am]) { rs[am] = rs[am]*expf(rm[am] - mxa) + se; rm[am] = mxa; }
            else              { rs[am] += se*expf(mxa - rm[am]); }
            __syncwarp();
        }
    }
    for (int am = 0; am < 2; am++) {
        int rl = warp_m*32 + am*16 + r;
        if ((lane & 1) == 0) red[rl][warp_n] = make_float2(rm[am], rs[am]);
    }
    __syncthreads();
    if (tid < 64) {
        int grow = by*64 + tid;
        if (grow < Mact) {
            float m = -1e30f, s = 0.f;
            for (int w = 0; w < 4; w++) {
                float2 p = red[tid][w];
                if (p.x > m) { s = s*expf(m - p.x) + p.y; m = p.x; }
                else         { s += p.y*expf(p.x - m); }
            }
            g_smpart[(size_t)grow*NCH2 + bx] = make_float2(m, s);
        }
    }
}

// ------------------- attention (scores + fused softmax) ----------------------
__global__ void attn_scores() {
    int bh = blockIdx.x; int b = bh / HH, h = bh % HH;
    __shared__ float ks[SS][HD];
    const float* base = g_qkv + (size_t)b*SS*3*DD;
    for (int i = threadIdx.x; i < SS*HD; i += blockDim.x) {
        int s = i / HD, d = i % HD;
        ks[s][d] = base[(size_t)s*3*DD + DD + h*HD + d];
    }
    __syncthreads();
    int q = threadIdx.x;
    if (q < SS) {
        float qr[HD];
#pragma unroll
        for (int d = 0; d < HD; d++) qr[d] = base[(size_t)q*3*DD + h*HD + d];
        float* srow = g_scores + ((size_t)bh*SS + q)*SS;
        float mx = -1e30f;
        for (int k = 0; k < SS; k++) {
            const float4* k4 = (const float4*)ks[k];
            float a = 0.f;
#pragma unroll
            for (int dq = 0; dq < 16; dq++) {
                float4 kv = k4[dq];
                a += qr[4*dq+0]*kv.x + qr[4*dq+1]*kv.y + qr[4*dq+2]*kv.z + qr[4*dq+3]*kv.w;
            }
            a *= 0.125f;
            srow[k] = a;
            mx = fmaxf(mx, a);
        }
        // fused softmax (rows are L1/L2-hot)
        float se = 0.f;
        for (int k = 0; k < SS; k++) {
            float e = expf(srow[k] - mx);
            srow[k] = e;
            se += e;
        }
        float inv = 1.f/se;
        for (int k = 0; k < SS; k++) srow[k] *= inv;
    }
}

// ctx with float2 per thread; writes packed bf16 directly
__global__ void attn_ctx2() {
    int bh = blockIdx.x; int b = bh / HH, h = bh % HH;
    __shared__ float vs[SS][HD];
    const float* base = g_qkv + (size_t)b*SS*3*DD + 2*DD + h*HD;
    for (int i = threadIdx.x; i < SS*HD; i += blockDim.x) {
        int s = i / HD, d = i % HD;
        vs[s][d] = base[(size_t)s*3*DD + d];
    }
    __syncthreads();
    for (int i = threadIdx.x; i < SS*(HD/2); i += blockDim.x) {
        int q = i / (HD/2), dp = i % (HD/2);
        const float* pr = g_scores + ((size_t)bh*SS + q)*SS;
        float a0 = 0.f, a1 = 0.f;
        for (int k = 0; k < SS; k++) {
            float pkv = pr[k];
            float2 v = *(const float2*)&vs[k][2*dp];
            a0 += pkv*v.x; a1 += pkv*v.y;
        }
        int m = b*SS + q;
        __nv_bfloat162 o = __float22bfloat162_rn(make_float2(a0, a1));
        *(__nv_bfloat162*)(g_ctxpk + (((size_t)(m >> 7)*8 + h)*TILE_ELEMS
                           + (size_t)(m & 127)*TROW + 2*dp)) = o;
    }
}

// ------------------- residual + layernorm (fp32 + packed bf16 out) -----------
__global__ void ln_kernel(float* __restrict__ x, __nv_bfloat16* __restrict__ xpk,
                          const float* __restrict__ add,
                          const float* __restrict__ gam, const float* __restrict__ bet) {
    __shared__ float red[256];
    __shared__ float stats[2];
    int tid = threadIdx.x;
    int row = blockIdx.x;
    float2 xv = ((float2*)(x + (size_t)row*DD))[tid];
    float2 av = ((const float2*)(add + (size_t)row*DD))[tid];
    float v0 = xv.x + av.x;
    float v1 = xv.y + av.y;
    red[tid] = v0 + v1;
    __syncthreads();
    for (int st = 128; st; st >>= 1) { if (tid < st) red[tid] += red[tid+st]; __syncthreads(); }
    if (tid == 0) stats[0] = red[0] * (1.f/DD);
    __syncthreads();
    float mean = stats[0];
    float d0 = v0 - mean, d1 = v1 - mean;
    red[tid] = d0*d0 + d1*d1;
    __syncthreads();
    for (int st = 128; st; st >>= 1) { if (tid < st) red[tid] += red[tid+st]; __syncthreads(); }
    if (tid == 0) stats[1] = rsqrtf(red[0]*(1.f/DD) + EPSV);
    __syncthreads();
    float inv = stats[1];
    float o0 = d0*inv*gam[2*tid]   + bet[2*tid];
    float o1 = d1*inv*gam[2*tid+1] + bet[2*tid+1];
    ((float2*)(x + (size_t)row*DD))[tid] = make_float2(o0, o1);
    __nv_bfloat162 ob = __float22bfloat162_rn(make_float2(o0, o1));
    *(__nv_bfloat162*)(xpk + pk(row, 2*tid, 8)) = ob;
}

// ------------------- velocity loss partials + pred_x1 (packed) ---------------
__global__ void velpred_kernel(const float* __restrict__ t, const float* __restrict__ x0) {
    int nv = g_nvalid;
    int total = nv * DD;
    float lsum = 0.f;
    for (int e = blockIdx.x*blockDim.x + threadIdx.x; e < total; e += gridDim.x*blockDim.x) {
        int r = e / DD, d = e % DD;
        int orig = g_comporig[r];
        int b = orig / WIN;
        int j = orig % WIN;
        float pv = g_predv[((size_t)(b*SS + 1 + j))*DD + d];
        float diff = pv - (g_x1[(size_t)orig*DD + d] - x0[(size_t)orig*DD + d]);
        lsum += diff*diff;
        g_px1pk[pk(r, d, 8)] = __float2bfloat16(g_xt[(size_t)orig*DD + d] + (1.f - t[b])*pv);
    }
    __shared__ float sm[256];
    sm[threadIdx.x] = lsum;
    __syncthreads();
    for (int st = 128; st; st >>= 1) { if (threadIdx.x < st) sm[threadIdx.x] += sm[threadIdx.x+st]; __syncthreads(); }
    if (threadIdx.x == 0) g_velred[blockIdx.x] = sm[0];
}

// ------------------- picked logit (packed operands) --------------------------
__global__ void picked_kernel(const float* __restrict__ decB) {
    int r = blockIdx.x*8 + threadIdx.x/32;
    int lane = threadIdx.x % 32;
    if (r >= g_nvalid) return;
    int lab = g_complabel[r];
    float s = 0.f;
    for (int i = lane; i < DD; i += 32) {
        __nv_bfloat16 a = g_habpk[pk(r, i, 8)];
        __nv_bfloat16 w = g_wdecP[pk(lab, i, 8)];
        s += __bfloat162float(a) * __bfloat162float(w);
    }
#pragma unroll
    for (int off = 16; off; off >>= 1) s += __shfl_xor_sync(0xffffffffu, s, off);
    if (lane == 0) g_picked[r] = s + decB[lab];
}

// ------------------- logsumexp combine ---------------------------------------
__global__ void combine_kernel() {
    int r = blockIdx.x;
    int nv = g_nvalid;
    float m = -1e30f, s = 0.f;
    if (r < nv) {
        for (int i = threadIdx.x; i < NCH2; i += blockDim.x) {
            float2 p = g_smpart[(size_t)r*NCH2 + i];
            if (p.x > m) { s = s*expf(m - p.x) + p.y; m = p.x; }
            else         { s += p.y*expf(p.x - m); }
        }
    }
    __shared__ float sm[128], ss[128];
    sm[threadIdx.x] = m; ss[threadIdx.x] = s;
    __syncthreads();
    for (int st = 64; st; st >>= 1) {
        if (threadIdx.x < st) {
            float m1 = sm[threadIdx.x], s1 = ss[threadIdx.x];
            float m2 = sm[threadIdx.x+st], s2 = ss[threadIdx.x+st];
            float M = fmaxf(m1, m2);
            sm[threadIdx.x] = M;
            ss[threadIdx.x] = s1*expf(m1 - M) + s2*expf(m2 - M);
        }
        __syncthreads();
    }
    if (threadIdx.x == 0) {
        if (r < nv) {
            float lse = sm[0] + logf(ss[0]);
            g_rowrecon[r] = lse - g_picked[r];
        } else {
            g_rowrecon[r] = 0.f;
        }
    }
}

// ------------------- final loss ----------------------------------------------
__global__ void final_kernel(float* __restrict__ out) {
    __shared__ float sm[256];
    int tid = threadIdx.x;
    int nv = g_nvalid;
    sm[tid] = g_velred[tid];
    __syncthreads();
    for (int st = 128; st; st >>= 1) { if (tid < st) sm[tid] += sm[tid+st]; __syncthreads(); }
    float vel = sm[0] / ((float)nv * (float)DD);
    __syncthreads();
    float r = 0.f;
    for (int i = tid; i < nv; i += 256) r += g_rowrecon[i];
    sm[tid] = r;
    __syncthreads();
    for (int st = 128; st; st >>= 1) { if (tid < st) sm[tid] += sm[tid+st]; __syncthreads(); }
    if (tid == 0) out[0] = vel + 0.1f * (sm[0] / (float)nv);
}

// ------------------- host side -----------------------------------------------
extern "C" void kernel_launch(void* const* d_in, const int* in_sizes, int n_in,
                              void* d_out, int out_size) {
    (void)in_sizes; (void)n_in; (void)out_size;
    const int*   tok       = (const int*)  d_in[0];
    const int*   motif_ids = (const int*)  d_in[1];
    const int*   motif_len = (const int*)  d_in[2];
    const int*   ws        = (const int*)  d_in[3];
    const int*   we        = (const int*)  d_in[4];
    const float* t         = (const float*)d_in[5];
    const float* x0        = (const float*)d_in[6];
    const float* emb       = (const float*)d_in[7];
    const float* decW      = (const float*)d_in[8];
    const float* decB      = (const float*)d_in[9];
    const float* adW       = (const float*)d_in[10];
    const float* adB       = (const float*)d_in[11];
    const float* tpW       = (const float*)d_in[12];
    const float* tpB       = (const float*)d_in[13];
    const float* cpW       = (const float*)d_in[14];
    const float* cpB       = (const float*)d_in[15];
    const float* qkvW      = (const float*)d_in[16];
    const float* qkvB      = (const float*)d_in[17];
    const float* aoW       = (const float*)d_in[18];
    const float* aoB       = (const float*)d_in[19];
    const float* f1W       = (const float*)d_in[20];
    const float* f1B       = (const float*)d_in[21];
    const float* f2W       = (const float*)d_in[22];
    const float* f2B       = (const float*)d_in[23];
    const float* ln1g      = (const float*)d_in[24];
    const float* ln1b      = (const float*)d_in[25];
    const float* ln2g      = (const float*)d_in[26];
    const float* ln2b      = (const float*)d_in[27];
    const float* outW      = (const float*)d_in[28];
    const float* outB      = (const float*)d_in[29];

    static bool inited = false;
    static float *p_x, *p_tmp, *p_predv, *p_qkv;
    static __nv_bfloat16 *p_xpk, *p_ctxpk, *p_ffpk, *p_px1pk, *p_habpk;
    static __nv_bfloat16 *p_wqkvP, *p_waoP, *p_wf1P, *p_wf2P, *p_woutP, *p_wadP, *p_wdecP;
    if (!inited) {
        cudaGetSymbolAddress((void**)&p_x,      g_x);
        cudaGetSymbolAddress((void**)&p_tmp,    g_tmp);
        cudaGetSymbolAddress((void**)&p_predv,  g_predv);
        cudaGetSymbolAddress((void**)&p_qkv,    g_qkv);
        cudaGetSymbolAddress((void**)&p_xpk,    g_xpk);
        cudaGetSymbolAddress((void**)&p_ctxpk,  g_ctxpk);
        cudaGetSymbolAddress((void**)&p_ffpk,   g_ffpk);
        cudaGetSymbolAddress((void**)&p_px1pk,  g_px1pk);
        cudaGetSymbolAddress((void**)&p_habpk,  g_habpk);
        cudaGetSymbolAddress((void**)&p_wqkvP,  g_wqkvP);
        cudaGetSymbolAddress((void**)&p_waoP,   g_waoP);
        cudaGetSymbolAddress((void**)&p_wf1P,   g_wf1P);
        cudaGetSymbolAddress((void**)&p_wf2P,   g_wf2P);
        cudaGetSymbolAddress((void**)&p_woutP,  g_woutP);
        cudaGetSymbolAddress((void**)&p_wadP,   g_wadP);
        cudaGetSymbolAddress((void**)&p_wdecP,  g_wdecP);
        cudaFuncSetAttribute(gemm64, cudaFuncAttributeMaxDynamicSharedMemorySize, DYNSM);
        cudaFuncSetAttribute(decode64, cudaFuncAttributeMaxDynamicSharedMemorySize, DYNSM);
        inited = true;
    }

    // 0: weights fp32 -> packed bf16 (one launch)
    wpack_all<<<12864, 256>>>(qkvW, aoW, f1W, f2W, outW, adW, decW);
    // 1-2: pools + prep
    pool_partial<<<dim3(BB, 8), 512>>>(tok, ws, we, emb);
    prep_kernel<<<BB, 512>>>(motif_ids, motif_len, ws, we, emb, t);
    // 3: temb + cond projections (warp per column x row-pair, full chip)
    gemm_small4<<<1024, 256>>>(tpW, tpB, cpW, cpB);
    // 4: build x (+ cond rows + compaction)
    build_all2<<<4129, 256>>>(tok, ws, we, t, x0, emb);

    // transformer layers
    for (int i = 0; i < NLAYER; i++) {
        gemm64<<<dim3(12, 34), 256, DYNSM>>>(
            p_xpk, p_wqkvP + (size_t)i*12*8*TILE_ELEMS, qkvB + (size_t)i*3*DD,
            p_qkv, (__nv_bfloat16*)0, RT, 3*DD, 8, 0, 0);
        attn_scores<<<BB*HH, 256>>>();
        attn_ctx2<<<BB*HH, 256>>>();
        gemm64<<<dim3(4, 34), 256, DYNSM>>>(
            p_ctxpk, p_waoP + (size_t)i*4*8*TILE_ELEMS, aoB + (size_t)i*DD,
            p_tmp, (__nv_bfloat16*)0, RT, DD, 8, 0, 0);
        ln_kernel<<<RT, 256>>>(p_x, p_xpk, p_tmp, ln1g + (size_t)i*DD, ln1b + (size_t)i*DD);
        gemm64<<<dim3(16, 34), 256, DYNSM>>>(
            p_xpk, p_wf1P + (size_t)i*16*8*TILE_ELEMS, f1B + (size_t)i*FF,
            (float*)0, p_ffpk, RT, FF, 8, 0, 1);
        gemm64<<<dim3(4, 34), 256, DYNSM>>>(
            p_ffpk, p_wf2P + (size_t)i*4*32*TILE_ELEMS, f2B + (size_t)i*DD,
            p_tmp, (__nv_bfloat16*)0, RT, DD, 32, 0, 0);
        ln_kernel<<<RT, 256>>>(p_x, p_xpk, p_tmp, ln2g + (size_t)i*DD, ln2b + (size_t)i*DD);
    }

    // pred_v over all transformer rows (valid rows consumed by velpred)
    gemm64<<<dim3(4, 34), 256, DYNSM>>>(
        p_xpk, p_woutP, outB, p_predv, (__nv_bfloat16*)0, RT, DD, 8, 0, 0);
    velpred_kernel<<<256, 256>>>(t, x0);
    // adapter over compact valid rows -> packed hab
    gemm64<<<dim3(4, 32), 256, DYNSM>>>(
        p_px1pk, p_wadP, adB, (float*)0, p_habpk, WR, DD, 8, 1, 0);
    // decode GEMM with fused online softmax partials
    decode64<<<dim3(NCH2, 32), 256, DYNSM>>>(p_habpk, p_wdecP, decB);
    picked_kernel<<<WR/8, 256>>>(decB);
    combine_kernel<<<WR, 128>>>();
    final_kernel<<<1, 256>>>((float*)d_out);
}